// round 2
// baseline (speedup 1.0000x reference)
#include <cuda_runtime.h>
#include <math.h>

#define Bc  32
#define Lc  256
#define Sc  5
#define Nc  1024
#define Dc  256
#define Vc  512
#define Hc  8
#define DHc 32

// ---------------- scratch (static device globals; no allocs) ----------------
__device__ float g_W3[2][Dc*Sc*Dc];      // [dir][i(dt')*1280 + s*256 + j]
__device__ float g_Graw[2][Sc*Vc*Dc];    // [dir][(s*512+v)*256 + i]
__device__ float g_Gp[2][Sc*Vc*Dc];      // [dir][(s*512+v)*256 + d]
__device__ float g_dirb[2][Dc];
__device__ float g_Q[2][Bc*Lc*Dc];
__device__ float g_K[Bc*Nc*Dc];
__device__ float g_Vm[Bc*Nc*Dc];
__device__ float g_F[2][Bc*Lc*Dc];
__device__ float g_num;

// ---------------- reduction helpers ----------------
__device__ __forceinline__ float warpSum(float v){
#pragma unroll
    for (int o=16;o>0;o>>=1) v += __shfl_xor_sync(0xffffffffu, v, o);
    return v;
}
__device__ __forceinline__ float warpMax(float v){
#pragma unroll
    for (int o=16;o>0;o>>=1) v = fmaxf(v, __shfl_xor_sync(0xffffffffu, v, o));
    return v;
}
__device__ __forceinline__ float blockSum(float v, float* red){
    v = warpSum(v);
    int w = threadIdx.x >> 5;
    __syncthreads();
    if ((threadIdx.x & 31) == 0) red[w] = v;
    __syncthreads();
    if (w == 0){
        float r = (threadIdx.x < 8) ? red[threadIdx.x] : 0.f;
        r = warpSum(r);
        if (threadIdx.x == 0) red[0] = r;
    }
    __syncthreads();
    return red[0];
}
__device__ __forceinline__ float blockMax(float v, float* red){
    v = warpMax(v);
    int w = threadIdx.x >> 5;
    __syncthreads();
    if ((threadIdx.x & 31) == 0) red[w] = v;
    __syncthreads();
    if (w == 0){
        float r = (threadIdx.x < 8) ? red[threadIdx.x] : -1e30f;
        r = warpMax(r);
        if (threadIdx.x == 0) red[0] = r;
    }
    __syncthreads();
    return red[0];
}

// ---------------- k0: zero accumulators ----------------
__global__ void k_zero(){
    if (threadIdx.x == 0) g_num = 0.f;
}

// ---------------- k1: fold conv + scrambled-mean into W3 ----------------
// qmean[dt'] = sum_{s,i} E[s,i] * W3[dt',s,i]
__global__ void k_w3(const float* __restrict__ wl, const float* __restrict__ wr){
    int dir = blockIdx.y;
    const float* w = dir ? wr : wl;                   // [O=256][I=256][3]
    int idx = blockIdx.x*256 + threadIdx.x;           // < 256*5*256
    int dt  = idx / (Sc*Dc);
    int rem = idx % (Sc*Dc);
    int s = rem / Dc, i = rem % Dc;
    float v = 0.f;
#pragma unroll
    for (int k=0;k<5;k++){
        int f = dt + 256*k;
        int o = f/5, sk = f%5;
        int t = s - sk + 1;
        if (t >= 0 && t < 3) v += w[(o*Dc + i)*3 + t];
    }
    g_W3[dir][dt*(Sc*Dc) + s*Dc + i] = 0.2f*v;
}

// ---------------- k2: Graw[s,v,i] = sum_j emb[v,j] * W3[i,s,j] ----------------
__global__ void k_graw(const float* __restrict__ emb){
    int dir  = blockIdx.y;
    int row0 = blockIdx.x*32;          // rows = s*512+v, tiles never cross s
    int s    = row0 / Vc;
    int vb   = row0 - s*Vc;
    extern __shared__ float sm[];
    float* Asm = sm;                   // [32][256]
    float* Wsm = sm + 32*256;          // [16][256]
    int t = threadIdx.x;
    for (int e=t; e<32*256; e+=256){
        int r = e>>8, j = e&255;
        Asm[e] = emb[(vb+r)*Dc + j];
    }
    float acc[32];
#pragma unroll
    for (int r=0;r<32;r++) acc[r]=0.f;
    const float* W3 = g_W3[dir];
    for (int jb=0;jb<256;jb+=16){
        __syncthreads();
        for (int e=t;e<16*256;e+=256){
            int j = e&15, col = e>>4;
            Wsm[j*256+col] = W3[col*(Sc*Dc) + s*Dc + jb + j];
        }
        __syncthreads();
#pragma unroll
        for (int j4=0;j4<16;j4+=4){
            float w0=Wsm[(j4+0)*256+t], w1=Wsm[(j4+1)*256+t];
            float w2=Wsm[(j4+2)*256+t], w3=Wsm[(j4+3)*256+t];
#pragma unroll
            for (int r=0;r<32;r++){
                float4 a = *(const float4*)&Asm[r*256 + jb + j4];
                acc[r] += a.x*w0 + a.y*w1 + a.z*w2 + a.w*w3;
            }
        }
    }
    for (int r=0;r<32;r++) g_Graw[dir][(row0+r)*Dc + t] = acc[r];
}

// ---------------- k3: Gp[s,v,d] = sum_i Graw[s,v,i] * P[d,i] ----------------
__global__ void k_gp(const float* __restrict__ P){
    int dir  = blockIdx.y;
    int row0 = blockIdx.x*32;
    extern __shared__ float sm[];
    float* Asm = sm;
    float* Wsm = sm + 32*256;
    int t = threadIdx.x;
    const float* A = g_Graw[dir] + row0*Dc;
    for (int e=t; e<32*256; e+=256) Asm[e] = A[e];
    float acc[32];
#pragma unroll
    for (int r=0;r<32;r++) acc[r]=0.f;
    for (int jb=0;jb<256;jb+=16){
        __syncthreads();
        for (int e=t;e<16*256;e+=256){
            int j = e&15, col = e>>4;
            Wsm[j*256+col] = P[col*Dc + jb + j];
        }
        __syncthreads();
#pragma unroll
        for (int j4=0;j4<16;j4+=4){
            float w0=Wsm[(j4+0)*256+t], w1=Wsm[(j4+1)*256+t];
            float w2=Wsm[(j4+2)*256+t], w3=Wsm[(j4+3)*256+t];
#pragma unroll
            for (int r=0;r<32;r++){
                float4 a = *(const float4*)&Asm[r*256 + jb + j4];
                acc[r] += a.x*w0 + a.y*w1 + a.z*w2 + a.w*w3;
            }
        }
    }
    for (int r=0;r<32;r++) g_Gp[dir][(row0+r)*Dc + t] = acc[r];
}

// ---------------- k4: dir' = dir_tok @ P^T + bias ----------------
__global__ void k_dirb(const float* __restrict__ dl, const float* __restrict__ dr,
                       const float* __restrict__ P, const float* __restrict__ pb){
    int dir = blockIdx.x;
    const float* dv = dir ? dr : dl;
    int d = threadIdx.x;
    float s = pb[d];
    for (int i=0;i<256;i++) s += dv[i]*P[d*Dc + i];
    g_dirb[dir][d] = s;
}

// ---------------- k5: Q = LN(sum_s Gp[s,id_s] + dir') ----------------
__global__ void k_q(const int* __restrict__ idl, const int* __restrict__ idr,
                    const float* __restrict__ gamma, const float* __restrict__ beta){
    int dir = blockIdx.y;
    int bl  = blockIdx.x;
    const int* ids = (dir ? idr : idl) + bl*Sc;
    __shared__ int sid[8];
    __shared__ float red[32];
    int d = threadIdx.x;
    if (d < Sc) sid[d] = ids[d];
    __syncthreads();
    float v = g_dirb[dir][d];
#pragma unroll
    for (int s=0;s<Sc;s++) v += g_Gp[dir][(s*Vc + sid[s])*Dc + d];
    float m   = blockSum(v, red) * (1.f/256.f);
    float dv  = v - m;
    float var = blockSum(dv*dv, red) * (1.f/256.f);
    float o   = dv * rsqrtf(var + 1e-5f) * gamma[d] + beta[d];
    g_Q[dir][bl*Dc + d] = o;
}

// ---------------- k6: K,V = LN(vis @ W^T + b), fused dual GEMM + LN ----------
__global__ void k_kv(const float* __restrict__ vis,
                     const float* __restrict__ kw, const float* __restrict__ kb,
                     const float* __restrict__ vw, const float* __restrict__ vb,
                     const float* __restrict__ gamma, const float* __restrict__ beta){
    extern __shared__ float sm[];
    float* Asm  = sm;               // [32][256]
    float* Wk   = sm + 8192;        // [16][256]
    float* Wv   = Wk + 4096;        // [16][256]
    float* stat = Wv + 4096;        // [64]
    int row0 = blockIdx.x*32;
    int t = threadIdx.x;
    for (int e=t;e<8192;e+=256) Asm[e] = vis[row0*Dc + e];
    float ak[32], av[32];
#pragma unroll
    for (int r=0;r<32;r++){ ak[r]=0.f; av[r]=0.f; }
    for (int jb=0;jb<256;jb+=16){
        __syncthreads();
        for (int e=t;e<16*256;e+=256){
            int j = e&15, col = e>>4;
            Wk[j*256+col] = kw[col*Dc + jb + j];
            Wv[j*256+col] = vw[col*Dc + jb + j];
        }
        __syncthreads();
#pragma unroll
        for (int j4=0;j4<16;j4+=4){
            float k0=Wk[(j4+0)*256+t], k1=Wk[(j4+1)*256+t], k2=Wk[(j4+2)*256+t], k3=Wk[(j4+3)*256+t];
            float v0=Wv[(j4+0)*256+t], v1=Wv[(j4+1)*256+t], v2=Wv[(j4+2)*256+t], v3=Wv[(j4+3)*256+t];
#pragma unroll
            for (int r=0;r<32;r++){
                float4 a = *(const float4*)&Asm[r*256 + jb + j4];
                ak[r] += a.x*k0 + a.y*k1 + a.z*k2 + a.w*k3;
                av[r] += a.x*v0 + a.y*v1 + a.z*v2 + a.w*v3;
            }
        }
    }
    float kbias = kb[t], vbias = vb[t];
    float gm = gamma[t], bt = beta[t];
    int w = t>>5, lane = t&31;

    // ---- K: stage, LN, write ----
    __syncthreads();
#pragma unroll
    for (int r=0;r<32;r++) Asm[r*256+t] = ak[r] + kbias;
    __syncthreads();
#pragma unroll
    for (int rr=0;rr<4;rr++){
        int row = w*4+rr;
        float s=0.f, s2=0.f;
        for (int c=lane;c<256;c+=32){ float x=Asm[row*256+c]; s+=x; s2+=x*x; }
        s = warpSum(s); s2 = warpSum(s2);
        if (lane==0){ float m=s*(1.f/256.f); stat[row]=m; stat[32+row]=rsqrtf(s2*(1.f/256.f)-m*m+1e-5f); }
    }
    __syncthreads();
#pragma unroll
    for (int r=0;r<32;r++)
        g_K[(row0+r)*Dc + t] = (Asm[r*256+t]-stat[r])*stat[32+r]*gm + bt;

    // ---- V: stage, LN, write ----
    __syncthreads();
#pragma unroll
    for (int r=0;r<32;r++) Asm[r*256+t] = av[r] + vbias;
    __syncthreads();
#pragma unroll
    for (int rr=0;rr<4;rr++){
        int row = w*4+rr;
        float s=0.f, s2=0.f;
        for (int c=lane;c<256;c+=32){ float x=Asm[row*256+c]; s+=x; s2+=x*x; }
        s = warpSum(s); s2 = warpSum(s2);
        if (lane==0){ float m=s*(1.f/256.f); stat[row]=m; stat[32+row]=rsqrtf(s2*(1.f/256.f)-m*m+1e-5f); }
    }
    __syncthreads();
#pragma unroll
    for (int r=0;r<32;r++)
        g_Vm[(row0+r)*Dc + t] = (Asm[r*256+t]-stat[r])*stat[32+r]*gm + bt;
}

// ---------------- k7: fused dual-direction multi-head flash attention --------
// grid (ltile=4, hpair=4, b=32); thread = (dir, hloc, lloc)
__global__ void __launch_bounds__(256) k_attn(const float* __restrict__ mask,
                                              const float* __restrict__ tau_p){
    __shared__ float Ksm[32][64];
    __shared__ float Vsm[32][64];
    __shared__ float Msm[64][33];
    int lt = blockIdx.x, hp = blockIdx.y, b = blockIdx.z;
    int t = threadIdx.x;
    int dir  = t >> 7;
    int hloc = (t >> 6) & 1;
    int lloc = t & 63;
    int h  = hp*2 + hloc;
    int l0 = lt*64;
    float tau = tau_p[0];
    tau = fminf(fmaxf(tau, 0.25f), 4.0f);
    float scale = 1.f / (5.656854249f * tau);

    float4 q4[8];
    const float4* qp = (const float4*)(g_Q[dir] + ((b*Lc + l0 + lloc)*Dc + h*DHc));
#pragma unroll
    for (int i=0;i<8;i++) q4[i] = qp[i];

    float acc[32];
#pragma unroll
    for (int i=0;i<32;i++) acc[i]=0.f;
    float mrow = -1e30f, lsum = 0.f;

    for (int n0=0;n0<Nc;n0+=32){
        __syncthreads();
        for (int fi=t; fi<512; fi+=256){
            int n = fi>>4, c4 = fi&15;
            const float4* kp = (const float4*)(g_K  + ((b*Nc + n0 + n)*Dc + hp*64));
            const float4* vp = (const float4*)(g_Vm + ((b*Nc + n0 + n)*Dc + hp*64));
            ((float4*)&Ksm[n][0])[c4] = kp[c4];
            ((float4*)&Vsm[n][0])[c4] = vp[c4];
        }
        for (int e=t; e<64*32; e+=256){
            int l = e>>5, n = e&31;
            Msm[l][n] = mask[(b*Lc + l0 + l)*Nc + n0 + n];
        }
        __syncthreads();

        float s[32];
#pragma unroll
        for (int n=0;n<32;n++){
            const float4* kr = (const float4*)&Ksm[n][hloc*32];
            float a = 0.f;
#pragma unroll
            for (int i=0;i<8;i++){
                float4 k = kr[i];
                a += q4[i].x*k.x + q4[i].y*k.y + q4[i].z*k.z + q4[i].w*k.w;
            }
            s[n] = a * scale * Msm[lloc][n];
        }
        float tm = s[0];
#pragma unroll
        for (int n=1;n<32;n++) tm = fmaxf(tm, s[n]);
        float mnew  = fmaxf(mrow, tm);
        float alpha = __expf(mrow - mnew);
        lsum *= alpha;
#pragma unroll
        for (int i=0;i<32;i++) acc[i] *= alpha;
#pragma unroll
        for (int n=0;n<32;n++){
            float p = __expf(s[n]-mnew);
            lsum += p;
            const float4* vr = (const float4*)&Vsm[n][hloc*32];
#pragma unroll
            for (int i=0;i<8;i++){
                float4 v = vr[i];
                acc[i*4+0] += p*v.x; acc[i*4+1] += p*v.y;
                acc[i*4+2] += p*v.z; acc[i*4+3] += p*v.w;
            }
        }
        mrow = mnew;
    }
    float inv = 1.f/lsum;
    float4* op = (float4*)(g_F[dir] + ((b*Lc + l0 + lloc)*Dc + h*DHc));
#pragma unroll
    for (int i=0;i<8;i++){
        float4 o;
        o.x=acc[i*4+0]*inv; o.y=acc[i*4+1]*inv; o.z=acc[i*4+2]*inv; o.w=acc[i*4+3]*inv;
        op[i] = o;
    }
}

// ---------------- k8: logits = F @ emb^T + cls_b -> d_out -------------------
__global__ void k_logits(const float* __restrict__ emb, const float* __restrict__ clsb,
                         float* __restrict__ out){
    int dir  = blockIdx.z;
    int vh   = blockIdx.y;              // 0/1 half of V
    int row0 = blockIdx.x*32;
    extern __shared__ float sm[];
    float* Asm = sm;
    float* Wsm = sm + 32*256;
    int t = threadIdx.x;
    const float* A = g_F[dir] + row0*Dc;
    for (int e=t; e<32*256; e+=256) Asm[e] = A[e];
    float acc[32];
#pragma unroll
    for (int r=0;r<32;r++) acc[r]=0.f;
    for (int jb=0;jb<256;jb+=16){
        __syncthreads();
        for (int e=t;e<16*256;e+=256){
            int j = e&15, col = e>>4;
            Wsm[j*256+col] = emb[(vh*256 + col)*Dc + jb + j];
        }
        __syncthreads();
#pragma unroll
        for (int j4=0;j4<16;j4+=4){
            float w0=Wsm[(j4+0)*256+t], w1=Wsm[(j4+1)*256+t];
            float w2=Wsm[(j4+2)*256+t], w3=Wsm[(j4+3)*256+t];
#pragma unroll
            for (int r=0;r<32;r++){
                float4 a = *(const float4*)&Asm[r*256 + jb + j4];
                acc[r] += a.x*w0 + a.y*w1 + a.z*w2 + a.w*w3;
            }
        }
    }
    float bias = clsb[vh*256 + t];
    long base = 1 + (long)dir*Bc*Lc*Vc;
    for (int r=0;r<32;r++)
        out[base + (long)(row0+r)*Vc + vh*256 + t] = acc[r] + bias;
}

// ---------------- k9: agreement loss numerator ------------------------------
__global__ void k_loss(const float* __restrict__ out, const float* __restrict__ tmask){
    int l = blockIdx.x;                 // 0..254
    int b = blockIdx.y;
    const float* rl = out + 1 + (long)(b*Lc + l)*Vc;
    const float* rr = out + 1 + (long)Bc*Lc*Vc + (long)(b*Lc + l + 1)*Vc;
    __shared__ float red[32];
    int t = threadIdx.x;
    float xl0 = rl[t]*0.5f,     xl1 = rl[t+256]*0.5f;
    float xr0 = rr[t]*0.5f,     xr1 = rr[t+256]*0.5f;
    float ml = blockMax(fmaxf(xl0,xl1), red);
    float el0 = __expf(xl0-ml), el1 = __expf(xl1-ml);
    float sl = blockSum(el0+el1, red);
    float mr = blockMax(fmaxf(xr0,xr1), red);
    float er0 = __expf(xr0-mr), er1 = __expf(xr1-mr);
    float sr = blockSum(er0+er1, red);
    float pl0 = el0/sl, pl1 = el1/sl;
    float pr0 = er0/sr, pr1 = er1/sr;
    float d0 = pl0-pr0, d1 = pl1-pr1;
    float agree = blockSum(d0*d0 + d1*d1, red);
    if (t == 0) atomicAdd(&g_num, agree * tmask[b*Lc + l]);
}

// ---------------- k10: finalize loss ----------------------------------------
__global__ void k_final(const float* __restrict__ tmask, float* __restrict__ out){
    __shared__ float red[32];
    float s = 0.f;
    for (int e=threadIdx.x; e<Bc*Lc; e+=256){
        int l = e % Lc;
        if (l < Lc-1) s += tmask[e];
    }
    s = blockSum(s, red);
    if (threadIdx.x == 0){
        float den = fmaxf(s, 1.0f);
        out[0] = 0.1f * g_num / den;
    }
}

// ---------------- launch ----------------------------------------------------
extern "C" void kernel_launch(void* const* d_in, const int* in_sizes, int n_in,
                              void* d_out, int out_size){
    const float* vis   = (const float*)d_in[0];
    const int*   idl   = (const int*)  d_in[1];
    const int*   idr   = (const int*)  d_in[2];
    const float* tmask = (const float*)d_in[4];
    const float* vmask = (const float*)d_in[5];
    const float* emb   = (const float*)d_in[6];
    const float* dl    = (const float*)d_in[7];
    const float* dr    = (const float*)d_in[8];
    const float* pw    = (const float*)d_in[9];
    const float* pb    = (const float*)d_in[10];
    const float* qg    = (const float*)d_in[11];
    const float* qb    = (const float*)d_in[12];
    const float* kw    = (const float*)d_in[13];
    const float* kb    = (const float*)d_in[14];
    const float* vw    = (const float*)d_in[15];
    const float* vb    = (const float*)d_in[16];
    const float* kvg   = (const float*)d_in[17];
    const float* kvb   = (const float*)d_in[18];
    const float* tau   = (const float*)d_in[19];
    const float* clsb  = (const float*)d_in[20];
    const float* cwl   = (const float*)d_in[21];
    const float* cwr   = (const float*)d_in[22];
    float* out = (float*)d_out;

    const int SM_GEMM = 48*1024;       // Asm 32KB + Wsm 16KB
    const int SM_KV   = 66*1024;       // Asm 32KB + Wk/Wv 32KB + stats
    cudaFuncSetAttribute(k_graw,   cudaFuncAttributeMaxDynamicSharedMemorySize, SM_GEMM);
    cudaFuncSetAttribute(k_gp,     cudaFuncAttributeMaxDynamicSharedMemorySize, SM_GEMM);
    cudaFuncSetAttribute(k_logits, cudaFuncAttributeMaxDynamicSharedMemorySize, SM_GEMM);
    cudaFuncSetAttribute(k_kv,     cudaFuncAttributeMaxDynamicSharedMemorySize, SM_KV);

    k_zero<<<1, 32>>>();
    k_w3<<<dim3(1280,2), 256>>>(cwl, cwr);
    k_graw<<<dim3(80,2), 256, SM_GEMM>>>(emb);
    k_gp<<<dim3(80,2), 256, SM_GEMM>>>(pw);
    k_dirb<<<2, 256>>>(dl, dr, pw, pb);
    k_q<<<dim3(Bc*Lc,2), 256>>>(idl, idr, qg, qb);
    k_kv<<<Bc*Nc/32, 256, SM_KV>>>(vis, kw, kb, vw, vb, kvg, kvb);
    k_attn<<<dim3(Lc/64, Hc/2, Bc), 256>>>(vmask, tau);
    k_logits<<<dim3(Bc*Lc/32, 2, 2), 256, SM_GEMM>>>(emb, clsb, out);
    k_loss<<<dim3(Lc-1, Bc), 256>>>(out, tmask);
    k_final<<<1, 256>>>(tmask, out);
}

// round 6
// speedup vs baseline: 1.3768x; 1.3768x over previous
#include <cuda_runtime.h>
#include <cstdint>
#include <math.h>
#include <mma.h>
using namespace nvcuda;

#define Bc  32
#define Lc  256
#define Sc  5
#define Nc  1024
#define Dc  256
#define Vc  512
#define Hc  8
#define DHc 32

// ---------------- scratch ----------------
__device__ float g_W3[2][Dc*Sc*Dc];      // [dir][dt*1280 + s*256 + j]
__device__ float g_Graw[2][Sc*Vc*Dc];
__device__ float g_Gp[2][Sc*Vc*Dc];
__device__ float g_dirb[2][Dc];
__device__ float g_Q[2][Bc*Lc*Dc];
__device__ float g_K[Bc*Nc*Dc];
__device__ float g_Vm[Bc*Nc*Dc];
__device__ float g_F[2][Bc*Lc*Dc];
__device__ float g_num;

// ---------------- helpers ----------------
__device__ __forceinline__ float warpSum(float v){
#pragma unroll
    for (int o=16;o>0;o>>=1) v += __shfl_xor_sync(0xffffffffu, v, o);
    return v;
}
__device__ __forceinline__ float warpMax(float v){
#pragma unroll
    for (int o=16;o>0;o>>=1) v = fmaxf(v, __shfl_xor_sync(0xffffffffu, v, o));
    return v;
}
__device__ __forceinline__ float blockSum(float v, float* red){
    v = warpSum(v);
    int w = threadIdx.x >> 5;
    __syncthreads();
    if ((threadIdx.x & 31) == 0) red[w] = v;
    __syncthreads();
    if (w == 0){
        float r = (threadIdx.x < 8) ? red[threadIdx.x] : 0.f;
        r = warpSum(r);
        if (threadIdx.x == 0) red[0] = r;
    }
    __syncthreads();
    return red[0];
}
__device__ __forceinline__ float blockMax(float v, float* red){
    v = warpMax(v);
    int w = threadIdx.x >> 5;
    __syncthreads();
    if ((threadIdx.x & 31) == 0) red[w] = v;
    __syncthreads();
    if (w == 0){
        float r = (threadIdx.x < 8) ? red[threadIdx.x] : -1e30f;
        r = warpMax(r);
        if (threadIdx.x == 0) red[0] = r;
    }
    __syncthreads();
    return red[0];
}
__device__ __forceinline__ float f2tf(float x){
    uint32_t u; asm("cvt.rna.tf32.f32 %0, %1;" : "=r"(u) : "f"(x));
    return __uint_as_float(u);
}
__device__ __forceinline__ uint32_t f2tf_u(float x){
    uint32_t u; asm("cvt.rna.tf32.f32 %0, %1;" : "=r"(u) : "f"(x));
    return u;
}
__device__ __forceinline__ void mma_tf32(float* c, const uint32_t* a, const uint32_t* b){
    asm volatile("mma.sync.aligned.m16n8k8.row.col.f32.tf32.tf32.f32 "
        "{%0,%1,%2,%3}, {%4,%5,%6,%7}, {%8,%9}, {%0,%1,%2,%3};"
        : "+f"(c[0]),"+f"(c[1]),"+f"(c[2]),"+f"(c[3])
        : "r"(a[0]),"r"(a[1]),"r"(a[2]),"r"(a[3]), "r"(b[0]),"r"(b[1]));
}

// ---------------- k0 ----------------
__global__ void k_zero(){ if (threadIdx.x == 0) g_num = 0.f; }

// ---------------- k1: fold conv + scrambled-mean into W3 ----------------
__global__ void k_w3(const float* __restrict__ wl, const float* __restrict__ wr){
    int dir = blockIdx.y;
    const float* w = dir ? wr : wl;
    int idx = blockIdx.x*256 + threadIdx.x;
    int dt  = idx / (Sc*Dc);
    int rem = idx % (Sc*Dc);
    int s = rem / Dc, i = rem % Dc;
    float v = 0.f;
#pragma unroll
    for (int k=0;k<5;k++){
        int f = dt + 256*k;
        int o = f/5, sk = f%5;
        int t = s - sk + 1;
        if (t >= 0 && t < 3) v += w[(o*Dc + i)*3 + t];
    }
    g_W3[dir][dt*(Sc*Dc) + s*Dc + i] = 0.2f*v;
}

// ---------------- generic tf32 GEMM: C = A @ B^T (+bias on mode 3) ---------
// modes: 0 kv (z: 0=K 1=V), 1 graw (z=dir*5+s), 2 gp (z=dir), 3 logits (z=dir)
__global__ void __launch_bounds__(256) k_gemm(int mode,
        const float* __restrict__ A, const float* __restrict__ B0,
        const float* __restrict__ B1, const float* __restrict__ bias,
        float* __restrict__ Cext){
    __shared__ float As[128][40];
    __shared__ float Bs[128][40];
    int z = blockIdx.z;
    const float* Ap; const float* Bp; float* Cp;
    int ldb, ldc;
    if (mode==0){
        Ap = A; Bp = z ? B1 : B0; ldb = 256;
        Cp = z ? &g_Vm[0] : &g_K[0]; ldc = 256;
    } else if (mode==1){
        int dir = z/5, s = z%5;
        Ap = A;
        Bp = &g_W3[0][0] + dir*327680 + s*256; ldb = 1280;
        Cp = &g_Graw[0][0] + dir*655360 + s*(512*256); ldc = 256;
    } else if (mode==2){
        Ap = &g_Graw[0][0] + z*655360;
        Bp = B0; ldb = 256;
        Cp = &g_Gp[0][0] + z*655360; ldc = 256;
    } else {
        Ap = &g_F[0][0] + (long)z*8192*256;
        Bp = B0; ldb = 256;
        Cp = Cext + 1 + (long)z*8192*512; ldc = 512;
    }
    int row0 = blockIdx.x*128, col0 = blockIdx.y*128;
    int t = threadIdx.x, wid = t>>5, lane = t&31;
    int wm = wid>>2, wn = wid&3;

    wmma::fragment<wmma::accumulator,16,16,8,float> acc[4][2];
#pragma unroll
    for (int mi=0;mi<4;mi++)
#pragma unroll
        for (int ni=0;ni<2;ni++) wmma::fill_fragment(acc[mi][ni], 0.f);

    for (int kb=0; kb<256; kb+=32){
        __syncthreads();
        for (int i=t; i<1024; i+=256){
            int r = i>>3, c4 = i&7;
            *(float4*)&As[r][c4*4] = *(const float4*)&Ap[(long)(row0+r)*256 + kb + c4*4];
        }
        for (int i=t; i<1024; i+=256){
            int r = i>>3, c4 = i&7;
            *(float4*)&Bs[r][c4*4] = *(const float4*)&Bp[(long)(col0+r)*ldb + kb + c4*4];
        }
        __syncthreads();
#pragma unroll
        for (int k8=0;k8<4;k8++){
            wmma::fragment<wmma::matrix_a,16,16,8,wmma::precision::tf32,wmma::row_major> af[4];
            wmma::fragment<wmma::matrix_b,16,16,8,wmma::precision::tf32,wmma::col_major> bf[2];
#pragma unroll
            for (int mi=0;mi<4;mi++){
                wmma::load_matrix_sync(af[mi], &As[wm*64 + mi*16][k8*8], 40);
#pragma unroll
                for (int e=0;e<af[mi].num_elements;e++) af[mi].x[e] = wmma::__float_to_tf32(af[mi].x[e]);
            }
#pragma unroll
            for (int ni=0;ni<2;ni++){
                wmma::load_matrix_sync(bf[ni], &Bs[wn*32 + ni*16][k8*8], 40);
#pragma unroll
                for (int e=0;e<bf[ni].num_elements;e++) bf[ni].x[e] = wmma::__float_to_tf32(bf[ni].x[e]);
            }
#pragma unroll
            for (int mi=0;mi<4;mi++)
#pragma unroll
                for (int ni=0;ni<2;ni++)
                    wmma::mma_sync(acc[mi][ni], af[mi], bf[ni], acc[mi][ni]);
        }
    }
    if (mode != 3){
#pragma unroll
        for (int mi=0;mi<4;mi++)
#pragma unroll
            for (int ni=0;ni<2;ni++)
                wmma::store_matrix_sync(&Cp[(long)(row0+wm*64+mi*16)*ldc + col0 + wn*32 + ni*16],
                                        acc[mi][ni], ldc, wmma::mem_row_major);
    } else {
        // misaligned output base (out+1): stage per-warp, scalar stores + bias
        __syncthreads();
        float* stage = &As[0][0] + wid*(16*18);
#pragma unroll
        for (int mi=0;mi<4;mi++)
#pragma unroll
            for (int ni=0;ni<2;ni++){
                wmma::store_matrix_sync(stage, acc[mi][ni], 18, wmma::mem_row_major);
                __syncwarp();
                for (int e=lane; e<256; e+=32){
                    int r = e>>4, c = e&15;
                    int col = col0 + wn*32 + ni*16 + c;
                    Cp[(long)(row0+wm*64+mi*16+r)*ldc + col] = stage[r*18+c] + bias[col];
                }
                __syncwarp();
            }
    }
}

// ---------------- LN (+bias) in place on g_K / g_Vm -------------------------
__global__ void k_ln(const float* __restrict__ kb, const float* __restrict__ vb,
                     const float* __restrict__ gamma, const float* __restrict__ beta){
    int z = blockIdx.y;
    float* X = z ? &g_Vm[0] : &g_K[0];
    const float* bias = z ? vb : kb;
    int wid = threadIdx.x>>5, lane = threadIdx.x&31;
    long row = (long)blockIdx.x*8 + wid;
    float4* R = (float4*)(X + row*256);
    const float4* B4 = (const float4*)bias;
    const float4* G4 = (const float4*)gamma;
    const float4* T4 = (const float4*)beta;
    float4 x0 = R[lane], x1 = R[lane+32];
    float4 b0 = B4[lane], b1 = B4[lane+32];
    x0.x+=b0.x; x0.y+=b0.y; x0.z+=b0.z; x0.w+=b0.w;
    x1.x+=b1.x; x1.y+=b1.y; x1.z+=b1.z; x1.w+=b1.w;
    float s  = x0.x+x0.y+x0.z+x0.w + x1.x+x1.y+x1.z+x1.w;
    float s2 = x0.x*x0.x+x0.y*x0.y+x0.z*x0.z+x0.w*x0.w
             + x1.x*x1.x+x1.y*x1.y+x1.z*x1.z+x1.w*x1.w;
    s = warpSum(s); s2 = warpSum(s2);
    float m = s*(1.f/256.f);
    float r = rsqrtf(s2*(1.f/256.f) - m*m + 1e-5f);
    float4 g0 = G4[lane], g1 = G4[lane+32];
    float4 t0 = T4[lane], t1 = T4[lane+32];
    float4 o0, o1;
    o0.x=(x0.x-m)*r*g0.x+t0.x; o0.y=(x0.y-m)*r*g0.y+t0.y;
    o0.z=(x0.z-m)*r*g0.z+t0.z; o0.w=(x0.w-m)*r*g0.w+t0.w;
    o1.x=(x1.x-m)*r*g1.x+t1.x; o1.y=(x1.y-m)*r*g1.y+t1.y;
    o1.z=(x1.z-m)*r*g1.z+t1.z; o1.w=(x1.w-m)*r*g1.w+t1.w;
    R[lane] = o0; R[lane+32] = o1;
}

// ---------------- dir' = dir_tok @ P^T + bias ----------------
__global__ void k_dirb(const float* __restrict__ dl, const float* __restrict__ dr,
                       const float* __restrict__ P, const float* __restrict__ pb){
    int dir = blockIdx.x;
    const float* dv = dir ? dr : dl;
    int d = threadIdx.x;
    float s = pb[d];
    for (int i=0;i<256;i++) s += dv[i]*P[d*Dc + i];
    g_dirb[dir][d] = s;
}

// ---------------- Q = LN(sum_s Gp[s,id_s] + dir') ----------------
__global__ void k_q(const int* __restrict__ idl, const int* __restrict__ idr,
                    const float* __restrict__ gamma, const float* __restrict__ beta){
    int dir = blockIdx.y;
    int bl  = blockIdx.x;
    const int* ids = (dir ? idr : idl) + bl*Sc;
    __shared__ int sid[8];
    __shared__ float red[32];
    int d = threadIdx.x;
    if (d < Sc) sid[d] = ids[d];
    __syncthreads();
    float v = g_dirb[dir][d];
#pragma unroll
    for (int s=0;s<Sc;s++) v += g_Gp[dir][(s*Vc + sid[s])*Dc + d];
    float m   = blockSum(v, red) * (1.f/256.f);
    float dv  = v - m;
    float var = blockSum(dv*dv, red) * (1.f/256.f);
    float o   = dv * rsqrtf(var + 1e-5f) * gamma[d] + beta[d];
    g_Q[dir][bl*Dc + d] = o;
}

// ---------------- flash attention, tf32 mma ---------------------------------
// block: (lt*4+hp, b, dir). 256 thr = 8 warps: wg=head(2), wr=row quarter(4)
__global__ void __launch_bounds__(256) k_attn(const float* __restrict__ mask,
                                              const float* __restrict__ tau_p){
    extern __shared__ float sm[];
    float* Ksm  = sm;                    // [2][32][36]
    float* Vtsm = Ksm + 2*32*36;         // [2][32][36] transposed: [dh][n]
    float* Msm  = Vtsm + 2*32*36;        // [128][36]
    float* Psm  = Msm + 128*36;          // [2][128][36]
    int lt = blockIdx.x >> 2, hp = blockIdx.x & 3;
    int b = blockIdx.y, dir = blockIdx.z;
    int l0 = lt*128;
    int t = threadIdx.x, wid = t>>5, lane = t&31;
    int wg = wid>>2, wr = wid&3;
    int lq = lane>>2, lr = lane&3;
    float tau = fminf(fmaxf(tau_p[0],0.25f),4.f);
    float scale = 1.f/(5.656854249f*tau);

    // stage Q (both heads) into Psm, load frags
    const float* Qbase = (dir ? g_Q[1] : g_Q[0]) + (long)(b*Lc + l0)*Dc + hp*64;
    for (int i=t; i<2048; i+=256){
        int hh = i>>10, rem = i&1023, row = rem>>3, c4 = rem&7;
        *(float4*)&Psm[(hh*128+row)*36 + c4*4] =
            *(const float4*)&Qbase[(long)row*Dc + hh*32 + c4*4];
    }
    __syncthreads();
    uint32_t qa[2][4][4];
    {
        const float* Qh = Psm + wg*128*36;
#pragma unroll
        for (int mi=0;mi<2;mi++)
#pragma unroll
        for (int k8=0;k8<4;k8++){
            int r = wr*32 + mi*16 + lq, c = k8*8 + lr;
            qa[mi][k8][0] = f2tf_u(Qh[r*36 + c]);
            qa[mi][k8][1] = f2tf_u(Qh[(r+8)*36 + c]);
            qa[mi][k8][2] = f2tf_u(Qh[r*36 + c+4]);
            qa[mi][k8][3] = f2tf_u(Qh[(r+8)*36 + c+4]);
        }
    }
    float o[2][4][4];
#pragma unroll
    for (int mi=0;mi<2;mi++)
#pragma unroll
        for (int ni=0;ni<4;ni++)
#pragma unroll
            for (int e=0;e<4;e++) o[mi][ni][e]=0.f;
    float mrow[4] = {-1e30f,-1e30f,-1e30f,-1e30f};
    float lsum[4] = {0.f,0.f,0.f,0.f};

    const float* Kg = g_K  + (long)(b*Nc)*Dc + hp*64;
    const float* Vg = g_Vm + (long)(b*Nc)*Dc + hp*64;
    const float* Mg = mask + (long)(b*Lc + l0)*Nc;
    float* Ph = Psm + wg*128*36;

    for (int n0=0; n0<Nc; n0+=32){
        __syncthreads();
        for (int i=t; i<512; i+=256){
            int hh = i>>8, rem = i&255, n = rem>>3, c4 = rem&7;
            float4 kv = *(const float4*)&Kg[(long)(n0+n)*Dc + hh*32 + c4*4];
            float* d = &Ksm[(hh*32+n)*36 + c4*4];
            d[0]=f2tf(kv.x); d[1]=f2tf(kv.y); d[2]=f2tf(kv.z); d[3]=f2tf(kv.w);
        }
        for (int i=t; i<512; i+=256){
            int hh = i>>8, rem = i&255, n = rem>>3, c4 = rem&7;
            float4 vv = *(const float4*)&Vg[(long)(n0+n)*Dc + hh*32 + c4*4];
            float* base = &Vtsm[hh*32*36];
            base[(c4*4+0)*36+n] = f2tf(vv.x);
            base[(c4*4+1)*36+n] = f2tf(vv.y);
            base[(c4*4+2)*36+n] = f2tf(vv.z);
            base[(c4*4+3)*36+n] = f2tf(vv.w);
        }
        for (int i=t; i<1024; i+=256){
            int row = i>>3, c4 = i&7;
            *(float4*)&Msm[row*36 + c4*4] = *(const float4*)&Mg[(long)row*Nc + n0 + c4*4];
        }
        __syncthreads();

        float sc[2][4][4];
#pragma unroll
        for (int mi=0;mi<2;mi++)
#pragma unroll
            for (int ni=0;ni<4;ni++)
#pragma unroll
                for (int e=0;e<4;e++) sc[mi][ni][e]=0.f;
        const float* Kh = Ksm + wg*32*36;
#pragma unroll
        for (int k8=0;k8<4;k8++){
            uint32_t bf[4][2];
#pragma unroll
            for (int ni=0;ni<4;ni++){
                bf[ni][0] = __float_as_uint(Kh[(ni*8+lq)*36 + k8*8 + lr]);
                bf[ni][1] = __float_as_uint(Kh[(ni*8+lq)*36 + k8*8 + lr + 4]);
            }
#pragma unroll
            for (int mi=0;mi<2;mi++)
#pragma unroll
                for (int ni=0;ni<4;ni++)
                    mma_tf32(sc[mi][ni], qa[mi][k8], bf[ni]);
        }
        // masked online softmax
#pragma unroll
        for (int mi=0;mi<2;mi++)
#pragma unroll
        for (int half=0;half<2;half++){
            int q = mi*2+half;
            int row = wr*32 + mi*16 + half*8 + lq;
            float x[8];
            float tm = -1e30f;
#pragma unroll
            for (int ni=0;ni<4;ni++){
                float m0 = Msm[row*36 + ni*8 + 2*lr];
                float m1 = Msm[row*36 + ni*8 + 2*lr + 1];
                x[ni*2]   = sc[mi][ni][half*2]   * scale * m0;
                x[ni*2+1] = sc[mi][ni][half*2+1] * scale * m1;
                tm = fmaxf(tm, fmaxf(x[ni*2], x[ni*2+1]));
            }
            tm = fmaxf(tm, __shfl_xor_sync(0xffffffffu, tm, 1));
            tm = fmaxf(tm, __shfl_xor_sync(0xffffffffu, tm, 2));
            float mnew = fmaxf(mrow[q], tm);
            float alpha = __expf(mrow[q] - mnew);
            mrow[q] = mnew;
            float ls = 0.f;
#pragma unroll
            for (int ni=0;ni<4;ni++){
                float p0 = __expf(x[ni*2]-mnew);
                float p1 = __expf(x[ni*2+1]-mnew);
                ls += p0+p1;
                float2 pp; pp.x = f2tf(p0); pp.y = f2tf(p1);
                *(float2*)&Ph[row*36 + ni*8 + 2*lr] = pp;
                o[mi][ni][half*2]   *= alpha;
                o[mi][ni][half*2+1] *= alpha;
            }
            ls += __shfl_xor_sync(0xffffffffu, ls, 1);
            ls += __shfl_xor_sync(0xffffffffu, ls, 2);
            lsum[q] = lsum[q]*alpha + ls;
        }
        __syncwarp();
        // O += P @ V
        const float* Vh = Vtsm + wg*32*36;
#pragma unroll
        for (int k8=0;k8<4;k8++){
            uint32_t pa[2][4];
#pragma unroll
            for (int mi=0;mi<2;mi++){
                int r = wr*32 + mi*16 + lq, c = k8*8+lr;
                pa[mi][0] = __float_as_uint(Ph[r*36 + c]);
                pa[mi][1] = __float_as_uint(Ph[(r+8)*36 + c]);
                pa[mi][2] = __float_as_uint(Ph[r*36 + c+4]);
                pa[mi][3] = __float_as_uint(Ph[(r+8)*36 + c+4]);
            }
            uint32_t vb[4][2];
#pragma unroll
            for (int ni=0;ni<4;ni++){
                vb[ni][0] = __float_as_uint(Vh[(ni*8+lq)*36 + k8*8 + lr]);
                vb[ni][1] = __float_as_uint(Vh[(ni*8+lq)*36 + k8*8 + lr + 4]);
            }
#pragma unroll
            for (int mi=0;mi<2;mi++)
#pragma unroll
                for (int ni=0;ni<4;ni++)
                    mma_tf32(o[mi][ni], pa[mi], vb[ni]);
        }
    }
    float* Fg = (dir ? g_F[1] : g_F[0]) + (long)(b*Lc + l0)*Dc + (hp*2+wg)*32;
#pragma unroll
    for (int mi=0;mi<2;mi++)
#pragma unroll
    for (int half=0;half<2;half++){
        int q = mi*2+half;
        int row = wr*32 + mi*16 + half*8 + lq;
        float inv = 1.f/lsum[q];
#pragma unroll
        for (int ni=0;ni<4;ni++){
            float2 oo;
            oo.x = o[mi][ni][half*2]*inv;
            oo.y = o[mi][ni][half*2+1]*inv;
            *(float2*)&Fg[(long)row*Dc + ni*8 + 2*lr] = oo;
        }
    }
}

// ---------------- agreement loss ----------------
__global__ void k_loss(const float* __restrict__ out, const float* __restrict__ tmask){
    int l = blockIdx.x;
    int b = blockIdx.y;
    const float* rl = out + 1 + (long)(b*Lc + l)*Vc;
    const float* rr = out + 1 + (long)Bc*Lc*Vc + (long)(b*Lc + l + 1)*Vc;
    __shared__ float red[32];
    int t = threadIdx.x;
    float xl0 = rl[t]*0.5f,     xl1 = rl[t+256]*0.5f;
    float xr0 = rr[t]*0.5f,     xr1 = rr[t+256]*0.5f;
    float ml = blockMax(fmaxf(xl0,xl1), red);
    float el0 = __expf(xl0-ml), el1 = __expf(xl1-ml);
    float sl = blockSum(el0+el1, red);
    float mr = blockMax(fmaxf(xr0,xr1), red);
    float er0 = __expf(xr0-mr), er1 = __expf(xr1-mr);
    float sr = blockSum(er0+er1, red);
    float pl0 = el0/sl, pl1 = el1/sl;
    float pr0 = er0/sr, pr1 = er1/sr;
    float d0 = pl0-pr0, d1 = pl1-pr1;
    float agree = blockSum(d0*d0 + d1*d1, red);
    if (t == 0) atomicAdd(&g_num, agree * tmask[b*Lc + l]);
}

__global__ void k_final(const float* __restrict__ tmask, float* __restrict__ out){
    __shared__ float red[32];
    float s = 0.f;
    for (int e=threadIdx.x; e<Bc*Lc; e+=256){
        int l = e % Lc;
        if (l < Lc-1) s += tmask[e];
    }
    s = blockSum(s, red);
    if (threadIdx.x == 0){
        float den = fmaxf(s, 1.0f);
        out[0] = 0.1f * g_num / den;
    }
}

// ---------------- launch ----------------------------------------------------
extern "C" void kernel_launch(void* const* d_in, const int* in_sizes, int n_in,
                              void* d_out, int out_size){
    const float* vis   = (const float*)d_in[0];
    const int*   idl   = (const int*)  d_in[1];
    const int*   idr   = (const int*)  d_in[2];
    const float* tmask = (const float*)d_in[4];
    const float* vmask = (const float*)d_in[5];
    const float* emb   = (const float*)d_in[6];
    const float* dl    = (const float*)d_in[7];
    const float* dr    = (const float*)d_in[8];
    const float* pw    = (const float*)d_in[9];
    const float* pb    = (const float*)d_in[10];
    const float* qg    = (const float*)d_in[11];
    const float* qb    = (const float*)d_in[12];
    const float* kw    = (const float*)d_in[13];
    const float* kb    = (const float*)d_in[14];
    const float* vw    = (const float*)d_in[15];
    const float* vb    = (const float*)d_in[16];
    const float* kvg   = (const float*)d_in[17];
    const float* kvb   = (const float*)d_in[18];
    const float* tau   = (const float*)d_in[19];
    const float* clsb  = (const float*)d_in[20];
    const float* cwl   = (const float*)d_in[21];
    const float* cwr   = (const float*)d_in[22];
    float* out = (float*)d_out;

    const int SM_ATTN = 73728;
    cudaFuncSetAttribute(k_attn, cudaFuncAttributeMaxDynamicSharedMemorySize, SM_ATTN);

    k_zero<<<1, 32>>>();
    k_w3<<<dim3(1280,2), 256>>>(cwl, cwr);
    k_gemm<<<dim3(4,2,10), 256>>>(1, emb, nullptr, nullptr, nullptr, nullptr);
    k_gemm<<<dim3(20,2,2), 256>>>(2, nullptr, pw, nullptr, nullptr, nullptr);
    k_dirb<<<2, 256>>>(dl, dr, pw, pb);
    k_q<<<dim3(Bc*Lc,2), 256>>>(idl, idr, qg, qb);
    k_gemm<<<dim3(256,2,2), 256>>>(0, vis, kw, vw, nullptr, nullptr);
    k_ln<<<dim3(4096,2), 256>>>(kb, vb, kvg, kvb);
    k_attn<<<dim3(8,32,2), 256, SM_ATTN>>>(vmask, tau);
    k_gemm<<<dim3(64,4,2), 256>>>(3, nullptr, emb, nullptr, clsb, out);
    k_loss<<<dim3(Lc-1, Bc), 256>>>(out, tmask);
    k_final<<<1, 256>>>(tmask, out);
}

// round 7
// speedup vs baseline: 1.6792x; 1.2196x over previous
#include <cuda_runtime.h>
#include <cstdint>
#include <math.h>
#include <mma.h>
using namespace nvcuda;

#define Bc  32
#define Lc  256
#define Sc  5
#define Nc  1024
#define Dc  256
#define Vc  512
#define Hc  8
#define DHc 32

// ---------------- scratch ----------------
__device__ float g_W3T[2][Sc*Dc*Dc];     // [dir][(s*256+j)*256 + dt]
__device__ float g_M[10*Dc*Dc];          // [dir*5+s][d*256 + j]
__device__ float g_Gp[2][Sc*Vc*Dc];
__device__ float g_dirb[2][Dc];
__device__ float g_Q[2][Bc*Lc*Dc];
__device__ float g_K[Bc*Nc*Dc];
__device__ float g_Vm[Bc*Nc*Dc];
__device__ float g_F[2][Bc*Lc*Dc];
__device__ float g_num;

// ---------------- helpers ----------------
__device__ __forceinline__ float warpSum(float v){
#pragma unroll
    for (int o=16;o>0;o>>=1) v += __shfl_xor_sync(0xffffffffu, v, o);
    return v;
}
__device__ __forceinline__ float warpMax(float v){
#pragma unroll
    for (int o=16;o>0;o>>=1) v = fmaxf(v, __shfl_xor_sync(0xffffffffu, v, o));
    return v;
}
__device__ __forceinline__ float blockSum(float v, float* red){
    v = warpSum(v);
    int w = threadIdx.x >> 5;
    __syncthreads();
    if ((threadIdx.x & 31) == 0) red[w] = v;
    __syncthreads();
    if (w == 0){
        float r = (threadIdx.x < 8) ? red[threadIdx.x] : 0.f;
        r = warpSum(r);
        if (threadIdx.x == 0) red[0] = r;
    }
    __syncthreads();
    return red[0];
}
__device__ __forceinline__ float blockMax(float v, float* red){
    v = warpMax(v);
    int w = threadIdx.x >> 5;
    __syncthreads();
    if ((threadIdx.x & 31) == 0) red[w] = v;
    __syncthreads();
    if (w == 0){
        float r = (threadIdx.x < 8) ? red[threadIdx.x] : -1e30f;
        r = warpMax(r);
        if (threadIdx.x == 0) red[0] = r;
    }
    __syncthreads();
    return red[0];
}
__device__ __forceinline__ float f2tf(float x){
    uint32_t u; asm("cvt.rna.tf32.f32 %0, %1;" : "=r"(u) : "f"(x));
    return __uint_as_float(u);
}
__device__ __forceinline__ uint32_t f2tf_u(float x){
    uint32_t u; asm("cvt.rna.tf32.f32 %0, %1;" : "=r"(u) : "f"(x));
    return u;
}
__device__ __forceinline__ void mma_tf32(float* c, const uint32_t* a, const uint32_t* b){
    asm volatile("mma.sync.aligned.m16n8k8.row.col.f32.tf32.tf32.f32 "
        "{%0,%1,%2,%3}, {%4,%5,%6,%7}, {%8,%9}, {%0,%1,%2,%3};"
        : "+f"(c[0]),"+f"(c[1]),"+f"(c[2]),"+f"(c[3])
        : "r"(a[0]),"r"(a[1]),"r"(a[2]),"r"(a[3]), "r"(b[0]),"r"(b[1]));
}

// ---------------- k0 ----------------
__global__ void k_zero(){ if (threadIdx.x == 0) g_num = 0.f; }

// ---------------- k1: fold conv + scrambled-mean into W3^T ------------------
// stored transposed: g_W3T[dir][(s*256+j)*256 + dt]  (coalesced in dt)
__global__ void k_w3(const float* __restrict__ wl, const float* __restrict__ wr){
    int dir = blockIdx.y;
    const float* w = dir ? wr : wl;
    int idx = blockIdx.x*256 + threadIdx.x;  // < 327680
    int dt = idx & 255;
    int sj = idx >> 8;                       // 0..1279
    int s = sj >> 8, j = sj & 255;           // s = sj/256 (sj<1280)
    s = sj / 256; j = sj % 256;
    float v = 0.f;
#pragma unroll
    for (int k=0;k<5;k++){
        int f = dt + 256*k;
        int o = f/5, sk = f%5;
        int tp = s - sk + 1;
        if (tp >= 0 && tp < 3) v += w[(o*Dc + j)*3 + tp];
    }
    g_W3T[dir][(s*Dc + j)*Dc + dt] = 0.2f*v;
}

// ---------------- generic tf32 GEMM: C = A @ B^T (+bias on mode 3) ----------
// modes: 0 kv (z: 0=K 1=V), 1 M=P@W3T^T (z=dir*5+s), 2 Gp=emb@M^T (z=dir*5+s),
//        3 logits (z=dir)
// tf32 conversion happens ONCE at smem store; gmem loads are reg-prefetched.
__global__ void __launch_bounds__(256,2) k_gemm(int mode,
        const float* __restrict__ A, const float* __restrict__ B0,
        const float* __restrict__ B1, const float* __restrict__ bias,
        float* __restrict__ Cext){
    __shared__ float As[128][40];
    __shared__ float Bs[128][40];
    int z = blockIdx.z;
    const float* Ap; const float* Bp; float* Cp;
    int ldb, ldc;
    if (mode==0){
        Ap = A; Bp = z ? B1 : B0; ldb = 256;
        Cp = z ? &g_Vm[0] : &g_K[0]; ldc = 256;
    } else if (mode==1){
        Ap = A;                                  // P [256,256]
        Bp = &g_W3T[0][0] + (long)z*65536; ldb = 256;
        Cp = &g_M[0] + (long)z*65536; ldc = 256;
    } else if (mode==2){
        Ap = A;                                  // emb [512,256]
        Bp = &g_M[0] + (long)z*65536; ldb = 256;
        Cp = &g_Gp[0][0] + (long)(z/5)*655360 + (long)(z%5)*131072; ldc = 256;
    } else {
        Ap = &g_F[0][0] + (long)z*8192*256;
        Bp = B0; ldb = 256;
        Cp = Cext + 1 + (long)z*8192*512; ldc = 512;
    }
    int row0 = blockIdx.x*128, col0 = blockIdx.y*128;
    int t = threadIdx.x, wid = t>>5, lane = t&31;
    int wm = wid>>2, wn = wid&3;

    wmma::fragment<wmma::accumulator,16,16,8,float> acc[4][2];
#pragma unroll
    for (int mi=0;mi<4;mi++)
#pragma unroll
        for (int ni=0;ni<2;ni++) wmma::fill_fragment(acc[mi][ni], 0.f);

    float4 pa[4], pb[4];
#pragma unroll
    for (int u=0;u<4;u++){
        int i = t + u*256, r = i>>3, c = (i&7)*4;
        pa[u] = *(const float4*)&Ap[(long)(row0+r)*256 + c];
        pb[u] = *(const float4*)&Bp[(long)(col0+r)*ldb + c];
    }

    for (int kb=0; kb<256; kb+=32){
        __syncthreads();
#pragma unroll
        for (int u=0;u<4;u++){
            int i = t + u*256, r = i>>3, c = (i&7)*4;
            As[r][c+0]=f2tf(pa[u].x); As[r][c+1]=f2tf(pa[u].y);
            As[r][c+2]=f2tf(pa[u].z); As[r][c+3]=f2tf(pa[u].w);
            Bs[r][c+0]=f2tf(pb[u].x); Bs[r][c+1]=f2tf(pb[u].y);
            Bs[r][c+2]=f2tf(pb[u].z); Bs[r][c+3]=f2tf(pb[u].w);
        }
        if (kb < 224){
#pragma unroll
            for (int u=0;u<4;u++){
                int i = t + u*256, r = i>>3, c = (i&7)*4;
                pa[u] = *(const float4*)&Ap[(long)(row0+r)*256 + kb+32 + c];
                pb[u] = *(const float4*)&Bp[(long)(col0+r)*ldb + kb+32 + c];
            }
        }
        __syncthreads();
#pragma unroll
        for (int k8=0;k8<4;k8++){
            wmma::fragment<wmma::matrix_a,16,16,8,wmma::precision::tf32,wmma::row_major> af[4];
            wmma::fragment<wmma::matrix_b,16,16,8,wmma::precision::tf32,wmma::col_major> bf[2];
#pragma unroll
            for (int mi=0;mi<4;mi++)
                wmma::load_matrix_sync(af[mi], &As[wm*64 + mi*16][k8*8], 40);
#pragma unroll
            for (int ni=0;ni<2;ni++)
                wmma::load_matrix_sync(bf[ni], &Bs[wn*32 + ni*16][k8*8], 40);
#pragma unroll
            for (int mi=0;mi<4;mi++)
#pragma unroll
                for (int ni=0;ni<2;ni++)
                    wmma::mma_sync(acc[mi][ni], af[mi], bf[ni], acc[mi][ni]);
        }
    }
    if (mode != 3){
#pragma unroll
        for (int mi=0;mi<4;mi++)
#pragma unroll
            for (int ni=0;ni<2;ni++)
                wmma::store_matrix_sync(&Cp[(long)(row0+wm*64+mi*16)*ldc + col0 + wn*32 + ni*16],
                                        acc[mi][ni], ldc, wmma::mem_row_major);
    } else {
        __syncthreads();
        float* stage = &As[0][0] + wid*(16*18);
#pragma unroll
        for (int mi=0;mi<4;mi++)
#pragma unroll
            for (int ni=0;ni<2;ni++){
                wmma::store_matrix_sync(stage, acc[mi][ni], 18, wmma::mem_row_major);
                __syncwarp();
                for (int e=lane; e<256; e+=32){
                    int r = e>>4, c = e&15;
                    int col = col0 + wn*32 + ni*16 + c;
                    Cp[(long)(row0+wm*64+mi*16+r)*ldc + col] = stage[r*18+c] + bias[col];
                }
                __syncwarp();
            }
    }
}

// ---------------- LN (+bias) in place on g_K / g_Vm -------------------------
__global__ void k_ln(const float* __restrict__ kb, const float* __restrict__ vb,
                     const float* __restrict__ gamma, const float* __restrict__ beta){
    int z = blockIdx.y;
    float* X = z ? &g_Vm[0] : &g_K[0];
    const float* bias = z ? vb : kb;
    int wid = threadIdx.x>>5, lane = threadIdx.x&31;
    long row = (long)blockIdx.x*8 + wid;
    float4* R = (float4*)(X + row*256);
    const float4* B4 = (const float4*)bias;
    const float4* G4 = (const float4*)gamma;
    const float4* T4 = (const float4*)beta;
    float4 x0 = R[lane], x1 = R[lane+32];
    float4 b0 = B4[lane], b1 = B4[lane+32];
    x0.x+=b0.x; x0.y+=b0.y; x0.z+=b0.z; x0.w+=b0.w;
    x1.x+=b1.x; x1.y+=b1.y; x1.z+=b1.z; x1.w+=b1.w;
    float s  = x0.x+x0.y+x0.z+x0.w + x1.x+x1.y+x1.z+x1.w;
    float s2 = x0.x*x0.x+x0.y*x0.y+x0.z*x0.z+x0.w*x0.w
             + x1.x*x1.x+x1.y*x1.y+x1.z*x1.z+x1.w*x1.w;
    s = warpSum(s); s2 = warpSum(s2);
    float m = s*(1.f/256.f);
    float r = rsqrtf(s2*(1.f/256.f) - m*m + 1e-5f);
    float4 g0 = G4[lane], g1 = G4[lane+32];
    float4 t0 = T4[lane], t1 = T4[lane+32];
    float4 o0, o1;
    o0.x=(x0.x-m)*r*g0.x+t0.x; o0.y=(x0.y-m)*r*g0.y+t0.y;
    o0.z=(x0.z-m)*r*g0.z+t0.z; o0.w=(x0.w-m)*r*g0.w+t0.w;
    o1.x=(x1.x-m)*r*g1.x+t1.x; o1.y=(x1.y-m)*r*g1.y+t1.y;
    o1.z=(x1.z-m)*r*g1.z+t1.z; o1.w=(x1.w-m)*r*g1.w+t1.w;
    R[lane] = o0; R[lane+32] = o1;
}

// ---------------- dir' = dir_tok @ P^T + bias ----------------
__global__ void k_dirb(const float* __restrict__ dl, const float* __restrict__ dr,
                       const float* __restrict__ P, const float* __restrict__ pb){
    int dir = blockIdx.x;
    const float* dv = dir ? dr : dl;
    int d = threadIdx.x;
    float s = pb[d];
    for (int i=0;i<256;i++) s += dv[i]*P[d*Dc + i];
    g_dirb[dir][d] = s;
}

// ---------------- Q = LN(sum_s Gp[s,id_s] + dir') ----------------
__global__ void k_q(const int* __restrict__ idl, const int* __restrict__ idr,
                    const float* __restrict__ gamma, const float* __restrict__ beta){
    int dir = blockIdx.y;
    int bl  = blockIdx.x;
    const int* ids = (dir ? idr : idl) + bl*Sc;
    __shared__ int sid[8];
    __shared__ float red[32];
    int d = threadIdx.x;
    if (d < Sc) sid[d] = ids[d];
    __syncthreads();
    float v = g_dirb[dir][d];
#pragma unroll
    for (int s=0;s<Sc;s++) v += g_Gp[dir][(s*Vc + sid[s])*Dc + d];
    float m   = blockSum(v, red) * (1.f/256.f);
    float dv  = v - m;
    float var = blockSum(dv*dv, red) * (1.f/256.f);
    float o   = dv * rsqrtf(var + 1e-5f) * gamma[d] + beta[d];
    g_Q[dir][bl*Dc + d] = o;
}

// ---------------- flash attention, tf32 mma, no-max softmax ------------------
// scores are bounded (~|6|) because Q,K are LayerNorm outputs scaled by 1/5.66τ,
// so exp() without max subtraction is numerically safe.
__global__ void __launch_bounds__(256) k_attn(const float* __restrict__ mask,
                                              const float* __restrict__ tau_p){
    extern __shared__ float sm[];
    float* Ksm  = sm;                    // [2][32][36]
    float* Vtsm = Ksm + 2*32*36;         // [2][32][36] transposed: [dh][n]
    float* Msm  = Vtsm + 2*32*36;        // [128][36]
    float* Psm  = Msm + 128*36;          // [2][128][36]
    int lt = blockIdx.x >> 2, hp = blockIdx.x & 3;
    int b = blockIdx.y, dir = blockIdx.z;
    int l0 = lt*128;
    int t = threadIdx.x, wid = t>>5, lane = t&31;
    int wg = wid>>2, wr = wid&3;
    int lq = lane>>2, lr = lane&3;
    float tau = fminf(fmaxf(tau_p[0],0.25f),4.f);
    float scale = 1.f/(5.656854249f*tau);

    const float* Qbase = (dir ? g_Q[1] : g_Q[0]) + (long)(b*Lc + l0)*Dc + hp*64;
    for (int i=t; i<2048; i+=256){
        int hh = i>>10, rem = i&1023, row = rem>>3, c4 = rem&7;
        *(float4*)&Psm[(hh*128+row)*36 + c4*4] =
            *(const float4*)&Qbase[(long)row*Dc + hh*32 + c4*4];
    }
    __syncthreads();
    uint32_t qa[2][4][4];
    {
        const float* Qh = Psm + wg*128*36;
#pragma unroll
        for (int mi=0;mi<2;mi++)
#pragma unroll
        for (int k8=0;k8<4;k8++){
            int r = wr*32 + mi*16 + lq, c = k8*8 + lr;
            qa[mi][k8][0] = f2tf_u(Qh[r*36 + c]);
            qa[mi][k8][1] = f2tf_u(Qh[(r+8)*36 + c]);
            qa[mi][k8][2] = f2tf_u(Qh[r*36 + c+4]);
            qa[mi][k8][3] = f2tf_u(Qh[(r+8)*36 + c+4]);
        }
    }
    float o[2][4][4];
#pragma unroll
    for (int mi=0;mi<2;mi++)
#pragma unroll
        for (int ni=0;ni<4;ni++)
#pragma unroll
            for (int e=0;e<4;e++) o[mi][ni][e]=0.f;
    float lsum[4] = {0.f,0.f,0.f,0.f};

    const float* Kg = g_K  + (long)(b*Nc)*Dc + hp*64;
    const float* Vg = g_Vm + (long)(b*Nc)*Dc + hp*64;
    const float* Mg = mask + (long)(b*Lc + l0)*Nc;
    float* Ph = Psm + wg*128*36;

    for (int n0=0; n0<Nc; n0+=32){
        __syncthreads();
        for (int i=t; i<512; i+=256){
            int hh = i>>8, rem = i&255, n = rem>>3, c4 = rem&7;
            float4 kv = *(const float4*)&Kg[(long)(n0+n)*Dc + hh*32 + c4*4];
            float* d = &Ksm[(hh*32+n)*36 + c4*4];
            d[0]=f2tf(kv.x); d[1]=f2tf(kv.y); d[2]=f2tf(kv.z); d[3]=f2tf(kv.w);
        }
        for (int i=t; i<512; i+=256){
            int hh = i>>8, rem = i&255, n = rem>>3, c4 = rem&7;
            float4 vv = *(const float4*)&Vg[(long)(n0+n)*Dc + hh*32 + c4*4];
            float* base = &Vtsm[hh*32*36];
            base[(c4*4+0)*36+n] = f2tf(vv.x);
            base[(c4*4+1)*36+n] = f2tf(vv.y);
            base[(c4*4+2)*36+n] = f2tf(vv.z);
            base[(c4*4+3)*36+n] = f2tf(vv.w);
        }
        for (int i=t; i<1024; i+=256){
            int row = i>>3, c4 = i&7;
            *(float4*)&Msm[row*36 + c4*4] = *(const float4*)&Mg[(long)row*Nc + n0 + c4*4];
        }
        __syncthreads();

        float sc[2][4][4];
#pragma unroll
        for (int mi=0;mi<2;mi++)
#pragma unroll
            for (int ni=0;ni<4;ni++)
#pragma unroll
                for (int e=0;e<4;e++) sc[mi][ni][e]=0.f;
        const float* Kh = Ksm + wg*32*36;
#pragma unroll
        for (int k8=0;k8<4;k8++){
            uint32_t bf[4][2];
#pragma unroll
            for (int ni=0;ni<4;ni++){
                bf[ni][0] = __float_as_uint(Kh[(ni*8+lq)*36 + k8*8 + lr]);
                bf[ni][1] = __float_as_uint(Kh[(ni*8+lq)*36 + k8*8 + lr + 4]);
            }
#pragma unroll
            for (int mi=0;mi<2;mi++)
#pragma unroll
                for (int ni=0;ni<4;ni++)
                    mma_tf32(sc[mi][ni], qa[mi][k8], bf[ni]);
        }
        // direct (no-max) softmax accumulation
#pragma unroll
        for (int mi=0;mi<2;mi++)
#pragma unroll
        for (int half=0;half<2;half++){
            int q = mi*2+half;
            int row = wr*32 + mi*16 + half*8 + lq;
            float ls = 0.f;
#pragma unroll
            for (int ni=0;ni<4;ni++){
                float m0 = Msm[row*36 + ni*8 + 2*lr];
                float m1 = Msm[row*36 + ni*8 + 2*lr + 1];
                float p0 = __expf(sc[mi][ni][half*2]   * scale * m0);
                float p1 = __expf(sc[mi][ni][half*2+1] * scale * m1);
                ls += p0 + p1;
                float2 pp; pp.x = f2tf(p0); pp.y = f2tf(p1);
                *(float2*)&Ph[row*36 + ni*8 + 2*lr] = pp;
            }
            ls += __shfl_xor_sync(0xffffffffu, ls, 1);
            ls += __shfl_xor_sync(0xffffffffu, ls, 2);
            lsum[q] += ls;
        }
        __syncwarp();
        // O += P @ V
        const float* Vh = Vtsm + wg*32*36;
#pragma unroll
        for (int k8=0;k8<4;k8++){
            uint32_t pa[2][4];
#pragma unroll
            for (int mi=0;mi<2;mi++){
                int r = wr*32 + mi*16 + lq, c = k8*8+lr;
                pa[mi][0] = __float_as_uint(Ph[r*36 + c]);
                pa[mi][1] = __float_as_uint(Ph[(r+8)*36 + c]);
                pa[mi][2] = __float_as_uint(Ph[r*36 + c+4]);
                pa[mi][3] = __float_as_uint(Ph[(r+8)*36 + c+4]);
            }
            uint32_t vb[4][2];
#pragma unroll
            for (int ni=0;ni<4;ni++){
                vb[ni][0] = __float_as_uint(Vh[(ni*8+lq)*36 + k8*8 + lr]);
                vb[ni][1] = __float_as_uint(Vh[(ni*8+lq)*36 + k8*8 + lr + 4]);
            }
#pragma unroll
            for (int mi=0;mi<2;mi++)
#pragma unroll
                for (int ni=0;ni<4;ni++)
                    mma_tf32(o[mi][ni], pa[mi], vb[ni]);
        }
    }
    float* Fg = (dir ? g_F[1] : g_F[0]) + (long)(b*Lc + l0)*Dc + (hp*2+wg)*32;
#pragma unroll
    for (int mi=0;mi<2;mi++)
#pragma unroll
    for (int half=0;half<2;half++){
        int q = mi*2+half;
        int row = wr*32 + mi*16 + half*8 + lq;
        float inv = 1.f/lsum[q];
#pragma unroll
        for (int ni=0;ni<4;ni++){
            float2 oo;
            oo.x = o[mi][ni][half*2]*inv;
            oo.y = o[mi][ni][half*2+1]*inv;
            *(float2*)&Fg[(long)row*Dc + ni*8 + 2*lr] = oo;
        }
    }
}

// ---------------- agreement loss ----------------
__global__ void k_loss(const float* __restrict__ out, const float* __restrict__ tmask){
    int l = blockIdx.x;
    int b = blockIdx.y;
    const float* rl = out + 1 + (long)(b*Lc + l)*Vc;
    const float* rr = out + 1 + (long)Bc*Lc*Vc + (long)(b*Lc + l + 1)*Vc;
    __shared__ float red[32];
    int t = threadIdx.x;
    float xl0 = rl[t]*0.5f,     xl1 = rl[t+256]*0.5f;
    float xr0 = rr[t]*0.5f,     xr1 = rr[t+256]*0.5f;
    float ml = blockMax(fmaxf(xl0,xl1), red);
    float el0 = __expf(xl0-ml), el1 = __expf(xl1-ml);
    float sl = blockSum(el0+el1, red);
    float mr = blockMax(fmaxf(xr0,xr1), red);
    float er0 = __expf(xr0-mr), er1 = __expf(xr1-mr);
    float sr = blockSum(er0+er1, red);
    float pl0 = el0/sl, pl1 = el1/sl;
    float pr0 = er0/sr, pr1 = er1/sr;
    float d0 = pl0-pr0, d1 = pl1-pr1;
    float agree = blockSum(d0*d0 + d1*d1, red);
    if (t == 0) atomicAdd(&g_num, agree * tmask[b*Lc + l]);
}

__global__ void k_final(const float* __restrict__ tmask, float* __restrict__ out){
    __shared__ float red[32];
    float s = 0.f;
    for (int e=threadIdx.x; e<Bc*Lc; e+=256){
        int l = e % Lc;
        if (l < Lc-1) s += tmask[e];
    }
    s = blockSum(s, red);
    if (threadIdx.x == 0){
        float den = fmaxf(s, 1.0f);
        out[0] = 0.1f * g_num / den;
    }
}

// ---------------- launch ----------------------------------------------------
extern "C" void kernel_launch(void* const* d_in, const int* in_sizes, int n_in,
                              void* d_out, int out_size){
    const float* vis   = (const float*)d_in[0];
    const int*   idl   = (const int*)  d_in[1];
    const int*   idr   = (const int*)  d_in[2];
    const float* tmask = (const float*)d_in[4];
    const float* vmask = (const float*)d_in[5];
    const float* emb   = (const float*)d_in[6];
    const float* dl    = (const float*)d_in[7];
    const float* dr    = (const float*)d_in[8];
    const float* pw    = (const float*)d_in[9];
    const float* pb    = (const float*)d_in[10];
    const float* qg    = (const float*)d_in[11];
    const float* qb    = (const float*)d_in[12];
    const float* kw    = (const float*)d_in[13];
    const float* kb    = (const float*)d_in[14];
    const float* vw    = (const float*)d_in[15];
    const float* vb    = (const float*)d_in[16];
    const float* kvg   = (const float*)d_in[17];
    const float* kvb   = (const float*)d_in[18];
    const float* tau   = (const float*)d_in[19];
    const float* clsb  = (const float*)d_in[20];
    const float* cwl   = (const float*)d_in[21];
    const float* cwr   = (const float*)d_in[22];
    float* out = (float*)d_out;

    const int SM_ATTN = 73728;
    cudaFuncSetAttribute(k_attn, cudaFuncAttributeMaxDynamicSharedMemorySize, SM_ATTN);

    k_zero<<<1, 32>>>();
    k_w3<<<dim3(1280,2), 256>>>(cwl, cwr);
    k_gemm<<<dim3(2,2,10), 256>>>(1, pw, nullptr, nullptr, nullptr, nullptr);
    k_gemm<<<dim3(4,2,10), 256>>>(2, emb, nullptr, nullptr, nullptr, nullptr);
    k_dirb<<<2, 256>>>(dl, dr, pw, pb);
    k_q<<<dim3(Bc*Lc,2), 256>>>(idl, idr, qg, qb);
    k_gemm<<<dim3(256,2,2), 256>>>(0, vis, kw, vw, nullptr, nullptr);
    k_ln<<<dim3(4096,2), 256>>>(kb, vb, kvg, kvb);
    k_attn<<<dim3(8,32,2), 256, SM_ATTN>>>(vmask, tau);
    k_gemm<<<dim3(64,4,2), 256>>>(3, nullptr, emb, nullptr, clsb, out);
    k_loss<<<dim3(Lc-1, Bc), 256>>>(out, tmask);
    k_final<<<1, 256>>>(tmask, out);
}

// round 8
// speedup vs baseline: 2.5611x; 1.5252x over previous
#include <cuda_runtime.h>
#include <cstdint>
#include <math.h>
#include <mma.h>
using namespace nvcuda;

#define Bc  32
#define Lc  256
#define Sc  5
#define Nc  1024
#define Dc  256
#define Vc  512
#define Hc  8
#define DHc 32

// ---------------- scratch ----------------
__device__ float g_W3T[2][Sc*Dc*Dc];     // [dir][(s*256+j)*256 + dt]
__device__ float g_M[10*Dc*Dc];          // [dir*5+s][d*256 + j]
__device__ float g_Gp[2][Sc*Vc*Dc];
__device__ float g_dirb[2][Dc];
__device__ float g_Q[2][Bc*Lc*Dc];
__device__ float g_K[Bc*Nc*Dc];
__device__ float g_Vm[Bc*Nc*Dc];
__device__ float g_F[2][Bc*Lc*Dc];
__device__ float g_num;

// ---------------- helpers ----------------
__device__ __forceinline__ float warpSum(float v){
#pragma unroll
    for (int o=16;o>0;o>>=1) v += __shfl_xor_sync(0xffffffffu, v, o);
    return v;
}
__device__ __forceinline__ float warpMax(float v){
#pragma unroll
    for (int o=16;o>0;o>>=1) v = fmaxf(v, __shfl_xor_sync(0xffffffffu, v, o));
    return v;
}
__device__ __forceinline__ float blockSum(float v, float* red){
    v = warpSum(v);
    int w = threadIdx.x >> 5;
    __syncthreads();
    if ((threadIdx.x & 31) == 0) red[w] = v;
    __syncthreads();
    if (w == 0){
        float r = (threadIdx.x < 8) ? red[threadIdx.x] : 0.f;
        r = warpSum(r);
        if (threadIdx.x == 0) red[0] = r;
    }
    __syncthreads();
    return red[0];
}
__device__ __forceinline__ float blockMax(float v, float* red){
    v = warpMax(v);
    int w = threadIdx.x >> 5;
    __syncthreads();
    if ((threadIdx.x & 31) == 0) red[w] = v;
    __syncthreads();
    if (w == 0){
        float r = (threadIdx.x < 8) ? red[threadIdx.x] : -1e30f;
        r = warpMax(r);
        if (threadIdx.x == 0) red[0] = r;
    }
    __syncthreads();
    return red[0];
}
__device__ __forceinline__ float f2tf(float x){
    uint32_t u; asm("cvt.rna.tf32.f32 %0, %1;" : "=r"(u) : "f"(x));
    return __uint_as_float(u);
}
__device__ __forceinline__ uint32_t f2tf_u(float x){
    uint32_t u; asm("cvt.rna.tf32.f32 %0, %1;" : "=r"(u) : "f"(x));
    return u;
}
__device__ __forceinline__ void mma_tf32(float* c, const uint32_t* a, const uint32_t* b){
    asm volatile("mma.sync.aligned.m16n8k8.row.col.f32.tf32.tf32.f32 "
        "{%0,%1,%2,%3}, {%4,%5,%6,%7}, {%8,%9}, {%0,%1,%2,%3};"
        : "+f"(c[0]),"+f"(c[1]),"+f"(c[2]),"+f"(c[3])
        : "r"(a[0]),"r"(a[1]),"r"(a[2]),"r"(a[3]), "r"(b[0]),"r"(b[1]));
}

// ---------------- k0 ----------------
__global__ void k_zero(){ if (threadIdx.x == 0) g_num = 0.f; }

// ---------------- k1: fold conv + scrambled-mean into W3^T ------------------
__global__ void k_w3(const float* __restrict__ wl, const float* __restrict__ wr){
    int dir = blockIdx.y;
    const float* w = dir ? wr : wl;
    int idx = blockIdx.x*256 + threadIdx.x;
    int dt = idx & 255;
    int sj = idx >> 8;
    int s = sj / 256, j = sj % 256;
    float v = 0.f;
#pragma unroll
    for (int k=0;k<5;k++){
        int f = dt + 256*k;
        int o = f/5, sk = f%5;
        int tp = s - sk + 1;
        if (tp >= 0 && tp < 3) v += w[(o*Dc + j)*3 + tp];
    }
    g_W3T[dir][(s*Dc + j)*Dc + dt] = 0.2f*v;
}

// ---------------- generic tf32 GEMM: C = A @ B^T (+bias on mode 3) ----------
__global__ void __launch_bounds__(256,2) k_gemm(int mode,
        const float* __restrict__ A, const float* __restrict__ B0,
        const float* __restrict__ B1, const float* __restrict__ bias,
        float* __restrict__ Cext){
    __shared__ float As[128][40];
    __shared__ float Bs[128][40];
    int z = blockIdx.z;
    const float* Ap; const float* Bp; float* Cp;
    int ldb, ldc;
    if (mode==0){
        Ap = A; Bp = z ? B1 : B0; ldb = 256;
        Cp = z ? &g_Vm[0] : &g_K[0]; ldc = 256;
    } else if (mode==1){
        Ap = A;
        Bp = &g_W3T[0][0] + (long)z*65536; ldb = 256;
        Cp = &g_M[0] + (long)z*65536; ldc = 256;
    } else if (mode==2){
        Ap = A;
        Bp = &g_M[0] + (long)z*65536; ldb = 256;
        Cp = &g_Gp[0][0] + (long)(z/5)*655360 + (long)(z%5)*131072; ldc = 256;
    } else {
        Ap = &g_F[0][0] + (long)z*8192*256;
        Bp = B0; ldb = 256;
        Cp = Cext + 1 + (long)z*8192*512; ldc = 512;
    }
    int row0 = blockIdx.x*128, col0 = blockIdx.y*128;
    int t = threadIdx.x, wid = t>>5, lane = t&31;
    int wm = wid>>2, wn = wid&3;

    wmma::fragment<wmma::accumulator,16,16,8,float> acc[4][2];
#pragma unroll
    for (int mi=0;mi<4;mi++)
#pragma unroll
        for (int ni=0;ni<2;ni++) wmma::fill_fragment(acc[mi][ni], 0.f);

    float4 pa[4], pb[4];
#pragma unroll
    for (int u=0;u<4;u++){
        int i = t + u*256, r = i>>3, c = (i&7)*4;
        pa[u] = *(const float4*)&Ap[(long)(row0+r)*256 + c];
        pb[u] = *(const float4*)&Bp[(long)(col0+r)*ldb + c];
    }

    for (int kb=0; kb<256; kb+=32){
        __syncthreads();
#pragma unroll
        for (int u=0;u<4;u++){
            int i = t + u*256, r = i>>3, c = (i&7)*4;
            As[r][c+0]=f2tf(pa[u].x); As[r][c+1]=f2tf(pa[u].y);
            As[r][c+2]=f2tf(pa[u].z); As[r][c+3]=f2tf(pa[u].w);
            Bs[r][c+0]=f2tf(pb[u].x); Bs[r][c+1]=f2tf(pb[u].y);
            Bs[r][c+2]=f2tf(pb[u].z); Bs[r][c+3]=f2tf(pb[u].w);
        }
        if (kb < 224){
#pragma unroll
            for (int u=0;u<4;u++){
                int i = t + u*256, r = i>>3, c = (i&7)*4;
                pa[u] = *(const float4*)&Ap[(long)(row0+r)*256 + kb+32 + c];
                pb[u] = *(const float4*)&Bp[(long)(col0+r)*ldb + kb+32 + c];
            }
        }
        __syncthreads();
#pragma unroll
        for (int k8=0;k8<4;k8++){
            wmma::fragment<wmma::matrix_a,16,16,8,wmma::precision::tf32,wmma::row_major> af[4];
            wmma::fragment<wmma::matrix_b,16,16,8,wmma::precision::tf32,wmma::col_major> bf[2];
#pragma unroll
            for (int mi=0;mi<4;mi++)
                wmma::load_matrix_sync(af[mi], &As[wm*64 + mi*16][k8*8], 40);
#pragma unroll
            for (int ni=0;ni<2;ni++)
                wmma::load_matrix_sync(bf[ni], &Bs[wn*32 + ni*16][k8*8], 40);
#pragma unroll
            for (int mi=0;mi<4;mi++)
#pragma unroll
                for (int ni=0;ni<2;ni++)
                    wmma::mma_sync(acc[mi][ni], af[mi], bf[ni], acc[mi][ni]);
        }
    }
    if (mode != 3){
#pragma unroll
        for (int mi=0;mi<4;mi++)
#pragma unroll
            for (int ni=0;ni<2;ni++)
                wmma::store_matrix_sync(&Cp[(long)(row0+wm*64+mi*16)*ldc + col0 + wn*32 + ni*16],
                                        acc[mi][ni], ldc, wmma::mem_row_major);
    } else {
        __syncthreads();
        float* stage = &As[0][0] + wid*(16*18);
#pragma unroll
        for (int mi=0;mi<4;mi++)
#pragma unroll
            for (int ni=0;ni<2;ni++){
                wmma::store_matrix_sync(stage, acc[mi][ni], 18, wmma::mem_row_major);
                __syncwarp();
                for (int e=lane; e<256; e+=32){
                    int r = e>>4, c = e&15;
                    int col = col0 + wn*32 + ni*16 + c;
                    Cp[(long)(row0+wm*64+mi*16+r)*ldc + col] = stage[r*18+c] + bias[col];
                }
                __syncwarp();
            }
    }
}

// ---------------- LN (+bias) in place on g_K / g_Vm -------------------------
__global__ void k_ln(const float* __restrict__ kb, const float* __restrict__ vb,
                     const float* __restrict__ gamma, const float* __restrict__ beta){
    int z = blockIdx.y;
    float* X = z ? &g_Vm[0] : &g_K[0];
    const float* bias = z ? vb : kb;
    int wid = threadIdx.x>>5, lane = threadIdx.x&31;
    long row = (long)blockIdx.x*8 + wid;
    float4* R = (float4*)(X + row*256);
    const float4* B4 = (const float4*)bias;
    const float4* G4 = (const float4*)gamma;
    const float4* T4 = (const float4*)beta;
    float4 x0 = R[lane], x1 = R[lane+32];
    float4 b0 = B4[lane], b1 = B4[lane+32];
    x0.x+=b0.x; x0.y+=b0.y; x0.z+=b0.z; x0.w+=b0.w;
    x1.x+=b1.x; x1.y+=b1.y; x1.z+=b1.z; x1.w+=b1.w;
    float s  = x0.x+x0.y+x0.z+x0.w + x1.x+x1.y+x1.z+x1.w;
    float s2 = x0.x*x0.x+x0.y*x0.y+x0.z*x0.z+x0.w*x0.w
             + x1.x*x1.x+x1.y*x1.y+x1.z*x1.z+x1.w*x1.w;
    s = warpSum(s); s2 = warpSum(s2);
    float m = s*(1.f/256.f);
    float r = rsqrtf(s2*(1.f/256.f) - m*m + 1e-5f);
    float4 g0 = G4[lane], g1 = G4[lane+32];
    float4 t0 = T4[lane], t1 = T4[lane+32];
    float4 o0, o1;
    o0.x=(x0.x-m)*r*g0.x+t0.x; o0.y=(x0.y-m)*r*g0.y+t0.y;
    o0.z=(x0.z-m)*r*g0.z+t0.z; o0.w=(x0.w-m)*r*g0.w+t0.w;
    o1.x=(x1.x-m)*r*g1.x+t1.x; o1.y=(x1.y-m)*r*g1.y+t1.y;
    o1.z=(x1.z-m)*r*g1.z+t1.z; o1.w=(x1.w-m)*r*g1.w+t1.w;
    R[lane] = o0; R[lane+32] = o1;
}

// ---------------- dir' = dir_tok @ P^T + bias ----------------
__global__ void k_dirb(const float* __restrict__ dl, const float* __restrict__ dr,
                       const float* __restrict__ P, const float* __restrict__ pb){
    int dir = blockIdx.x;
    const float* dv = dir ? dr : dl;
    int d = threadIdx.x;
    float s = pb[d];
    for (int i=0;i<256;i++) s += dv[i]*P[d*Dc + i];
    g_dirb[dir][d] = s;
}

// ---------------- Q = LN(sum_s Gp[s,id_s] + dir') ----------------
__global__ void k_q(const int* __restrict__ idl, const int* __restrict__ idr,
                    const float* __restrict__ gamma, const float* __restrict__ beta){
    int dir = blockIdx.y;
    int bl  = blockIdx.x;
    const int* ids = (dir ? idr : idl) + bl*Sc;
    __shared__ int sid[8];
    __shared__ float red[32];
    int d = threadIdx.x;
    if (d < Sc) sid[d] = ids[d];
    __syncthreads();
    float v = g_dirb[dir][d];
#pragma unroll
    for (int s=0;s<Sc;s++) v += g_Gp[dir][(s*Vc + sid[s])*Dc + d];
    float m   = blockSum(v, red) * (1.f/256.f);
    float dv  = v - m;
    float var = blockSum(dv*dv, red) * (1.f/256.f);
    float o   = dv * rsqrtf(var + 1e-5f) * gamma[d] + beta[d];
    g_Q[dir][bl*Dc + d] = o;
}

// ---------------- flash attention, tf32 mma, no-max softmax ------------------
// K pre-scaled by scale*log2e at staging; p = exp2f(sc * mask).
// V staged in NATURAL [n][dh] layout (PV B-fragment (k=n, col=dh) maps directly);
// pad 40 makes all fragment LDS and staging STS bank-conflict-free.
#define LDA 40
__global__ void __launch_bounds__(256,2) k_attn(const float* __restrict__ mask,
                                                const float* __restrict__ tau_p){
    extern __shared__ float sm[];
    float* Ksm  = sm;                    // [2][32][40]
    float* Vsm  = Ksm + 2*32*LDA;        // [2][32][40] natural [n][dh]
    float* Msm  = Vsm + 2*32*LDA;        // [128][40]
    float* Psm  = Msm + 128*LDA;         // [2][128][40]
    int lt = blockIdx.x >> 2, hp = blockIdx.x & 3;
    int b = blockIdx.y, dir = blockIdx.z;
    int l0 = lt*128;
    int t = threadIdx.x, wid = t>>5, lane = t&31;
    int wg = wid>>2, wr = wid&3;
    int lq = lane>>2, lr = lane&3;
    float tau = fminf(fmaxf(tau_p[0],0.25f),4.f);
    float kscale = 1.44269504f/(5.656854249f*tau);   // scale * log2(e)

    const float* Qbase = (dir ? g_Q[1] : g_Q[0]) + (long)(b*Lc + l0)*Dc + hp*64;
    for (int i=t; i<2048; i+=256){
        int hh = i>>10, rem = i&1023, row = rem>>3, c4 = rem&7;
        *(float4*)&Psm[(hh*128+row)*LDA + c4*4] =
            *(const float4*)&Qbase[(long)row*Dc + hh*32 + c4*4];
    }
    __syncthreads();
    uint32_t qa[2][4][4];
    {
        const float* Qh = Psm + wg*128*LDA;
#pragma unroll
        for (int mi=0;mi<2;mi++)
#pragma unroll
        for (int k8=0;k8<4;k8++){
            int r = wr*32 + mi*16 + lq, c = k8*8 + lr;
            qa[mi][k8][0] = f2tf_u(Qh[r*LDA + c]);
            qa[mi][k8][1] = f2tf_u(Qh[(r+8)*LDA + c]);
            qa[mi][k8][2] = f2tf_u(Qh[r*LDA + c+4]);
            qa[mi][k8][3] = f2tf_u(Qh[(r+8)*LDA + c+4]);
        }
    }
    float o[2][4][4];
#pragma unroll
    for (int mi=0;mi<2;mi++)
#pragma unroll
        for (int ni=0;ni<4;ni++)
#pragma unroll
            for (int e=0;e<4;e++) o[mi][ni][e]=0.f;
    float lsum[4] = {0.f,0.f,0.f,0.f};

    const float* Kg = g_K  + (long)(b*Nc)*Dc + hp*64;
    const float* Vg = g_Vm + (long)(b*Nc)*Dc + hp*64;
    const float* Mg = mask + (long)(b*Lc + l0)*Nc;
    float* Ph = Psm + wg*128*LDA;

    for (int n0=0; n0<Nc; n0+=32){
        __syncthreads();
        for (int i=t; i<512; i+=256){
            int hh = i>>8, rem = i&255, n = rem>>3, c4 = rem&7;
            float4 kv = *(const float4*)&Kg[(long)(n0+n)*Dc + hh*32 + c4*4];
            float* d = &Ksm[(hh*32+n)*LDA + c4*4];
            d[0]=f2tf(kv.x*kscale); d[1]=f2tf(kv.y*kscale);
            d[2]=f2tf(kv.z*kscale); d[3]=f2tf(kv.w*kscale);
            float4 vv = *(const float4*)&Vg[(long)(n0+n)*Dc + hh*32 + c4*4];
            float* dv = &Vsm[(hh*32+n)*LDA + c4*4];
            dv[0]=f2tf(vv.x); dv[1]=f2tf(vv.y);
            dv[2]=f2tf(vv.z); dv[3]=f2tf(vv.w);
        }
        for (int i=t; i<1024; i+=256){
            int row = i>>3, c4 = i&7;
            *(float4*)&Msm[row*LDA + c4*4] = *(const float4*)&Mg[(long)row*Nc + n0 + c4*4];
        }
        __syncthreads();

        float sc[2][4][4];
#pragma unroll
        for (int mi=0;mi<2;mi++)
#pragma unroll
            for (int ni=0;ni<4;ni++)
#pragma unroll
                for (int e=0;e<4;e++) sc[mi][ni][e]=0.f;
        const float* Kh = Ksm + wg*32*LDA;
#pragma unroll
        for (int k8=0;k8<4;k8++){
            uint32_t bf[4][2];
#pragma unroll
            for (int ni=0;ni<4;ni++){
                bf[ni][0] = __float_as_uint(Kh[(ni*8+lq)*LDA + k8*8 + lr]);
                bf[ni][1] = __float_as_uint(Kh[(ni*8+lq)*LDA + k8*8 + lr + 4]);
            }
#pragma unroll
            for (int mi=0;mi<2;mi++)
#pragma unroll
                for (int ni=0;ni<4;ni++)
                    mma_tf32(sc[mi][ni], qa[mi][k8], bf[ni]);
        }
        // direct (no-max) softmax: p = exp2(sc * mask)
#pragma unroll
        for (int mi=0;mi<2;mi++)
#pragma unroll
        for (int half=0;half<2;half++){
            int q = mi*2+half;
            int row = wr*32 + mi*16 + half*8 + lq;
            float ls = 0.f;
#pragma unroll
            for (int ni=0;ni<4;ni++){
                float m0 = Msm[row*LDA + ni*8 + 2*lr];
                float m1 = Msm[row*LDA + ni*8 + 2*lr + 1];
                float p0 = exp2f(sc[mi][ni][half*2]   * m0);
                float p1 = exp2f(sc[mi][ni][half*2+1] * m1);
                ls += p0 + p1;
                float2 pp; pp.x = f2tf(p0); pp.y = f2tf(p1);
                *(float2*)&Ph[row*LDA + ni*8 + 2*lr] = pp;
            }
            ls += __shfl_xor_sync(0xffffffffu, ls, 1);
            ls += __shfl_xor_sync(0xffffffffu, ls, 2);
            lsum[q] += ls;
        }
        __syncwarp();
        // O += P @ V   (V natural [n][dh]: b = V[(k8*8+lr)(+4)][ni*8+lq])
        const float* Vh = Vsm + wg*32*LDA;
#pragma unroll
        for (int k8=0;k8<4;k8++){
            uint32_t pa[2][4];
#pragma unroll
            for (int mi=0;mi<2;mi++){
                int r = wr*32 + mi*16 + lq, c = k8*8+lr;
                pa[mi][0] = __float_as_uint(Ph[r*LDA + c]);
                pa[mi][1] = __float_as_uint(Ph[(r+8)*LDA + c]);
                pa[mi][2] = __float_as_uint(Ph[r*LDA + c+4]);
                pa[mi][3] = __float_as_uint(Ph[(r+8)*LDA + c+4]);
            }
            uint32_t vb[4][2];
#pragma unroll
            for (int ni=0;ni<4;ni++){
                vb[ni][0] = __float_as_uint(Vh[(k8*8+lr)*LDA + ni*8 + lq]);
                vb[ni][1] = __float_as_uint(Vh[(k8*8+lr+4)*LDA + ni*8 + lq]);
            }
#pragma unroll
            for (int mi=0;mi<2;mi++)
#pragma unroll
                for (int ni=0;ni<4;ni++)
                    mma_tf32(o[mi][ni], pa[mi], vb[ni]);
        }
    }
    float* Fg = (dir ? g_F[1] : g_F[0]) + (long)(b*Lc + l0)*Dc + (hp*2+wg)*32;
#pragma unroll
    for (int mi=0;mi<2;mi++)
#pragma unroll
    for (int half=0;half<2;half++){
        int q = mi*2+half;
        int row = wr*32 + mi*16 + half*8 + lq;
        float inv = 1.f/lsum[q];
#pragma unroll
        for (int ni=0;ni<4;ni++){
            float2 oo;
            oo.x = o[mi][ni][half*2]*inv;
            oo.y = o[mi][ni][half*2+1]*inv;
            *(float2*)&Fg[(long)row*Dc + ni*8 + 2*lr] = oo;
        }
    }
}

// ---------------- agreement loss ----------------
__global__ void k_loss(const float* __restrict__ out, const float* __restrict__ tmask){
    int l = blockIdx.x;
    int b = blockIdx.y;
    const float* rl = out + 1 + (long)(b*Lc + l)*Vc;
    const float* rr = out + 1 + (long)Bc*Lc*Vc + (long)(b*Lc + l + 1)*Vc;
    __shared__ float red[32];
    int t = threadIdx.x;
    float xl0 = rl[t]*0.5f,     xl1 = rl[t+256]*0.5f;
    float xr0 = rr[t]*0.5f,     xr1 = rr[t+256]*0.5f;
    float ml = blockMax(fmaxf(xl0,xl1), red);
    float el0 = __expf(xl0-ml), el1 = __expf(xl1-ml);
    float sl = blockSum(el0+el1, red);
    float mr = blockMax(fmaxf(xr0,xr1), red);
    float er0 = __expf(xr0-mr), er1 = __expf(xr1-mr);
    float sr = blockSum(er0+er1, red);
    float pl0 = el0/sl, pl1 = el1/sl;
    float pr0 = er0/sr, pr1 = er1/sr;
    float d0 = pl0-pr0, d1 = pl1-pr1;
    float agree = blockSum(d0*d0 + d1*d1, red);
    if (t == 0) atomicAdd(&g_num, agree * tmask[b*Lc + l]);
}

__global__ void k_final(const float* __restrict__ tmask, float* __restrict__ out){
    __shared__ float red[32];
    float s = 0.f;
    for (int e=threadIdx.x; e<Bc*Lc; e+=256){
        int l = e % Lc;
        if (l < Lc-1) s += tmask[e];
    }
    s = blockSum(s, red);
    if (threadIdx.x == 0){
        float den = fmaxf(s, 1.0f);
        out[0] = 0.1f * g_num / den;
    }
}

// ---------------- launch ----------------------------------------------------
extern "C" void kernel_launch(void* const* d_in, const int* in_sizes, int n_in,
                              void* d_out, int out_size){
    const float* vis   = (const float*)d_in[0];
    const int*   idl   = (const int*)  d_in[1];
    const int*   idr   = (const int*)  d_in[2];
    const float* tmask = (const float*)d_in[4];
    const float* vmask = (const float*)d_in[5];
    const float* emb   = (const float*)d_in[6];
    const float* dl    = (const float*)d_in[7];
    const float* dr    = (const float*)d_in[8];
    const float* pw    = (const float*)d_in[9];
    const float* pb    = (const float*)d_in[10];
    const float* qg    = (const float*)d_in[11];
    const float* qb    = (const float*)d_in[12];
    const float* kw    = (const float*)d_in[13];
    const float* kb    = (const float*)d_in[14];
    const float* vw    = (const float*)d_in[15];
    const float* vb    = (const float*)d_in[16];
    const float* kvg   = (const float*)d_in[17];
    const float* kvb   = (const float*)d_in[18];
    const float* tau   = (const float*)d_in[19];
    const float* clsb  = (const float*)d_in[20];
    const float* cwl   = (const float*)d_in[21];
    const float* cwr   = (const float*)d_in[22];
    float* out = (float*)d_out;

    const int SM_ATTN = (2*32*LDA + 2*32*LDA + 128*LDA + 2*128*LDA)*4;  // 81920
    cudaFuncSetAttribute(k_attn, cudaFuncAttributeMaxDynamicSharedMemorySize, SM_ATTN);

    k_zero<<<1, 32>>>();
    k_w3<<<dim3(1280,2), 256>>>(cwl, cwr);
    k_gemm<<<dim3(2,2,10), 256>>>(1, pw, nullptr, nullptr, nullptr, nullptr);
    k_gemm<<<dim3(4,2,10), 256>>>(2, emb, nullptr, nullptr, nullptr, nullptr);
    k_dirb<<<2, 256>>>(dl, dr, pw, pb);
    k_q<<<dim3(Bc*Lc,2), 256>>>(idl, idr, qg, qb);
    k_gemm<<<dim3(256,2,2), 256>>>(0, vis, kw, vw, nullptr, nullptr);
    k_ln<<<dim3(4096,2), 256>>>(kb, vb, kvg, kvb);
    k_attn<<<dim3(8,32,2), 256, SM_ATTN>>>(vmask, tau);
    k_gemm<<<dim3(64,4,2), 256>>>(3, nullptr, emb, nullptr, clsb, out);
    k_loss<<<dim3(Lc-1, Bc), 256>>>(out, tmask);
    k_final<<<1, 256>>>(tmask, out);
}

// round 9
// speedup vs baseline: 3.0235x; 1.1806x over previous
#include <cuda_runtime.h>
#include <cstdint>
#include <math.h>
#include <mma.h>
using namespace nvcuda;

#define Bc  32
#define Lc  256
#define Sc  5
#define Nc  1024
#define Dc  256
#define Vc  512
#define Hc  8
#define DHc 32

// ---------------- scratch ----------------
__device__ float g_W3T[2][Sc*Dc*Dc];     // [dir][(s*256+j)*256 + dt]
__device__ float g_M[10*Dc*Dc];          // [dir*5+s][d*256 + j]
__device__ float g_Gp[2][Sc*Vc*Dc];
__device__ float g_dirb[2][Dc];
__device__ float g_Q[2][Bc*Lc*Dc];
__device__ float g_K[Bc*Nc*Dc];
__device__ float g_Vm[Bc*Nc*Dc];
__device__ float g_F[2][Bc*Lc*Dc];
__device__ float g_num;

// ---------------- helpers ----------------
__device__ __forceinline__ float warpSum(float v){
#pragma unroll
    for (int o=16;o>0;o>>=1) v += __shfl_xor_sync(0xffffffffu, v, o);
    return v;
}
__device__ __forceinline__ float warpMax(float v){
#pragma unroll
    for (int o=16;o>0;o>>=1) v = fmaxf(v, __shfl_xor_sync(0xffffffffu, v, o));
    return v;
}
__device__ __forceinline__ float blockSum(float v, float* red){
    v = warpSum(v);
    int w = threadIdx.x >> 5;
    __syncthreads();
    if ((threadIdx.x & 31) == 0) red[w] = v;
    __syncthreads();
    if (w == 0){
        float r = (threadIdx.x < 8) ? red[threadIdx.x] : 0.f;
        r = warpSum(r);
        if (threadIdx.x == 0) red[0] = r;
    }
    __syncthreads();
    return red[0];
}
__device__ __forceinline__ float blockMax(float v, float* red){
    v = warpMax(v);
    int w = threadIdx.x >> 5;
    __syncthreads();
    if ((threadIdx.x & 31) == 0) red[w] = v;
    __syncthreads();
    if (w == 0){
        float r = (threadIdx.x < 8) ? red[threadIdx.x] : -1e30f;
        r = warpMax(r);
        if (threadIdx.x == 0) red[0] = r;
    }
    __syncthreads();
    return red[0];
}
__device__ __forceinline__ float f2tf(float x){
    uint32_t u; asm("cvt.rna.tf32.f32 %0, %1;" : "=r"(u) : "f"(x));
    return __uint_as_float(u);
}
__device__ __forceinline__ uint32_t f2tf_u(float x){
    uint32_t u; asm("cvt.rna.tf32.f32 %0, %1;" : "=r"(u) : "f"(x));
    return u;
}
__device__ __forceinline__ void mma_tf32(float* c, const uint32_t* a, const uint32_t* b){
    asm volatile("mma.sync.aligned.m16n8k8.row.col.f32.tf32.tf32.f32 "
        "{%0,%1,%2,%3}, {%4,%5,%6,%7}, {%8,%9}, {%0,%1,%2,%3};"
        : "+f"(c[0]),"+f"(c[1]),"+f"(c[2]),"+f"(c[3])
        : "r"(a[0]),"r"(a[1]),"r"(a[2]),"r"(a[3]), "r"(b[0]),"r"(b[1]));
}

// ---------------- k1: fold conv + scrambled-mean into W3^T (+ zero g_num) ---
__global__ void k_w3(const float* __restrict__ wl, const float* __restrict__ wr){
    if (blockIdx.x == 0 && blockIdx.y == 0 && threadIdx.x == 0) g_num = 0.f;
    int dir = blockIdx.y;
    const float* w = dir ? wr : wl;
    int idx = blockIdx.x*256 + threadIdx.x;
    int dt = idx & 255;
    int sj = idx >> 8;
    int s = sj / 256, j = sj % 256;
    float v = 0.f;
#pragma unroll
    for (int k=0;k<5;k++){
        int f = dt + 256*k;
        int o = f/5, sk = f%5;
        int tp = s - sk + 1;
        if (tp >= 0 && tp < 3) v += w[(o*Dc + j)*3 + tp];
    }
    g_W3T[dir][(s*Dc + j)*Dc + dt] = 0.2f*v;
}

// ---------------- generic tf32 GEMM, double-buffered smem -------------------
// C = A @ B^T (+bias on mode 3)
// modes: 0 kv (z: 0=K 1=V), 1 M=P@W3T^T (z=dir*5+s), 2 Gp=emb@M^T (z=dir*5+s),
//        3 logits (z=dir)
#define GSM_FLOATS (4*5120)
__global__ void __launch_bounds__(256,2) k_gemm(int mode,
        const float* __restrict__ A, const float* __restrict__ B0,
        const float* __restrict__ B1, const float* __restrict__ bias,
        float* __restrict__ Cext){
    extern __shared__ float smem[];
    // layout: A0[128*40] B0[128*40] A1[128*40] B1[128*40]
    int z = blockIdx.z;
    const float* Ap; const float* Bp; float* Cp;
    int ldb, ldc;
    if (mode==0){
        Ap = A; Bp = z ? B1 : B0; ldb = 256;
        Cp = z ? &g_Vm[0] : &g_K[0]; ldc = 256;
    } else if (mode==1){
        Ap = A;
        Bp = &g_W3T[0][0] + (long)z*65536; ldb = 256;
        Cp = &g_M[0] + (long)z*65536; ldc = 256;
    } else if (mode==2){
        Ap = A;
        Bp = &g_M[0] + (long)z*65536; ldb = 256;
        Cp = &g_Gp[0][0] + (long)(z/5)*655360 + (long)(z%5)*131072; ldc = 256;
    } else {
        Ap = &g_F[0][0] + (long)z*8192*256;
        Bp = B0; ldb = 256;
        Cp = Cext + 1 + (long)z*8192*512; ldc = 512;
    }
    int row0 = blockIdx.x*128, col0 = blockIdx.y*128;
    int t = threadIdx.x, wid = t>>5, lane = t&31;
    int wm = wid>>2, wn = wid&3;

    wmma::fragment<wmma::accumulator,16,16,8,float> acc[4][2];
#pragma unroll
    for (int mi=0;mi<4;mi++)
#pragma unroll
        for (int ni=0;ni<2;ni++) wmma::fill_fragment(acc[mi][ni], 0.f);

    int r8 = t>>3, c8 = (t&7)*4;
    const float* Ag = &Ap[(long)(row0+r8)*256 + c8];
    const float* Bg = &Bp[(long)(col0+r8)*ldb + c8];

    float4 pa[4], pb[4];
#pragma unroll
    for (int u=0;u<4;u++){
        pa[u] = *(const float4*)(Ag + (long)(u*32)*256);
        pb[u] = *(const float4*)(Bg + (long)(u*32)*ldb);
    }
    // store tile 0 into buffer 0
    {
        float* Ad = smem + r8*40 + c8;
        float* Bd = smem + 5120 + r8*40 + c8;
#pragma unroll
        for (int u=0;u<4;u++){
            Ad[u*32*40+0]=f2tf(pa[u].x); Ad[u*32*40+1]=f2tf(pa[u].y);
            Ad[u*32*40+2]=f2tf(pa[u].z); Ad[u*32*40+3]=f2tf(pa[u].w);
            Bd[u*32*40+0]=f2tf(pb[u].x); Bd[u*32*40+1]=f2tf(pb[u].y);
            Bd[u*32*40+2]=f2tf(pb[u].z); Bd[u*32*40+3]=f2tf(pb[u].w);
        }
    }

    for (int kb8=0; kb8<8; kb8++){
        __syncthreads();                     // buffer kb8&1 fully stored
        if (kb8 < 7){
            int off = (kb8+1)*32;
#pragma unroll
            for (int u=0;u<4;u++){
                pa[u] = *(const float4*)(Ag + (long)(u*32)*256 + off);
                pb[u] = *(const float4*)(Bg + (long)(u*32)*ldb + off);
            }
        }
        const float* Asb = smem + (kb8&1)*10240;
        const float* Bsb = smem + 5120 + (kb8&1)*10240;
#pragma unroll
        for (int k8=0;k8<4;k8++){
            wmma::fragment<wmma::matrix_a,16,16,8,wmma::precision::tf32,wmma::row_major> af[4];
            wmma::fragment<wmma::matrix_b,16,16,8,wmma::precision::tf32,wmma::col_major> bf[2];
#pragma unroll
            for (int mi=0;mi<4;mi++)
                wmma::load_matrix_sync(af[mi], Asb + (wm*64 + mi*16)*40 + k8*8, 40);
#pragma unroll
            for (int ni=0;ni<2;ni++)
                wmma::load_matrix_sync(bf[ni], Bsb + (wn*32 + ni*16)*40 + k8*8, 40);
#pragma unroll
            for (int mi=0;mi<4;mi++)
#pragma unroll
                for (int ni=0;ni<2;ni++)
                    wmma::mma_sync(acc[mi][ni], af[mi], bf[ni], acc[mi][ni]);
        }
        if (kb8 < 7){
            float* Ad = smem + ((kb8+1)&1)*10240 + r8*40 + c8;
            float* Bd = smem + 5120 + ((kb8+1)&1)*10240 + r8*40 + c8;
#pragma unroll
            for (int u=0;u<4;u++){
                Ad[u*32*40+0]=f2tf(pa[u].x); Ad[u*32*40+1]=f2tf(pa[u].y);
                Ad[u*32*40+2]=f2tf(pa[u].z); Ad[u*32*40+3]=f2tf(pa[u].w);
                Bd[u*32*40+0]=f2tf(pb[u].x); Bd[u*32*40+1]=f2tf(pb[u].y);
                Bd[u*32*40+2]=f2tf(pb[u].z); Bd[u*32*40+3]=f2tf(pb[u].w);
            }
        }
    }
    if (mode != 3){
#pragma unroll
        for (int mi=0;mi<4;mi++)
#pragma unroll
            for (int ni=0;ni<2;ni++)
                wmma::store_matrix_sync(&Cp[(long)(row0+wm*64+mi*16)*ldc + col0 + wn*32 + ni*16],
                                        acc[mi][ni], ldc, wmma::mem_row_major);
    } else {
        __syncthreads();
        float* stage = smem + wid*(16*18);
#pragma unroll
        for (int mi=0;mi<4;mi++)
#pragma unroll
            for (int ni=0;ni<2;ni++){
                wmma::store_matrix_sync(stage, acc[mi][ni], 18, wmma::mem_row_major);
                __syncwarp();
                for (int e=lane; e<256; e+=32){
                    int r = e>>4, c = e&15;
                    int col = col0 + wn*32 + ni*16 + c;
                    Cp[(long)(row0+wm*64+mi*16+r)*ldc + col] = stage[r*18+c] + bias[col];
                }
                __syncwarp();
            }
    }
}

// ---------------- LN (+bias) in place on g_K / g_Vm -------------------------
__global__ void k_ln(const float* __restrict__ kb, const float* __restrict__ vb,
                     const float* __restrict__ gamma, const float* __restrict__ beta){
    int z = blockIdx.y;
    float* X = z ? &g_Vm[0] : &g_K[0];
    const float* bias = z ? vb : kb;
    int wid = threadIdx.x>>5, lane = threadIdx.x&31;
    long row = (long)blockIdx.x*8 + wid;
    float4* R = (float4*)(X + row*256);
    const float4* B4 = (const float4*)bias;
    const float4* G4 = (const float4*)gamma;
    const float4* T4 = (const float4*)beta;
    float4 x0 = R[lane], x1 = R[lane+32];
    float4 b0 = B4[lane], b1 = B4[lane+32];
    x0.x+=b0.x; x0.y+=b0.y; x0.z+=b0.z; x0.w+=b0.w;
    x1.x+=b1.x; x1.y+=b1.y; x1.z+=b1.z; x1.w+=b1.w;
    float s  = x0.x+x0.y+x0.z+x0.w + x1.x+x1.y+x1.z+x1.w;
    float s2 = x0.x*x0.x+x0.y*x0.y+x0.z*x0.z+x0.w*x0.w
             + x1.x*x1.x+x1.y*x1.y+x1.z*x1.z+x1.w*x1.w;
    s = warpSum(s); s2 = warpSum(s2);
    float m = s*(1.f/256.f);
    float r = rsqrtf(s2*(1.f/256.f) - m*m + 1e-5f);
    float4 g0 = G4[lane], g1 = G4[lane+32];
    float4 t0 = T4[lane], t1 = T4[lane+32];
    float4 o0, o1;
    o0.x=(x0.x-m)*r*g0.x+t0.x; o0.y=(x0.y-m)*r*g0.y+t0.y;
    o0.z=(x0.z-m)*r*g0.z+t0.z; o0.w=(x0.w-m)*r*g0.w+t0.w;
    o1.x=(x1.x-m)*r*g1.x+t1.x; o1.y=(x1.y-m)*r*g1.y+t1.y;
    o1.z=(x1.z-m)*r*g1.z+t1.z; o1.w=(x1.w-m)*r*g1.w+t1.w;
    R[lane] = o0; R[lane+32] = o1;
}

// ---------------- dir' = dir_tok @ P^T + bias ----------------
__global__ void k_dirb(const float* __restrict__ dl, const float* __restrict__ dr,
                       const float* __restrict__ P, const float* __restrict__ pb){
    int dir = blockIdx.x;
    const float* dv = dir ? dr : dl;
    int d = threadIdx.x;
    float s = pb[d];
    for (int i=0;i<256;i++) s += dv[i]*P[d*Dc + i];
    g_dirb[dir][d] = s;
}

// ---------------- Q = LN(sum_s Gp[s,id_s] + dir') ----------------
__global__ void k_q(const int* __restrict__ idl, const int* __restrict__ idr,
                    const float* __restrict__ gamma, const float* __restrict__ beta){
    int dir = blockIdx.y;
    int bl  = blockIdx.x;
    const int* ids = (dir ? idr : idl) + bl*Sc;
    __shared__ int sid[8];
    __shared__ float red[32];
    int d = threadIdx.x;
    if (d < Sc) sid[d] = ids[d];
    __syncthreads();
    float v = g_dirb[dir][d];
#pragma unroll
    for (int s=0;s<Sc;s++) v += g_Gp[dir][(s*Vc + sid[s])*Dc + d];
    float m   = blockSum(v, red) * (1.f/256.f);
    float dv  = v - m;
    float var = blockSum(dv*dv, red) * (1.f/256.f);
    float o   = dv * rsqrtf(var + 1e-5f) * gamma[d] + beta[d];
    g_Q[dir][bl*Dc + d] = o;
}

// ---------------- flash attention, tf32 mma, no-max softmax ------------------
// K pre-scaled by scale*log2e; p = exp2f(sc*mask); V natural [n][dh].
// Next chunk's K/V/M prefetched into registers during compute phase.
#define LDA 40
__global__ void __launch_bounds__(256,2) k_attn(const float* __restrict__ mask,
                                                const float* __restrict__ tau_p){
    extern __shared__ float sm[];
    float* Ksm  = sm;                    // [2][32][40]
    float* Vsm  = Ksm + 2*32*LDA;        // [2][32][40]
    float* Msm  = Vsm + 2*32*LDA;        // [128][40]
    float* Psm  = Msm + 128*LDA;         // [2][128][40]
    int lt = blockIdx.x >> 2, hp = blockIdx.x & 3;
    int b = blockIdx.y, dir = blockIdx.z;
    int l0 = lt*128;
    int t = threadIdx.x, wid = t>>5, lane = t&31;
    int wg = wid>>2, wr = wid&3;
    int lq = lane>>2, lr = lane&3;
    float tau = fminf(fmaxf(tau_p[0],0.25f),4.f);
    float kscale = 1.44269504f/(5.656854249f*tau);

    const float* Qbase = (dir ? g_Q[1] : g_Q[0]) + (long)(b*Lc + l0)*Dc + hp*64;
    for (int i=t; i<2048; i+=256){
        int hh = i>>10, rem = i&1023, row = rem>>3, c4 = rem&7;
        *(float4*)&Psm[(hh*128+row)*LDA + c4*4] =
            *(const float4*)&Qbase[(long)row*Dc + hh*32 + c4*4];
    }
    __syncthreads();
    uint32_t qa[2][4][4];
    {
        const float* Qh = Psm + wg*128*LDA;
#pragma unroll
        for (int mi=0;mi<2;mi++)
#pragma unroll
        for (int k8=0;k8<4;k8++){
            int r = wr*32 + mi*16 + lq, c = k8*8 + lr;
            qa[mi][k8][0] = f2tf_u(Qh[r*LDA + c]);
            qa[mi][k8][1] = f2tf_u(Qh[(r+8)*LDA + c]);
            qa[mi][k8][2] = f2tf_u(Qh[r*LDA + c+4]);
            qa[mi][k8][3] = f2tf_u(Qh[(r+8)*LDA + c+4]);
        }
    }
    float o[2][4][4];
#pragma unroll
    for (int mi=0;mi<2;mi++)
#pragma unroll
        for (int ni=0;ni<4;ni++)
#pragma unroll
            for (int e=0;e<4;e++) o[mi][ni][e]=0.f;
    float lsum[4] = {0.f,0.f,0.f,0.f};

    const float* Kg = g_K  + (long)(b*Nc)*Dc + hp*64;
    const float* Vg = g_Vm + (long)(b*Nc)*Dc + hp*64;
    const float* Mg = mask + (long)(b*Lc + l0)*Nc;
    float* Ph = Psm + wg*128*LDA;

    // staging index decomposition (per thread, 2 K/V items + 1 M item)
    int s_hh[2], s_n[2], s_c4[2];
#pragma unroll
    for (int u=0;u<2;u++){
        int i = t + u*256;
        s_hh[u] = i>>8; int rem = i&255;
        s_n[u] = rem>>3; s_c4[u] = rem&7;
    }
    int m_row = t>>1, m_c4 = (t&1)*4;    // 256 threads: rows 0..127, two float4 each? (128*8=1024 items /256 = 4)
    // M: 1024 float4-items? Msm rows 128 × 8 c4 = 1024 items over 256 thr = 4 each
    float4 pk[2], pv[2], pm[4];
#pragma unroll
    for (int u=0;u<2;u++){
        pk[u] = *(const float4*)&Kg[(long)(s_n[u])*Dc + s_hh[u]*32 + s_c4[u]*4];
        pv[u] = *(const float4*)&Vg[(long)(s_n[u])*Dc + s_hh[u]*32 + s_c4[u]*4];
    }
#pragma unroll
    for (int u=0;u<4;u++){
        int i = t + u*256, row = i>>3, c4 = i&7;
        pm[u] = *(const float4*)&Mg[(long)row*Nc + c4*4];
    }

    for (int n0=0; n0<Nc; n0+=32){
        __syncthreads();
        // store staged regs
#pragma unroll
        for (int u=0;u<2;u++){
            float* d = &Ksm[(s_hh[u]*32+s_n[u])*LDA + s_c4[u]*4];
            d[0]=f2tf(pk[u].x*kscale); d[1]=f2tf(pk[u].y*kscale);
            d[2]=f2tf(pk[u].z*kscale); d[3]=f2tf(pk[u].w*kscale);
            float* dv = &Vsm[(s_hh[u]*32+s_n[u])*LDA + s_c4[u]*4];
            dv[0]=f2tf(pv[u].x); dv[1]=f2tf(pv[u].y);
            dv[2]=f2tf(pv[u].z); dv[3]=f2tf(pv[u].w);
        }
#pragma unroll
        for (int u=0;u<4;u++){
            int i = t + u*256, row = i>>3, c4 = i&7;
            *(float4*)&Msm[row*LDA + c4*4] = pm[u];
        }
        // prefetch next chunk
        if (n0 + 32 < Nc){
#pragma unroll
            for (int u=0;u<2;u++){
                pk[u] = *(const float4*)&Kg[(long)(n0+32+s_n[u])*Dc + s_hh[u]*32 + s_c4[u]*4];
                pv[u] = *(const float4*)&Vg[(long)(n0+32+s_n[u])*Dc + s_hh[u]*32 + s_c4[u]*4];
            }
#pragma unroll
            for (int u=0;u<4;u++){
                int i = t + u*256, row = i>>3, c4 = i&7;
                pm[u] = *(const float4*)&Mg[(long)row*Nc + n0+32 + c4*4];
            }
        }
        __syncthreads();

        float sc[2][4][4];
#pragma unroll
        for (int mi=0;mi<2;mi++)
#pragma unroll
            for (int ni=0;ni<4;ni++)
#pragma unroll
                for (int e=0;e<4;e++) sc[mi][ni][e]=0.f;
        const float* Kh = Ksm + wg*32*LDA;
#pragma unroll
        for (int k8=0;k8<4;k8++){
            uint32_t bf[4][2];
#pragma unroll
            for (int ni=0;ni<4;ni++){
                bf[ni][0] = __float_as_uint(Kh[(ni*8+lq)*LDA + k8*8 + lr]);
                bf[ni][1] = __float_as_uint(Kh[(ni*8+lq)*LDA + k8*8 + lr + 4]);
            }
#pragma unroll
            for (int mi=0;mi<2;mi++)
#pragma unroll
                for (int ni=0;ni<4;ni++)
                    mma_tf32(sc[mi][ni], qa[mi][k8], bf[ni]);
        }
#pragma unroll
        for (int mi=0;mi<2;mi++)
#pragma unroll
        for (int half=0;half<2;half++){
            int q = mi*2+half;
            int row = wr*32 + mi*16 + half*8 + lq;
            float ls = 0.f;
#pragma unroll
            for (int ni=0;ni<4;ni++){
                float m0 = Msm[row*LDA + ni*8 + 2*lr];
                float m1 = Msm[row*LDA + ni*8 + 2*lr + 1];
                float p0 = exp2f(sc[mi][ni][half*2]   * m0);
                float p1 = exp2f(sc[mi][ni][half*2+1] * m1);
                ls += p0 + p1;
                float2 pp; pp.x = p0; pp.y = p1;   // raw fp32; mma truncates to tf32
                *(float2*)&Ph[row*LDA + ni*8 + 2*lr] = pp;
            }
            ls += __shfl_xor_sync(0xffffffffu, ls, 1);
            ls += __shfl_xor_sync(0xffffffffu, ls, 2);
            lsum[q] += ls;
        }
        __syncwarp();
        const float* Vh = Vsm + wg*32*LDA;
#pragma unroll
        for (int k8=0;k8<4;k8++){
            uint32_t pafr[2][4];
#pragma unroll
            for (int mi=0;mi<2;mi++){
                int r = wr*32 + mi*16 + lq, c = k8*8+lr;
                pafr[mi][0] = __float_as_uint(Ph[r*LDA + c]);
                pafr[mi][1] = __float_as_uint(Ph[(r+8)*LDA + c]);
                pafr[mi][2] = __float_as_uint(Ph[r*LDA + c+4]);
                pafr[mi][3] = __float_as_uint(Ph[(r+8)*LDA + c+4]);
            }
            uint32_t vbf[4][2];
#pragma unroll
            for (int ni=0;ni<4;ni++){
                vbf[ni][0] = __float_as_uint(Vh[(k8*8+lr)*LDA + ni*8 + lq]);
                vbf[ni][1] = __float_as_uint(Vh[(k8*8+lr+4)*LDA + ni*8 + lq]);
            }
#pragma unroll
            for (int mi=0;mi<2;mi++)
#pragma unroll
                for (int ni=0;ni<4;ni++)
                    mma_tf32(o[mi][ni], pafr[mi], vbf[ni]);
        }
    }
    float* Fg = (dir ? g_F[1] : g_F[0]) + (long)(b*Lc + l0)*Dc + (hp*2+wg)*32;
#pragma unroll
    for (int mi=0;mi<2;mi++)
#pragma unroll
    for (int half=0;half<2;half++){
        int q = mi*2+half;
        int row = wr*32 + mi*16 + half*8 + lq;
        float inv = 1.f/lsum[q];
#pragma unroll
        for (int ni=0;ni<4;ni++){
            float2 oo;
            oo.x = o[mi][ni][half*2]*inv;
            oo.y = o[mi][ni][half*2+1]*inv;
            *(float2*)&Fg[(long)row*Dc + ni*8 + 2*lr] = oo;
        }
    }
}

// ---------------- agreement loss ----------------
__global__ void k_loss(const float* __restrict__ out, const float* __restrict__ tmask){
    int l = blockIdx.x;
    int b = blockIdx.y;
    const float* rl = out + 1 + (long)(b*Lc + l)*Vc;
    const float* rr = out + 1 + (long)Bc*Lc*Vc + (long)(b*Lc + l + 1)*Vc;
    __shared__ float red[32];
    int t = threadIdx.x;
    float xl0 = rl[t]*0.5f,     xl1 = rl[t+256]*0.5f;
    float xr0 = rr[t]*0.5f,     xr1 = rr[t+256]*0.5f;
    float ml = blockMax(fmaxf(xl0,xl1), red);
    float el0 = __expf(xl0-ml), el1 = __expf(xl1-ml);
    float sl = blockSum(el0+el1, red);
    float mr = blockMax(fmaxf(xr0,xr1), red);
    float er0 = __expf(xr0-mr), er1 = __expf(xr1-mr);
    float sr = blockSum(er0+er1, red);
    float pl0 = el0/sl, pl1 = el1/sl;
    float pr0 = er0/sr, pr1 = er1/sr;
    float d0 = pl0-pr0, d1 = pl1-pr1;
    float agree = blockSum(d0*d0 + d1*d1, red);
    if (t == 0) atomicAdd(&g_num, agree * tmask[b*Lc + l]);
}

__global__ void k_final(const float* __restrict__ tmask, float* __restrict__ out){
    __shared__ float red[32];
    float s = 0.f;
    for (int e=threadIdx.x; e<Bc*Lc; e+=256){
        int l = e % Lc;
        if (l < Lc-1) s += tmask[e];
    }
    s = blockSum(s, red);
    if (threadIdx.x == 0){
        float den = fmaxf(s, 1.0f);
        out[0] = 0.1f * g_num / den;
    }
}

// ---------------- launch ----------------------------------------------------
extern "C" void kernel_launch(void* const* d_in, const int* in_sizes, int n_in,
                              void* d_out, int out_size){
    const float* vis   = (const float*)d_in[0];
    const int*   idl   = (const int*)  d_in[1];
    const int*   idr   = (const int*)  d_in[2];
    const float* tmask = (const float*)d_in[4];
    const float* vmask = (const float*)d_in[5];
    const float* emb   = (const float*)d_in[6];
    const float* dl    = (const float*)d_in[7];
    const float* dr    = (const float*)d_in[8];
    const float* pw    = (const float*)d_in[9];
    const float* pb    = (const float*)d_in[10];
    const float* qg    = (const float*)d_in[11];
    const float* qb    = (const float*)d_in[12];
    const float* kw    = (const float*)d_in[13];
    const float* kb    = (const float*)d_in[14];
    const float* vw    = (const float*)d_in[15];
    const float* vb    = (const float*)d_in[16];
    const float* kvg   = (const float*)d_in[17];
    const float* kvb   = (const float*)d_in[18];
    const float* tau   = (const float*)d_in[19];
    const float* clsb  = (const float*)d_in[20];
    const float* cwl   = (const float*)d_in[21];
    const float* cwr   = (const float*)d_in[22];
    float* out = (float*)d_out;

    const int SM_GEMM = GSM_FLOATS*4;                                 // 81920
    const int SM_ATTN = (2*32*LDA + 2*32*LDA + 128*LDA + 2*128*LDA)*4; // 81920
    cudaFuncSetAttribute(k_gemm, cudaFuncAttributeMaxDynamicSharedMemorySize, SM_GEMM);
    cudaFuncSetAttribute(k_attn, cudaFuncAttributeMaxDynamicSharedMemorySize, SM_ATTN);

    k_w3<<<dim3(1280,2), 256>>>(cwl, cwr);
    k_gemm<<<dim3(2,2,10), 256, SM_GEMM>>>(1, pw, nullptr, nullptr, nullptr, nullptr);
    k_gemm<<<dim3(4,2,10), 256, SM_GEMM>>>(2, emb, nullptr, nullptr, nullptr, nullptr);
    k_dirb<<<2, 256>>>(dl, dr, pw, pb);
    k_q<<<dim3(Bc*Lc,2), 256>>>(idl, idr, qg, qb);
    k_gemm<<<dim3(256,2,2), 256, SM_GEMM>>>(0, vis, kw, vw, nullptr, nullptr);
    k_ln<<<dim3(4096,2), 256>>>(kb, vb, kvg, kvb);
    k_attn<<<dim3(8,32,2), 256, SM_ATTN>>>(vmask, tau);
    k_gemm<<<dim3(64,4,2), 256, SM_GEMM>>>(3, nullptr, emb, nullptr, clsb, out);
    k_loss<<<dim3(Lc-1, Bc), 256>>>(out, tmask);
    k_final<<<1, 256>>>(tmask, out);
}

// round 10
// speedup vs baseline: 3.1263x; 1.0340x over previous
#include <cuda_runtime.h>
#include <cstdint>
#include <math.h>
#include <mma.h>
using namespace nvcuda;

#define Bc  32
#define Lc  256
#define Sc  5
#define Nc  1024
#define Dc  256
#define Vc  512
#define Hc  8
#define DHc 32

// ---------------- scratch ----------------
__device__ float g_W3T[2][Sc*Dc*Dc];     // [dir][(s*256+j)*256 + dt]
__device__ float g_M[10*Dc*Dc];          // [dir*5+s][d*256 + j]
__device__ float g_Gp[2][Sc*Vc*Dc];
__device__ float g_dirb[2][Dc];
__device__ float g_Q[2][Bc*Lc*Dc];
__device__ float g_K[Bc*Nc*Dc];
__device__ float g_Vm[Bc*Nc*Dc];
__device__ float g_F[2][Bc*Lc*Dc];
__device__ float g_num;

// ---------------- helpers ----------------
__device__ __forceinline__ float warpSum(float v){
#pragma unroll
    for (int o=16;o>0;o>>=1) v += __shfl_xor_sync(0xffffffffu, v, o);
    return v;
}
__device__ __forceinline__ float warpMax(float v){
#pragma unroll
    for (int o=16;o>0;o>>=1) v = fmaxf(v, __shfl_xor_sync(0xffffffffu, v, o));
    return v;
}
__device__ __forceinline__ float blockSum(float v, float* red){
    v = warpSum(v);
    int w = threadIdx.x >> 5;
    __syncthreads();
    if ((threadIdx.x & 31) == 0) red[w] = v;
    __syncthreads();
    if (w == 0){
        float r = (threadIdx.x < 8) ? red[threadIdx.x] : 0.f;
        r = warpSum(r);
        if (threadIdx.x == 0) red[0] = r;
    }
    __syncthreads();
    return red[0];
}
__device__ __forceinline__ float f2tf(float x){
    uint32_t u; asm("cvt.rna.tf32.f32 %0, %1;" : "=r"(u) : "f"(x));
    return __uint_as_float(u);
}
__device__ __forceinline__ uint32_t f2tf_u(float x){
    uint32_t u; asm("cvt.rna.tf32.f32 %0, %1;" : "=r"(u) : "f"(x));
    return u;
}
__device__ __forceinline__ void mma_tf32(float* c, const uint32_t* a, const uint32_t* b){
    asm volatile("mma.sync.aligned.m16n8k8.row.col.f32.tf32.tf32.f32 "
        "{%0,%1,%2,%3}, {%4,%5,%6,%7}, {%8,%9}, {%0,%1,%2,%3};"
        : "+f"(c[0]),"+f"(c[1]),"+f"(c[2]),"+f"(c[3])
        : "r"(a[0]),"r"(a[1]),"r"(a[2]),"r"(a[3]), "r"(b[0]),"r"(b[1]));
}

// ---------------- k1: fold conv + scrambled-mean into W3^T (+ zero g_num) ---
__global__ void k_w3(const float* __restrict__ wl, const float* __restrict__ wr){
    if (blockIdx.x == 0 && blockIdx.y == 0 && threadIdx.x == 0) g_num = 0.f;
    int dir = blockIdx.y;
    const float* w = dir ? wr : wl;
    int idx = blockIdx.x*256 + threadIdx.x;
    int dt = idx & 255;
    int sj = idx >> 8;
    int s = sj / 256, j = sj % 256;
    float v = 0.f;
#pragma unroll
    for (int k=0;k<5;k++){
        int f = dt + 256*k;
        int o = f/5, sk = f%5;
        int tp = s - sk + 1;
        if (tp >= 0 && tp < 3) v += w[(o*Dc + j)*3 + tp];
    }
    g_W3T[dir][(s*Dc + j)*Dc + dt] = 0.2f*v;
}

// ---------------- generic tf32 GEMM, double-buffered smem -------------------
#define GSM_FLOATS (4*5120)
__global__ void __launch_bounds__(256,2) k_gemm(int mode,
        const float* __restrict__ A, const float* __restrict__ B0,
        const float* __restrict__ B1, const float* __restrict__ bias,
        float* __restrict__ Cext){
    extern __shared__ float smem[];
    int z = blockIdx.z;
    const float* Ap; const float* Bp; float* Cp;
    int ldb, ldc;
    if (mode==0){
        Ap = A; Bp = z ? B1 : B0; ldb = 256;
        Cp = z ? &g_Vm[0] : &g_K[0]; ldc = 256;
    } else if (mode==1){
        Ap = A;
        Bp = &g_W3T[0][0] + (long)z*65536; ldb = 256;
        Cp = &g_M[0] + (long)z*65536; ldc = 256;
    } else if (mode==2){
        Ap = A;
        Bp = &g_M[0] + (long)z*65536; ldb = 256;
        Cp = &g_Gp[0][0] + (long)(z/5)*655360 + (long)(z%5)*131072; ldc = 256;
    } else {
        Ap = &g_F[0][0] + (long)z*8192*256;
        Bp = B0; ldb = 256;
        Cp = Cext + 1 + (long)z*8192*512; ldc = 512;
    }
    int row0 = blockIdx.x*128, col0 = blockIdx.y*128;
    int t = threadIdx.x, wid = t>>5, lane = t&31;
    int wm = wid>>2, wn = wid&3;

    wmma::fragment<wmma::accumulator,16,16,8,float> acc[4][2];
#pragma unroll
    for (int mi=0;mi<4;mi++)
#pragma unroll
        for (int ni=0;ni<2;ni++) wmma::fill_fragment(acc[mi][ni], 0.f);

    int r8 = t>>3, c8 = (t&7)*4;
    const float* Ag = &Ap[(long)(row0+r8)*256 + c8];
    const float* Bg = &Bp[(long)(col0+r8)*ldb + c8];

    float4 pa[4], pb[4];
#pragma unroll
    for (int u=0;u<4;u++){
        pa[u] = *(const float4*)(Ag + (long)(u*32)*256);
        pb[u] = *(const float4*)(Bg + (long)(u*32)*ldb);
    }
    {
        float* Ad = smem + r8*40 + c8;
        float* Bd = smem + 5120 + r8*40 + c8;
#pragma unroll
        for (int u=0;u<4;u++){
            Ad[u*32*40+0]=f2tf(pa[u].x); Ad[u*32*40+1]=f2tf(pa[u].y);
            Ad[u*32*40+2]=f2tf(pa[u].z); Ad[u*32*40+3]=f2tf(pa[u].w);
            Bd[u*32*40+0]=f2tf(pb[u].x); Bd[u*32*40+1]=f2tf(pb[u].y);
            Bd[u*32*40+2]=f2tf(pb[u].z); Bd[u*32*40+3]=f2tf(pb[u].w);
        }
    }

    for (int kb8=0; kb8<8; kb8++){
        __syncthreads();
        if (kb8 < 7){
            int off = (kb8+1)*32;
#pragma unroll
            for (int u=0;u<4;u++){
                pa[u] = *(const float4*)(Ag + (long)(u*32)*256 + off);
                pb[u] = *(const float4*)(Bg + (long)(u*32)*ldb + off);
            }
        }
        const float* Asb = smem + (kb8&1)*10240;
        const float* Bsb = smem + 5120 + (kb8&1)*10240;
#pragma unroll
        for (int k8=0;k8<4;k8++){
            wmma::fragment<wmma::matrix_a,16,16,8,wmma::precision::tf32,wmma::row_major> af[4];
            wmma::fragment<wmma::matrix_b,16,16,8,wmma::precision::tf32,wmma::col_major> bf[2];
#pragma unroll
            for (int mi=0;mi<4;mi++)
                wmma::load_matrix_sync(af[mi], Asb + (wm*64 + mi*16)*40 + k8*8, 40);
#pragma unroll
            for (int ni=0;ni<2;ni++)
                wmma::load_matrix_sync(bf[ni], Bsb + (wn*32 + ni*16)*40 + k8*8, 40);
#pragma unroll
            for (int mi=0;mi<4;mi++)
#pragma unroll
                for (int ni=0;ni<2;ni++)
                    wmma::mma_sync(acc[mi][ni], af[mi], bf[ni], acc[mi][ni]);
        }
        if (kb8 < 7){
            float* Ad = smem + ((kb8+1)&1)*10240 + r8*40 + c8;
            float* Bd = smem + 5120 + ((kb8+1)&1)*10240 + r8*40 + c8;
#pragma unroll
            for (int u=0;u<4;u++){
                Ad[u*32*40+0]=f2tf(pa[u].x); Ad[u*32*40+1]=f2tf(pa[u].y);
                Ad[u*32*40+2]=f2tf(pa[u].z); Ad[u*32*40+3]=f2tf(pa[u].w);
                Bd[u*32*40+0]=f2tf(pb[u].x); Bd[u*32*40+1]=f2tf(pb[u].y);
                Bd[u*32*40+2]=f2tf(pb[u].z); Bd[u*32*40+3]=f2tf(pb[u].w);
            }
        }
    }
    if (mode != 3){
#pragma unroll
        for (int mi=0;mi<4;mi++)
#pragma unroll
            for (int ni=0;ni<2;ni++)
                wmma::store_matrix_sync(&Cp[(long)(row0+wm*64+mi*16)*ldc + col0 + wn*32 + ni*16],
                                        acc[mi][ni], ldc, wmma::mem_row_major);
    } else {
        __syncthreads();
        float* stage = smem + wid*(16*18);
#pragma unroll
        for (int mi=0;mi<4;mi++)
#pragma unroll
            for (int ni=0;ni<2;ni++){
                wmma::store_matrix_sync(stage, acc[mi][ni], 18, wmma::mem_row_major);
                __syncwarp();
                for (int e=lane; e<256; e+=32){
                    int r = e>>4, c = e&15;
                    int col = col0 + wn*32 + ni*16 + c;
                    Cp[(long)(row0+wm*64+mi*16+r)*ldc + col] = stage[r*18+c] + bias[col];
                }
                __syncwarp();
            }
    }
}

// ---------------- LN (+bias) in place on g_K / g_Vm -------------------------
__global__ void k_ln(const float* __restrict__ kb, const float* __restrict__ vb,
                     const float* __restrict__ gamma, const float* __restrict__ beta){
    int z = blockIdx.y;
    float* X = z ? &g_Vm[0] : &g_K[0];
    const float* bias = z ? vb : kb;
    int wid = threadIdx.x>>5, lane = threadIdx.x&31;
    long row = (long)blockIdx.x*8 + wid;
    float4* R = (float4*)(X + row*256);
    const float4* B4 = (const float4*)bias;
    const float4* G4 = (const float4*)gamma;
    const float4* T4 = (const float4*)beta;
    float4 x0 = R[lane], x1 = R[lane+32];
    float4 b0 = B4[lane], b1 = B4[lane+32];
    x0.x+=b0.x; x0.y+=b0.y; x0.z+=b0.z; x0.w+=b0.w;
    x1.x+=b1.x; x1.y+=b1.y; x1.z+=b1.z; x1.w+=b1.w;
    float s  = x0.x+x0.y+x0.z+x0.w + x1.x+x1.y+x1.z+x1.w;
    float s2 = x0.x*x0.x+x0.y*x0.y+x0.z*x0.z+x0.w*x0.w
             + x1.x*x1.x+x1.y*x1.y+x1.z*x1.z+x1.w*x1.w;
    s = warpSum(s); s2 = warpSum(s2);
    float m = s*(1.f/256.f);
    float r = rsqrtf(s2*(1.f/256.f) - m*m + 1e-5f);
    float4 g0 = G4[lane], g1 = G4[lane+32];
    float4 t0 = T4[lane], t1 = T4[lane+32];
    float4 o0, o1;
    o0.x=(x0.x-m)*r*g0.x+t0.x; o0.y=(x0.y-m)*r*g0.y+t0.y;
    o0.z=(x0.z-m)*r*g0.z+t0.z; o0.w=(x0.w-m)*r*g0.w+t0.w;
    o1.x=(x1.x-m)*r*g1.x+t1.x; o1.y=(x1.y-m)*r*g1.y+t1.y;
    o1.z=(x1.z-m)*r*g1.z+t1.z; o1.w=(x1.w-m)*r*g1.w+t1.w;
    R[lane] = o0; R[lane+32] = o1;
}

// ---------------- dir' = dir_tok @ P^T + bias (warp-per-output) -------------
__global__ void k_dirb(const float* __restrict__ dl, const float* __restrict__ dr,
                       const float* __restrict__ P, const float* __restrict__ pb){
    int gw = blockIdx.x*8 + (threadIdx.x>>5);   // 0..511
    int dir = gw >> 8, d = gw & 255;
    int lane = threadIdx.x & 31;
    const float* dv = dir ? dr : dl;
    const float4* P4 = (const float4*)(P + d*Dc);
    const float4* D4 = (const float4*)dv;
    float4 p0 = P4[lane], q0 = D4[lane];
    float4 p1 = P4[lane+32], q1 = D4[lane+32];
    float s = p0.x*q0.x + p0.y*q0.y + p0.z*q0.z + p0.w*q0.w
            + p1.x*q1.x + p1.y*q1.y + p1.z*q1.z + p1.w*q1.w;
    s = warpSum(s);
    if (lane == 0) g_dirb[dir][d] = s + pb[d];
}

// ---------------- Q = LN(sum_s Gp[s,id_s] + dir') ----------------
__global__ void k_q(const int* __restrict__ idl, const int* __restrict__ idr,
                    const float* __restrict__ gamma, const float* __restrict__ beta){
    int dir = blockIdx.y;
    int bl  = blockIdx.x;
    const int* ids = (dir ? idr : idl) + bl*Sc;
    __shared__ int sid[8];
    __shared__ float red[32];
    int d = threadIdx.x;
    if (d < Sc) sid[d] = ids[d];
    __syncthreads();
    float v = g_dirb[dir][d];
#pragma unroll
    for (int s=0;s<Sc;s++) v += g_Gp[dir][(s*Vc + sid[s])*Dc + d];
    float m   = blockSum(v, red) * (1.f/256.f);
    float dv  = v - m;
    float var = blockSum(dv*dv, red) * (1.f/256.f);
    float o   = dv * rsqrtf(var + 1e-5f) * gamma[d] + beta[d];
    g_Q[dir][bl*Dc + d] = o;
}

// ---------------- flash attention, tf32 mma, no-max softmax ------------------
#define LDA 40
__global__ void __launch_bounds__(256,2) k_attn(const float* __restrict__ mask,
                                                const float* __restrict__ tau_p){
    extern __shared__ float sm[];
    float* Ksm  = sm;                    // [2][32][40]
    float* Vsm  = Ksm + 2*32*LDA;        // [2][32][40]
    float* Msm  = Vsm + 2*32*LDA;        // [128][40]
    float* Psm  = Msm + 128*LDA;         // [2][128][40]
    int lt = blockIdx.x >> 2, hp = blockIdx.x & 3;
    int b = blockIdx.y, dir = blockIdx.z;
    int l0 = lt*128;
    int t = threadIdx.x, wid = t>>5, lane = t&31;
    int wg = wid>>2, wr = wid&3;
    int lq = lane>>2, lr = lane&3;
    float tau = fminf(fmaxf(tau_p[0],0.25f),4.f);
    float kscale = 1.44269504f/(5.656854249f*tau);

    const float* Qbase = (dir ? g_Q[1] : g_Q[0]) + (long)(b*Lc + l0)*Dc + hp*64;
    for (int i=t; i<2048; i+=256){
        int hh = i>>10, rem = i&1023, row = rem>>3, c4 = rem&7;
        *(float4*)&Psm[(hh*128+row)*LDA + c4*4] =
            *(const float4*)&Qbase[(long)row*Dc + hh*32 + c4*4];
    }
    __syncthreads();
    uint32_t qa[2][4][4];
    {
        const float* Qh = Psm + wg*128*LDA;
#pragma unroll
        for (int mi=0;mi<2;mi++)
#pragma unroll
        for (int k8=0;k8<4;k8++){
            int r = wr*32 + mi*16 + lq, c = k8*8 + lr;
            qa[mi][k8][0] = f2tf_u(Qh[r*LDA + c]);
            qa[mi][k8][1] = f2tf_u(Qh[(r+8)*LDA + c]);
            qa[mi][k8][2] = f2tf_u(Qh[r*LDA + c+4]);
            qa[mi][k8][3] = f2tf_u(Qh[(r+8)*LDA + c+4]);
        }
    }
    float o[2][4][4];
#pragma unroll
    for (int mi=0;mi<2;mi++)
#pragma unroll
        for (int ni=0;ni<4;ni++)
#pragma unroll
            for (int e=0;e<4;e++) o[mi][ni][e]=0.f;
    float lsum[4] = {0.f,0.f,0.f,0.f};

    const float* Kg = g_K  + (long)(b*Nc)*Dc + hp*64;
    const float* Vg = g_Vm + (long)(b*Nc)*Dc + hp*64;
    const float* Mg = mask + (long)(b*Lc + l0)*Nc;
    float* Ph = Psm + wg*128*LDA;

    int s_hh[2], s_n[2], s_c4[2];
#pragma unroll
    for (int u=0;u<2;u++){
        int i = t + u*256;
        s_hh[u] = i>>8; int rem = i&255;
        s_n[u] = rem>>3; s_c4[u] = rem&7;
    }
    float4 pk[2], pv[2], pm[4];
#pragma unroll
    for (int u=0;u<2;u++){
        pk[u] = *(const float4*)&Kg[(long)(s_n[u])*Dc + s_hh[u]*32 + s_c4[u]*4];
        pv[u] = *(const float4*)&Vg[(long)(s_n[u])*Dc + s_hh[u]*32 + s_c4[u]*4];
    }
#pragma unroll
    for (int u=0;u<4;u++){
        int i = t + u*256, row = i>>3, c4 = i&7;
        pm[u] = *(const float4*)&Mg[(long)row*Nc + c4*4];
    }

    for (int n0=0; n0<Nc; n0+=32){
        __syncthreads();
#pragma unroll
        for (int u=0;u<2;u++){
            float* d = &Ksm[(s_hh[u]*32+s_n[u])*LDA + s_c4[u]*4];
            d[0]=f2tf(pk[u].x*kscale); d[1]=f2tf(pk[u].y*kscale);
            d[2]=f2tf(pk[u].z*kscale); d[3]=f2tf(pk[u].w*kscale);
            float* dv = &Vsm[(s_hh[u]*32+s_n[u])*LDA + s_c4[u]*4];
            dv[0]=f2tf(pv[u].x); dv[1]=f2tf(pv[u].y);
            dv[2]=f2tf(pv[u].z); dv[3]=f2tf(pv[u].w);
        }
#pragma unroll
        for (int u=0;u<4;u++){
            int i = t + u*256, row = i>>3, c4 = i&7;
            *(float4*)&Msm[row*LDA + c4*4] = pm[u];
        }
        if (n0 + 32 < Nc){
#pragma unroll
            for (int u=0;u<2;u++){
                pk[u] = *(const float4*)&Kg[(long)(n0+32+s_n[u])*Dc + s_hh[u]*32 + s_c4[u]*4];
                pv[u] = *(const float4*)&Vg[(long)(n0+32+s_n[u])*Dc + s_hh[u]*32 + s_c4[u]*4];
            }
#pragma unroll
            for (int u=0;u<4;u++){
                int i = t + u*256, row = i>>3, c4 = i&7;
                pm[u] = *(const float4*)&Mg[(long)row*Nc + n0+32 + c4*4];
            }
        }
        __syncthreads();

        float sc[2][4][4];
#pragma unroll
        for (int mi=0;mi<2;mi++)
#pragma unroll
            for (int ni=0;ni<4;ni++)
#pragma unroll
                for (int e=0;e<4;e++) sc[mi][ni][e]=0.f;
        const float* Kh = Ksm + wg*32*LDA;
#pragma unroll
        for (int k8=0;k8<4;k8++){
            uint32_t bf[4][2];
#pragma unroll
            for (int ni=0;ni<4;ni++){
                bf[ni][0] = __float_as_uint(Kh[(ni*8+lq)*LDA + k8*8 + lr]);
                bf[ni][1] = __float_as_uint(Kh[(ni*8+lq)*LDA + k8*8 + lr + 4]);
            }
#pragma unroll
            for (int mi=0;mi<2;mi++)
#pragma unroll
                for (int ni=0;ni<4;ni++)
                    mma_tf32(sc[mi][ni], qa[mi][k8], bf[ni]);
        }
#pragma unroll
        for (int mi=0;mi<2;mi++)
#pragma unroll
        for (int half=0;half<2;half++){
            int q = mi*2+half;
            int row = wr*32 + mi*16 + half*8 + lq;
            float ls = 0.f;
#pragma unroll
            for (int ni=0;ni<4;ni++){
                float m0 = Msm[row*LDA + ni*8 + 2*lr];
                float m1 = Msm[row*LDA + ni*8 + 2*lr + 1];
                // tf32-round p BEFORE summing so lsum matches the PV numerator
                float p0 = f2tf(exp2f(sc[mi][ni][half*2]   * m0));
                float p1 = f2tf(exp2f(sc[mi][ni][half*2+1] * m1));
                ls += p0 + p1;
                float2 pp; pp.x = p0; pp.y = p1;
                *(float2*)&Ph[row*LDA + ni*8 + 2*lr] = pp;
            }
            ls += __shfl_xor_sync(0xffffffffu, ls, 1);
            ls += __shfl_xor_sync(0xffffffffu, ls, 2);
            lsum[q] += ls;
        }
        __syncwarp();
        const float* Vh = Vsm + wg*32*LDA;
#pragma unroll
        for (int k8=0;k8<4;k8++){
            uint32_t pafr[2][4];
#pragma unroll
            for (int mi=0;mi<2;mi++){
                int r = wr*32 + mi*16 + lq, c = k8*8+lr;
                pafr[mi][0] = __float_as_uint(Ph[r*LDA + c]);
                pafr[mi][1] = __float_as_uint(Ph[(r+8)*LDA + c]);
                pafr[mi][2] = __float_as_uint(Ph[r*LDA + c+4]);
                pafr[mi][3] = __float_as_uint(Ph[(r+8)*LDA + c+4]);
            }
            uint32_t vbf[4][2];
#pragma unroll
            for (int ni=0;ni<4;ni++){
                vbf[ni][0] = __float_as_uint(Vh[(k8*8+lr)*LDA + ni*8 + lq]);
                vbf[ni][1] = __float_as_uint(Vh[(k8*8+lr+4)*LDA + ni*8 + lq]);
            }
#pragma unroll
            for (int mi=0;mi<2;mi++)
#pragma unroll
                for (int ni=0;ni<4;ni++)
                    mma_tf32(o[mi][ni], pafr[mi], vbf[ni]);
        }
    }
    float* Fg = (dir ? g_F[1] : g_F[0]) + (long)(b*Lc + l0)*Dc + (hp*2+wg)*32;
#pragma unroll
    for (int mi=0;mi<2;mi++)
#pragma unroll
    for (int half=0;half<2;half++){
        int q = mi*2+half;
        int row = wr*32 + mi*16 + half*8 + lq;
        float inv = 1.f/lsum[q];
#pragma unroll
        for (int ni=0;ni<4;ni++){
            float2 oo;
            oo.x = o[mi][ni][half*2]*inv;
            oo.y = o[mi][ni][half*2+1]*inv;
            *(float2*)&Fg[(long)row*Dc + ni*8 + 2*lr] = oo;
        }
    }
}

// ---------------- agreement loss: warp per (b,l) ----------------------------
__global__ void k_loss(const float* __restrict__ out, const float* __restrict__ tmask){
    int gw = blockIdx.x*8 + (threadIdx.x>>5);
    if (gw >= (Lc-1)*Bc) return;
    int l = gw % (Lc-1), b = gw / (Lc-1);
    int lane = threadIdx.x & 31;
    const float* rl = out + 1 + (long)(b*Lc + l)*Vc;
    const float* rr = out + 1 + (long)Bc*Lc*Vc + (long)(b*Lc + l + 1)*Vc;
    float xl[16], xr[16];
    float ml = -1e30f, mr = -1e30f;
#pragma unroll
    for (int u=0;u<16;u++){
        xl[u] = rl[lane + u*32]*0.5f;
        xr[u] = rr[lane + u*32]*0.5f;
        ml = fmaxf(ml, xl[u]); mr = fmaxf(mr, xr[u]);
    }
    ml = warpMax(ml); mr = warpMax(mr);
    float el[16], er[16], sl = 0.f, sr = 0.f;
#pragma unroll
    for (int u=0;u<16;u++){
        el[u] = __expf(xl[u]-ml); sl += el[u];
        er[u] = __expf(xr[u]-mr); sr += er[u];
    }
    sl = warpSum(sl); sr = warpSum(sr);
    float isl = 1.f/sl, isr = 1.f/sr;
    float agree = 0.f;
#pragma unroll
    for (int u=0;u<16;u++){
        float d = el[u]*isl - er[u]*isr;
        agree += d*d;
    }
    agree = warpSum(agree);
    if (lane == 0) atomicAdd(&g_num, agree * tmask[b*Lc + l]);
}

__global__ void k_final(const float* __restrict__ tmask, float* __restrict__ out){
    __shared__ float red[32];
    float s = 0.f;
    for (int e=threadIdx.x; e<Bc*Lc; e+=256){
        int l = e % Lc;
        if (l < Lc-1) s += tmask[e];
    }
    s = blockSum(s, red);
    if (threadIdx.x == 0){
        float den = fmaxf(s, 1.0f);
        out[0] = 0.1f * g_num / den;
    }
}

// ---------------- launch ----------------------------------------------------
extern "C" void kernel_launch(void* const* d_in, const int* in_sizes, int n_in,
                              void* d_out, int out_size){
    const float* vis   = (const float*)d_in[0];
    const int*   idl   = (const int*)  d_in[1];
    const int*   idr   = (const int*)  d_in[2];
    const float* tmask = (const float*)d_in[4];
    const float* vmask = (const float*)d_in[5];
    const float* emb   = (const float*)d_in[6];
    const float* dl    = (const float*)d_in[7];
    const float* dr    = (const float*)d_in[8];
    const float* pw    = (const float*)d_in[9];
    const float* pb    = (const float*)d_in[10];
    const float* qg    = (const float*)d_in[11];
    const float* qb    = (const float*)d_in[12];
    const float* kw    = (const float*)d_in[13];
    const float* kb    = (const float*)d_in[14];
    const float* vw    = (const float*)d_in[15];
    const float* vb    = (const float*)d_in[16];
    const float* kvg   = (const float*)d_in[17];
    const float* kvb   = (const float*)d_in[18];
    const float* tau   = (const float*)d_in[19];
    const float* clsb  = (const float*)d_in[20];
    const float* cwl   = (const float*)d_in[21];
    const float* cwr   = (const float*)d_in[22];
    float* out = (float*)d_out;

    const int SM_GEMM = GSM_FLOATS*4;                                  // 81920
    const int SM_ATTN = (2*32*LDA + 2*32*LDA + 128*LDA + 2*128*LDA)*4; // 81920
    cudaFuncSetAttribute(k_gemm, cudaFuncAttributeMaxDynamicSharedMemorySize, SM_GEMM);
    cudaFuncSetAttribute(k_attn, cudaFuncAttributeMaxDynamicSharedMemorySize, SM_ATTN);

    k_w3<<<dim3(1280,2), 256>>>(cwl, cwr);
    k_dirb<<<64, 256>>>(dl, dr, pw, pb);
    k_gemm<<<dim3(2,2,10), 256, SM_GEMM>>>(1, pw, nullptr, nullptr, nullptr, nullptr);
    k_gemm<<<dim3(4,2,10), 256, SM_GEMM>>>(2, emb, nullptr, nullptr, nullptr, nullptr);
    k_q<<<dim3(Bc*Lc,2), 256>>>(idl, idr, qg, qb);
    k_gemm<<<dim3(256,2,2), 256, SM_GEMM>>>(0, vis, kw, vw, nullptr, nullptr);
    k_ln<<<dim3(4096,2), 256>>>(kb, vb, kvg, kvb);
    k_attn<<<dim3(8,32,2), 256, SM_ATTN>>>(vmask, tau);
    k_gemm<<<dim3(64,4,2), 256, SM_GEMM>>>(3, nullptr, emb, nullptr, clsb, out);
    k_loss<<<1020, 256>>>(out, tmask);
    k_final<<<1, 256>>>(tmask, out);
}

// round 11
// speedup vs baseline: 3.2571x; 1.0418x over previous
#include <cuda_runtime.h>
#include <cstdint>
#include <math.h>
#include <mma.h>
using namespace nvcuda;

#define Bc  32
#define Lc  256
#define Sc  5
#define Nc  1024
#define Dc  256
#define Vc  512
#define Hc  8
#define DHc 32

// ---------------- scratch ----------------
__device__ float g_W3T[2][Sc*Dc*Dc];     // [dir][(s*256+j)*256 + dt]
__device__ float g_M[10*Dc*Dc];          // [dir*5+s][d*256 + j]
__device__ float g_Gp[2][Sc*Vc*Dc];
__device__ float g_dirb[2][Dc];
__device__ float g_Q[2][Bc*Lc*Dc];
__device__ float g_K[Bc*Nc*Dc];
__device__ float g_Vm[Bc*Nc*Dc];
__device__ float g_F[2][Bc*Lc*Dc];
__device__ float g_num;

// ---------------- helpers ----------------
__device__ __forceinline__ float warpSum(float v){
#pragma unroll
    for (int o=16;o>0;o>>=1) v += __shfl_xor_sync(0xffffffffu, v, o);
    return v;
}
__device__ __forceinline__ float warpMax(float v){
#pragma unroll
    for (int o=16;o>0;o>>=1) v = fmaxf(v, __shfl_xor_sync(0xffffffffu, v, o));
    return v;
}
__device__ __forceinline__ float blockSum(float v, float* red){
    v = warpSum(v);
    int w = threadIdx.x >> 5;
    __syncthreads();
    if ((threadIdx.x & 31) == 0) red[w] = v;
    __syncthreads();
    if (w == 0){
        float r = (threadIdx.x < 8) ? red[threadIdx.x] : 0.f;
        r = warpSum(r);
        if (threadIdx.x == 0) red[0] = r;
    }
    __syncthreads();
    return red[0];
}
__device__ __forceinline__ float f2tf(float x){
    uint32_t u; asm("cvt.rna.tf32.f32 %0, %1;" : "=r"(u) : "f"(x));
    return __uint_as_float(u);
}
__device__ __forceinline__ uint32_t f2tf_u(float x){
    uint32_t u; asm("cvt.rna.tf32.f32 %0, %1;" : "=r"(u) : "f"(x));
    return u;
}
__device__ __forceinline__ void mma_tf32(float* c, const uint32_t* a, const uint32_t* b){
    asm volatile("mma.sync.aligned.m16n8k8.row.col.f32.tf32.tf32.f32 "
        "{%0,%1,%2,%3}, {%4,%5,%6,%7}, {%8,%9}, {%0,%1,%2,%3};"
        : "+f"(c[0]),"+f"(c[1]),"+f"(c[2]),"+f"(c[3])
        : "r"(a[0]),"r"(a[1]),"r"(a[2]),"r"(a[3]), "r"(b[0]),"r"(b[1]));
}

// ---------------- k1: W3^T fold + dirb + zero, merged -----------------------
// grid (2624, 2): x<2560 -> w3 (y=dir); x>=2560 -> dirb (y==0 only)
__global__ void k_w3dirb(const float* __restrict__ wl, const float* __restrict__ wr,
                         const float* __restrict__ dl, const float* __restrict__ dr,
                         const float* __restrict__ P, const float* __restrict__ pb){
    if (blockIdx.x == 0 && blockIdx.y == 0 && threadIdx.x == 0) g_num = 0.f;
    if (blockIdx.x < 2560){
        int dir = blockIdx.y;
        const float* w = dir ? wr : wl;
        int idx = blockIdx.x*256 + threadIdx.x;
        int dt = idx & 255;
        int sj = idx >> 8;
        int s = sj / 256, j = sj % 256;
        float v = 0.f;
#pragma unroll
        for (int k=0;k<5;k++){
            int f = dt + 256*k;
            int o = f/5, sk = f%5;
            int tp = s - sk + 1;
            if (tp >= 0 && tp < 3) v += w[(o*Dc + j)*3 + tp];
        }
        g_W3T[dir][(s*Dc + j)*Dc + dt] = 0.2f*v;
    } else if (blockIdx.y == 0){
        int gw = (blockIdx.x-2560)*8 + (threadIdx.x>>5);   // 0..511
        int dir = gw >> 8, d = gw & 255;
        int lane = threadIdx.x & 31;
        const float* dv = dir ? dr : dl;
        const float4* P4 = (const float4*)(P + d*Dc);
        const float4* D4 = (const float4*)dv;
        float4 p0 = P4[lane], q0 = D4[lane];
        float4 p1 = P4[lane+32], q1 = D4[lane+32];
        float s = p0.x*q0.x + p0.y*q0.y + p0.z*q0.z + p0.w*q0.w
                + p1.x*q1.x + p1.y*q1.y + p1.z*q1.z + p1.w*q1.w;
        s = warpSum(s);
        if (lane == 0) g_dirb[dir][d] = s + pb[d];
    }
}

// ---------------- generic tf32 GEMM, double-buffered smem -------------------
#define GSM_FLOATS (4*5120)
__global__ void __launch_bounds__(256,2) k_gemm(int mode,
        const float* __restrict__ A, const float* __restrict__ B0,
        const float* __restrict__ B1, const float* __restrict__ bias,
        float* __restrict__ Cext){
    extern __shared__ float smem[];
    int z = blockIdx.z;
    const float* Ap; const float* Bp; float* Cp;
    int ldb, ldc;
    if (mode==0){
        Ap = A; Bp = z ? B1 : B0; ldb = 256;
        Cp = z ? &g_Vm[0] : &g_K[0]; ldc = 256;
    } else if (mode==1){
        Ap = A;
        Bp = &g_W3T[0][0] + (long)z*65536; ldb = 256;
        Cp = &g_M[0] + (long)z*65536; ldc = 256;
    } else if (mode==2){
        Ap = A;
        Bp = &g_M[0] + (long)z*65536; ldb = 256;
        Cp = &g_Gp[0][0] + (long)(z/5)*655360 + (long)(z%5)*131072; ldc = 256;
    } else {
        Ap = &g_F[0][0] + (long)z*8192*256;
        Bp = B0; ldb = 256;
        Cp = Cext + 1 + (long)z*8192*512; ldc = 512;
    }
    int row0 = blockIdx.x*128, col0 = blockIdx.y*128;
    int t = threadIdx.x, wid = t>>5, lane = t&31;
    int wm = wid>>2, wn = wid&3;

    wmma::fragment<wmma::accumulator,16,16,8,float> acc[4][2];
#pragma unroll
    for (int mi=0;mi<4;mi++)
#pragma unroll
        for (int ni=0;ni<2;ni++) wmma::fill_fragment(acc[mi][ni], 0.f);

    int r8 = t>>3, c8 = (t&7)*4;
    const float* Ag = &Ap[(long)(row0+r8)*256 + c8];
    const float* Bg = &Bp[(long)(col0+r8)*ldb + c8];

    float4 pa[4], pb[4];
#pragma unroll
    for (int u=0;u<4;u++){
        pa[u] = *(const float4*)(Ag + (long)(u*32)*256);
        pb[u] = *(const float4*)(Bg + (long)(u*32)*ldb);
    }
    {
        float* Ad = smem + r8*40 + c8;
        float* Bd = smem + 5120 + r8*40 + c8;
#pragma unroll
        for (int u=0;u<4;u++){
            Ad[u*32*40+0]=f2tf(pa[u].x); Ad[u*32*40+1]=f2tf(pa[u].y);
            Ad[u*32*40+2]=f2tf(pa[u].z); Ad[u*32*40+3]=f2tf(pa[u].w);
            Bd[u*32*40+0]=f2tf(pb[u].x); Bd[u*32*40+1]=f2tf(pb[u].y);
            Bd[u*32*40+2]=f2tf(pb[u].z); Bd[u*32*40+3]=f2tf(pb[u].w);
        }
    }

    for (int kb8=0; kb8<8; kb8++){
        __syncthreads();
        if (kb8 < 7){
            int off = (kb8+1)*32;
#pragma unroll
            for (int u=0;u<4;u++){
                pa[u] = *(const float4*)(Ag + (long)(u*32)*256 + off);
                pb[u] = *(const float4*)(Bg + (long)(u*32)*ldb + off);
            }
        }
        const float* Asb = smem + (kb8&1)*10240;
        const float* Bsb = smem + 5120 + (kb8&1)*10240;
#pragma unroll
        for (int k8=0;k8<4;k8++){
            wmma::fragment<wmma::matrix_a,16,16,8,wmma::precision::tf32,wmma::row_major> af[4];
            wmma::fragment<wmma::matrix_b,16,16,8,wmma::precision::tf32,wmma::col_major> bf[2];
#pragma unroll
            for (int mi=0;mi<4;mi++)
                wmma::load_matrix_sync(af[mi], Asb + (wm*64 + mi*16)*40 + k8*8, 40);
#pragma unroll
            for (int ni=0;ni<2;ni++)
                wmma::load_matrix_sync(bf[ni], Bsb + (wn*32 + ni*16)*40 + k8*8, 40);
#pragma unroll
            for (int mi=0;mi<4;mi++)
#pragma unroll
                for (int ni=0;ni<2;ni++)
                    wmma::mma_sync(acc[mi][ni], af[mi], bf[ni], acc[mi][ni]);
        }
        if (kb8 < 7){
            float* Ad = smem + ((kb8+1)&1)*10240 + r8*40 + c8;
            float* Bd = smem + 5120 + ((kb8+1)&1)*10240 + r8*40 + c8;
#pragma unroll
            for (int u=0;u<4;u++){
                Ad[u*32*40+0]=f2tf(pa[u].x); Ad[u*32*40+1]=f2tf(pa[u].y);
                Ad[u*32*40+2]=f2tf(pa[u].z); Ad[u*32*40+3]=f2tf(pa[u].w);
                Bd[u*32*40+0]=f2tf(pb[u].x); Bd[u*32*40+1]=f2tf(pb[u].y);
                Bd[u*32*40+2]=f2tf(pb[u].z); Bd[u*32*40+3]=f2tf(pb[u].w);
            }
        }
    }
    if (mode != 3){
#pragma unroll
        for (int mi=0;mi<4;mi++)
#pragma unroll
            for (int ni=0;ni<2;ni++)
                wmma::store_matrix_sync(&Cp[(long)(row0+wm*64+mi*16)*ldc + col0 + wn*32 + ni*16],
                                        acc[mi][ni], ldc, wmma::mem_row_major);
    } else {
        __syncthreads();
        float* stage = smem + wid*(16*18);
#pragma unroll
        for (int mi=0;mi<4;mi++)
#pragma unroll
            for (int ni=0;ni<2;ni++){
                wmma::store_matrix_sync(stage, acc[mi][ni], 18, wmma::mem_row_major);
                __syncwarp();
                for (int e=lane; e<256; e+=32){
                    int r = e>>4, c = e&15;
                    int col = col0 + wn*32 + ni*16 + c;
                    Cp[(long)(row0+wm*64+mi*16+r)*ldc + col] = stage[r*18+c] + bias[col];
                }
                __syncwarp();
            }
    }
}

// ---------------- LN (+bias) in place on g_K / g_Vm -------------------------
__global__ void k_ln(const float* __restrict__ kb, const float* __restrict__ vb,
                     const float* __restrict__ gamma, const float* __restrict__ beta){
    int z = blockIdx.y;
    float* X = z ? &g_Vm[0] : &g_K[0];
    const float* bias = z ? vb : kb;
    int wid = threadIdx.x>>5, lane = threadIdx.x&31;
    long row = (long)blockIdx.x*8 + wid;
    float4* R = (float4*)(X + row*256);
    const float4* B4 = (const float4*)bias;
    const float4* G4 = (const float4*)gamma;
    const float4* T4 = (const float4*)beta;
    float4 x0 = R[lane], x1 = R[lane+32];
    float4 b0 = B4[lane], b1 = B4[lane+32];
    x0.x+=b0.x; x0.y+=b0.y; x0.z+=b0.z; x0.w+=b0.w;
    x1.x+=b1.x; x1.y+=b1.y; x1.z+=b1.z; x1.w+=b1.w;
    float s  = x0.x+x0.y+x0.z+x0.w + x1.x+x1.y+x1.z+x1.w;
    float s2 = x0.x*x0.x+x0.y*x0.y+x0.z*x0.z+x0.w*x0.w
             + x1.x*x1.x+x1.y*x1.y+x1.z*x1.z+x1.w*x1.w;
    s = warpSum(s); s2 = warpSum(s2);
    float m = s*(1.f/256.f);
    float r = rsqrtf(s2*(1.f/256.f) - m*m + 1e-5f);
    float4 g0 = G4[lane], g1 = G4[lane+32];
    float4 t0 = T4[lane], t1 = T4[lane+32];
    float4 o0, o1;
    o0.x=(x0.x-m)*r*g0.x+t0.x; o0.y=(x0.y-m)*r*g0.y+t0.y;
    o0.z=(x0.z-m)*r*g0.z+t0.z; o0.w=(x0.w-m)*r*g0.w+t0.w;
    o1.x=(x1.x-m)*r*g1.x+t1.x; o1.y=(x1.y-m)*r*g1.y+t1.y;
    o1.z=(x1.z-m)*r*g1.z+t1.z; o1.w=(x1.w-m)*r*g1.w+t1.w;
    R[lane] = o0; R[lane+32] = o1;
}

// ---------------- Q = LN(sum_s Gp[s,id_s] + dir') ----------------
__global__ void k_q(const int* __restrict__ idl, const int* __restrict__ idr,
                    const float* __restrict__ gamma, const float* __restrict__ beta){
    int dir = blockIdx.y;
    int bl  = blockIdx.x;
    const int* ids = (dir ? idr : idl) + bl*Sc;
    __shared__ int sid[8];
    __shared__ float red[32];
    int d = threadIdx.x;
    if (d < Sc) sid[d] = ids[d];
    __syncthreads();
    float v = g_dirb[dir][d];
#pragma unroll
    for (int s=0;s<Sc;s++) v += g_Gp[dir][(s*Vc + sid[s])*Dc + d];
    float m   = blockSum(v, red) * (1.f/256.f);
    float dv  = v - m;
    float var = blockSum(dv*dv, red) * (1.f/256.f);
    float o   = dv * rsqrtf(var + 1e-5f) * gamma[d] + beta[d];
    g_Q[dir][bl*Dc + d] = o;
}

// ---------------- flash attention, tf32 mma, no-max softmax ------------------
#define LDA 40
__global__ void __launch_bounds__(256,2) k_attn(const float* __restrict__ mask,
                                                const float* __restrict__ tau_p){
    extern __shared__ float sm[];
    float* Ksm  = sm;                    // [2][32][40]
    float* Vsm  = Ksm + 2*32*LDA;        // [2][32][40]
    float* Msm  = Vsm + 2*32*LDA;        // [128][40]
    float* Psm  = Msm + 128*LDA;         // [2][128][40]
    int lt = blockIdx.x >> 2, hp = blockIdx.x & 3;
    int b = blockIdx.y, dir = blockIdx.z;
    int l0 = lt*128;
    int t = threadIdx.x, wid = t>>5, lane = t&31;
    int wg = wid>>2, wr = wid&3;
    int lq = lane>>2, lr = lane&3;
    float tau = fminf(fmaxf(tau_p[0],0.25f),4.f);
    float kscale = 1.44269504f/(5.656854249f*tau);

    const float* Qbase = (dir ? g_Q[1] : g_Q[0]) + (long)(b*Lc + l0)*Dc + hp*64;
    for (int i=t; i<2048; i+=256){
        int hh = i>>10, rem = i&1023, row = rem>>3, c4 = rem&7;
        *(float4*)&Psm[(hh*128+row)*LDA + c4*4] =
            *(const float4*)&Qbase[(long)row*Dc + hh*32 + c4*4];
    }
    __syncthreads();
    uint32_t qa[2][4][4];
    {
        const float* Qh = Psm + wg*128*LDA;
#pragma unroll
        for (int mi=0;mi<2;mi++)
#pragma unroll
        for (int k8=0;k8<4;k8++){
            int r = wr*32 + mi*16 + lq, c = k8*8 + lr;
            qa[mi][k8][0] = f2tf_u(Qh[r*LDA + c]);
            qa[mi][k8][1] = f2tf_u(Qh[(r+8)*LDA + c]);
            qa[mi][k8][2] = f2tf_u(Qh[r*LDA + c+4]);
            qa[mi][k8][3] = f2tf_u(Qh[(r+8)*LDA + c+4]);
        }
    }
    float o[2][4][4];
#pragma unroll
    for (int mi=0;mi<2;mi++)
#pragma unroll
        for (int ni=0;ni<4;ni++)
#pragma unroll
            for (int e=0;e<4;e++) o[mi][ni][e]=0.f;
    float lsum[4] = {0.f,0.f,0.f,0.f};

    const float* Kg = g_K  + (long)(b*Nc)*Dc + hp*64;
    const float* Vg = g_Vm + (long)(b*Nc)*Dc + hp*64;
    const float* Mg = mask + (long)(b*Lc + l0)*Nc;
    float* Ph = Psm + wg*128*LDA;

    int s_hh[2], s_n[2], s_c4[2];
#pragma unroll
    for (int u=0;u<2;u++){
        int i = t + u*256;
        s_hh[u] = i>>8; int rem = i&255;
        s_n[u] = rem>>3; s_c4[u] = rem&7;
    }
    float4 pk[2], pv[2], pm[4];
#pragma unroll
    for (int u=0;u<2;u++){
        pk[u] = *(const float4*)&Kg[(long)(s_n[u])*Dc + s_hh[u]*32 + s_c4[u]*4];
        pv[u] = *(const float4*)&Vg[(long)(s_n[u])*Dc + s_hh[u]*32 + s_c4[u]*4];
    }
#pragma unroll
    for (int u=0;u<4;u++){
        int i = t + u*256, row = i>>3, c4 = i&7;
        pm[u] = *(const float4*)&Mg[(long)row*Nc + c4*4];
    }

    for (int n0=0; n0<Nc; n0+=32){
        __syncthreads();
#pragma unroll
        for (int u=0;u<2;u++){
            float* d = &Ksm[(s_hh[u]*32+s_n[u])*LDA + s_c4[u]*4];
            d[0]=f2tf(pk[u].x*kscale); d[1]=f2tf(pk[u].y*kscale);
            d[2]=f2tf(pk[u].z*kscale); d[3]=f2tf(pk[u].w*kscale);
            float* dv = &Vsm[(s_hh[u]*32+s_n[u])*LDA + s_c4[u]*4];
            dv[0]=f2tf(pv[u].x); dv[1]=f2tf(pv[u].y);
            dv[2]=f2tf(pv[u].z); dv[3]=f2tf(pv[u].w);
        }
#pragma unroll
        for (int u=0;u<4;u++){
            int i = t + u*256, row = i>>3, c4 = i&7;
            *(float4*)&Msm[row*LDA + c4*4] = pm[u];
        }
        if (n0 + 32 < Nc){
#pragma unroll
            for (int u=0;u<2;u++){
                pk[u] = *(const float4*)&Kg[(long)(n0+32+s_n[u])*Dc + s_hh[u]*32 + s_c4[u]*4];
                pv[u] = *(const float4*)&Vg[(long)(n0+32+s_n[u])*Dc + s_hh[u]*32 + s_c4[u]*4];
            }
#pragma unroll
            for (int u=0;u<4;u++){
                int i = t + u*256, row = i>>3, c4 = i&7;
                pm[u] = *(const float4*)&Mg[(long)row*Nc + n0+32 + c4*4];
            }
        }
        __syncthreads();

        float sc[2][4][4];
#pragma unroll
        for (int mi=0;mi<2;mi++)
#pragma unroll
            for (int ni=0;ni<4;ni++)
#pragma unroll
                for (int e=0;e<4;e++) sc[mi][ni][e]=0.f;
        const float* Kh = Ksm + wg*32*LDA;
#pragma unroll
        for (int k8=0;k8<4;k8++){
            uint32_t bf[4][2];
#pragma unroll
            for (int ni=0;ni<4;ni++){
                bf[ni][0] = __float_as_uint(Kh[(ni*8+lq)*LDA + k8*8 + lr]);
                bf[ni][1] = __float_as_uint(Kh[(ni*8+lq)*LDA + k8*8 + lr + 4]);
            }
#pragma unroll
            for (int mi=0;mi<2;mi++)
#pragma unroll
                for (int ni=0;ni<4;ni++)
                    mma_tf32(sc[mi][ni], qa[mi][k8], bf[ni]);
        }
#pragma unroll
        for (int mi=0;mi<2;mi++)
#pragma unroll
        for (int half=0;half<2;half++){
            int q = mi*2+half;
            int row = wr*32 + mi*16 + half*8 + lq;
            float ls = 0.f;
#pragma unroll
            for (int ni=0;ni<4;ni++){
                float2 mm = *(const float2*)&Msm[row*LDA + ni*8 + 2*lr];
                float p0 = f2tf(exp2f(sc[mi][ni][half*2]   * mm.x));
                float p1 = f2tf(exp2f(sc[mi][ni][half*2+1] * mm.y));
                ls += p0 + p1;
                float2 pp; pp.x = p0; pp.y = p1;
                *(float2*)&Ph[row*LDA + ni*8 + 2*lr] = pp;
            }
            ls += __shfl_xor_sync(0xffffffffu, ls, 1);
            ls += __shfl_xor_sync(0xffffffffu, ls, 2);
            lsum[q] += ls;
        }
        __syncwarp();
        const float* Vh = Vsm + wg*32*LDA;
#pragma unroll
        for (int k8=0;k8<4;k8++){
            uint32_t pafr[2][4];
#pragma unroll
            for (int mi=0;mi<2;mi++){
                int r = wr*32 + mi*16 + lq, c = k8*8+lr;
                pafr[mi][0] = __float_as_uint(Ph[r*LDA + c]);
                pafr[mi][1] = __float_as_uint(Ph[(r+8)*LDA + c]);
                pafr[mi][2] = __float_as_uint(Ph[r*LDA + c+4]);
                pafr[mi][3] = __float_as_uint(Ph[(r+8)*LDA + c+4]);
            }
            uint32_t vbf[4][2];
#pragma unroll
            for (int ni=0;ni<4;ni++){
                vbf[ni][0] = __float_as_uint(Vh[(k8*8+lr)*LDA + ni*8 + lq]);
                vbf[ni][1] = __float_as_uint(Vh[(k8*8+lr+4)*LDA + ni*8 + lq]);
            }
#pragma unroll
            for (int mi=0;mi<2;mi++)
#pragma unroll
                for (int ni=0;ni<4;ni++)
                    mma_tf32(o[mi][ni], pafr[mi], vbf[ni]);
        }
    }
    float* Fg = (dir ? g_F[1] : g_F[0]) + (long)(b*Lc + l0)*Dc + (hp*2+wg)*32;
#pragma unroll
    for (int mi=0;mi<2;mi++)
#pragma unroll
    for (int half=0;half<2;half++){
        int q = mi*2+half;
        int row = wr*32 + mi*16 + half*8 + lq;
        float inv = 1.f/lsum[q];
#pragma unroll
        for (int ni=0;ni<4;ni++){
            float2 oo;
            oo.x = o[mi][ni][half*2]*inv;
            oo.y = o[mi][ni][half*2+1]*inv;
            *(float2*)&Fg[(long)row*Dc + ni*8 + 2*lr] = oo;
        }
    }
}

// ---------------- agreement loss: warp per (b,l) ----------------------------
__global__ void k_loss(const float* __restrict__ out, const float* __restrict__ tmask){
    int gw = blockIdx.x*8 + (threadIdx.x>>5);
    if (gw >= (Lc-1)*Bc) return;
    int l = gw % (Lc-1), b = gw / (Lc-1);
    int lane = threadIdx.x & 31;
    const float* rl = out + 1 + (long)(b*Lc + l)*Vc;
    const float* rr = out + 1 + (long)Bc*Lc*Vc + (long)(b*Lc + l + 1)*Vc;
    float xl[16], xr[16];
    float ml = -1e30f, mr = -1e30f;
#pragma unroll
    for (int u=0;u<16;u++){
        xl[u] = rl[lane + u*32]*0.5f;
        xr[u] = rr[lane + u*32]*0.5f;
        ml = fmaxf(ml, xl[u]); mr = fmaxf(mr, xr[u]);
    }
    ml = warpMax(ml); mr = warpMax(mr);
    float el[16], er[16], sl = 0.f, sr = 0.f;
#pragma unroll
    for (int u=0;u<16;u++){
        el[u] = __expf(xl[u]-ml); sl += el[u];
        er[u] = __expf(xr[u]-mr); sr += er[u];
    }
    sl = warpSum(sl); sr = warpSum(sr);
    float isl = 1.f/sl, isr = 1.f/sr;
    float agree = 0.f;
#pragma unroll
    for (int u=0;u<16;u++){
        float d = el[u]*isl - er[u]*isr;
        agree += d*d;
    }
    agree = warpSum(agree);
    if (lane == 0) atomicAdd(&g_num, agree * tmask[b*Lc + l]);
}

__global__ void k_final(const float* __restrict__ tmask, float* __restrict__ out){
    __shared__ float red[32];
    float s = 0.f;
    for (int e=threadIdx.x; e<Bc*Lc; e+=256){
        int l = e % Lc;
        if (l < Lc-1) s += tmask[e];
    }
    s = blockSum(s, red);
    if (threadIdx.x == 0){
        float den = fmaxf(s, 1.0f);
        out[0] = 0.1f * g_num / den;
    }
}

// ---------------- launch ----------------------------------------------------
extern "C" void kernel_launch(void* const* d_in, const int* in_sizes, int n_in,
                              void* d_out, int out_size){
    const float* vis   = (const float*)d_in[0];
    const int*   idl   = (const int*)  d_in[1];
    const int*   idr   = (const int*)  d_in[2];
    const float* tmask = (const float*)d_in[4];
    const float* vmask = (const float*)d_in[5];
    const float* emb   = (const float*)d_in[6];
    const float* dl    = (const float*)d_in[7];
    const float* dr    = (const float*)d_in[8];
    const float* pw    = (const float*)d_in[9];
    const float* pb    = (const float*)d_in[10];
    const float* qg    = (const float*)d_in[11];
    const float* qb    = (const float*)d_in[12];
    const float* kw    = (const float*)d_in[13];
    const float* kb    = (const float*)d_in[14];
    const float* vw    = (const float*)d_in[15];
    const float* vb    = (const float*)d_in[16];
    const float* kvg   = (const float*)d_in[17];
    const float* kvb   = (const float*)d_in[18];
    const float* tau   = (const float*)d_in[19];
    const float* clsb  = (const float*)d_in[20];
    const float* cwl   = (const float*)d_in[21];
    const float* cwr   = (const float*)d_in[22];
    float* out = (float*)d_out;

    const int SM_GEMM = GSM_FLOATS*4;                                  // 81920
    const int SM_ATTN = (2*32*LDA + 2*32*LDA + 128*LDA + 2*128*LDA)*4; // 81920
    static bool init_done = false;
    static cudaStream_t s1;
    static cudaEvent_t e0, e1;
    if (!init_done){
        cudaFuncSetAttribute(k_gemm, cudaFuncAttributeMaxDynamicSharedMemorySize, SM_GEMM);
        cudaFuncSetAttribute(k_attn, cudaFuncAttributeMaxDynamicSharedMemorySize, SM_ATTN);
        cudaStreamCreateWithFlags(&s1, cudaStreamNonBlocking);
        cudaEventCreateWithFlags(&e0, cudaEventDisableTiming);
        cudaEventCreateWithFlags(&e1, cudaEventDisableTiming);
        init_done = true;
    }

    // fork: chain B (KV gemm + LN) on s1, chain A on capture stream
    cudaEventRecord(e0, 0);
    cudaStreamWaitEvent(s1, e0, 0);
    k_gemm<<<dim3(256,2,2), 256, SM_GEMM, s1>>>(0, vis, kw, vw, nullptr, nullptr);
    k_ln<<<dim3(4096,2), 256, 0, s1>>>(kb, vb, kvg, kvb);
    cudaEventRecord(e1, s1);

    k_w3dirb<<<dim3(2624,2), 256>>>(cwl, cwr, dl, dr, pw, pb);
    k_gemm<<<dim3(2,2,10), 256, SM_GEMM>>>(1, pw, nullptr, nullptr, nullptr, nullptr);
    k_gemm<<<dim3(4,2,10), 256, SM_GEMM>>>(2, emb, nullptr, nullptr, nullptr, nullptr);
    k_q<<<dim3(Bc*Lc,2), 256>>>(idl, idr, qg, qb);

    // join
    cudaStreamWaitEvent(0, e1, 0);
    k_attn<<<dim3(8,32,2), 256, SM_ATTN>>>(vmask, tau);
    k_gemm<<<dim3(64,4,2), 256, SM_GEMM>>>(3, nullptr, emb, nullptr, clsb, out);
    k_loss<<<1020, 256>>>(out, tmask);
    k_final<<<1, 256>>>(tmask, out);
}

// round 13
// speedup vs baseline: 3.5414x; 1.0873x over previous
#include <cuda_runtime.h>
#include <cstdint>
#include <math.h>
#include <mma.h>
using namespace nvcuda;

#define Bc  32
#define Lc  256
#define Sc  5
#define Nc  1024
#define Dc  256
#define Vc  512
#define Hc  8
#define DHc 32

// ---------------- scratch ----------------
__device__ float g_W3T[2][Sc*Dc*Dc];
__device__ float g_M[10*Dc*Dc];
__device__ float g_Gp[2][Sc*Vc*Dc];
__device__ float g_dirb[2][Dc];
__device__ float g_Q[2][Bc*Lc*Dc];
__device__ float g_K[Bc*Nc*Dc];
__device__ float g_Vm[Bc*Nc*Dc];
__device__ float g_F[2][Bc*Lc*Dc];
__device__ float g_num;

// ---------------- helpers ----------------
__device__ __forceinline__ float warpSum(float v){
#pragma unroll
    for (int o=16;o>0;o>>=1) v += __shfl_xor_sync(0xffffffffu, v, o);
    return v;
}
__device__ __forceinline__ float warpMax(float v){
#pragma unroll
    for (int o=16;o>0;o>>=1) v = fmaxf(v, __shfl_xor_sync(0xffffffffu, v, o));
    return v;
}
__device__ __forceinline__ float blockSum(float v, float* red){
    v = warpSum(v);
    int w = threadIdx.x >> 5;
    __syncthreads();
    if ((threadIdx.x & 31) == 0) red[w] = v;
    __syncthreads();
    if (w == 0){
        float r = (threadIdx.x < 8) ? red[threadIdx.x] : 0.f;
        r = warpSum(r);
        if (threadIdx.x == 0) red[0] = r;
    }
    __syncthreads();
    return red[0];
}
__device__ __forceinline__ float f2tf(float x){
    uint32_t u; asm("cvt.rna.tf32.f32 %0, %1;" : "=r"(u) : "f"(x));
    return __uint_as_float(u);
}
__device__ __forceinline__ uint32_t f2tf_u(float x){
    uint32_t u; asm("cvt.rna.tf32.f32 %0, %1;" : "=r"(u) : "f"(x));
    return u;
}
__device__ __forceinline__ void mma_tf32(float* c, const uint32_t* a, const uint32_t* b){
    asm volatile("mma.sync.aligned.m16n8k8.row.col.f32.tf32.tf32.f32 "
        "{%0,%1,%2,%3}, {%4,%5,%6,%7}, {%8,%9}, {%0,%1,%2,%3};"
        : "+f"(c[0]),"+f"(c[1]),"+f"(c[2]),"+f"(c[3])
        : "r"(a[0]),"r"(a[1]),"r"(a[2]),"r"(a[3]), "r"(b[0]),"r"(b[1]));
}

// ---------------- k1: W3^T fold + dirb + zero, merged -----------------------
__global__ void k_w3dirb(const float* __restrict__ wl, const float* __restrict__ wr,
                         const float* __restrict__ dl, const float* __restrict__ dr,
                         const float* __restrict__ P, const float* __restrict__ pb){
    if (blockIdx.x == 0 && blockIdx.y == 0 && threadIdx.x == 0) g_num = 0.f;
    if (blockIdx.x < 2560){
        int dir = blockIdx.y;
        const float* w = dir ? wr : wl;
        int idx = blockIdx.x*256 + threadIdx.x;
        int dt = idx & 255;
        int sj = idx >> 8;
        int s = sj / 256, j = sj % 256;
        float v = 0.f;
#pragma unroll
        for (int k=0;k<5;k++){
            int f = dt + 256*k;
            int o = f/5, sk = f%5;
            int tp = s - sk + 1;
            if (tp >= 0 && tp < 3) v += w[(o*Dc + j)*3 + tp];
        }
        g_W3T[dir][(s*Dc + j)*Dc + dt] = 0.2f*v;
    } else if (blockIdx.y == 0){
        int gw = (blockIdx.x-2560)*8 + (threadIdx.x>>5);
        int dir = gw >> 8, d = gw & 255;
        int lane = threadIdx.x & 31;
        const float* dv = dir ? dr : dl;
        const float4* P4 = (const float4*)(P + d*Dc);
        const float4* D4 = (const float4*)dv;
        float4 p0 = P4[lane], q0 = D4[lane];
        float4 p1 = P4[lane+32], q1 = D4[lane+32];
        float s = p0.x*q0.x + p0.y*q0.y + p0.z*q0.z + p0.w*q0.w
                + p1.x*q1.x + p1.y*q1.y + p1.z*q1.z + p1.w*q1.w;
        s = warpSum(s);
        if (lane == 0) g_dirb[dir][d] = s + pb[d];
    }
}

// ---------------- generic tf32 GEMM, double-buffered smem -------------------
#define GSM_FLOATS (4*5120)
__global__ void __launch_bounds__(256,2) k_gemm(int mode,
        const float* __restrict__ A, const float* __restrict__ B0,
        const float* __restrict__ B1, const float* __restrict__ bias,
        float* __restrict__ Cext){
    extern __shared__ float smem[];
    int z = blockIdx.z;
    const float* Ap; const float* Bp; float* Cp;
    int ldb, ldc;
    if (mode==0){
        Ap = A; Bp = z ? B1 : B0; ldb = 256;
        Cp = z ? &g_Vm[0] : &g_K[0]; ldc = 256;
    } else if (mode==1){
        Ap = A;
        Bp = &g_W3T[0][0] + (long)z*65536; ldb = 256;
        Cp = &g_M[0] + (long)z*65536; ldc = 256;
    } else if (mode==2){
        Ap = A;
        Bp = &g_M[0] + (long)z*65536; ldb = 256;
        Cp = &g_Gp[0][0] + (long)(z/5)*655360 + (long)(z%5)*131072; ldc = 256;
    } else {
        Ap = &g_F[0][0] + (long)z*8192*256;
        Bp = B0; ldb = 256;
        Cp = Cext + 1 + (long)z*8192*512; ldc = 512;
    }
    int row0 = blockIdx.x*128, col0 = blockIdx.y*128;
    int t = threadIdx.x, wid = t>>5, lane = t&31;
    int wm = wid>>2, wn = wid&3;

    wmma::fragment<wmma::accumulator,16,16,8,float> acc[4][2];
#pragma unroll
    for (int mi=0;mi<4;mi++)
#pragma unroll
        for (int ni=0;ni<2;ni++) wmma::fill_fragment(acc[mi][ni], 0.f);

    int r8 = t>>3, c8 = (t&7)*4;
    const float* Ag = &Ap[(long)(row0+r8)*256 + c8];
    const float* Bg = &Bp[(long)(col0+r8)*ldb + c8];

    float4 pa[4], pb[4];
#pragma unroll
    for (int u=0;u<4;u++){
        pa[u] = *(const float4*)(Ag + (long)(u*32)*256);
        pb[u] = *(const float4*)(Bg + (long)(u*32)*ldb);
    }
    {
        float* Ad = smem + r8*40 + c8;
        float* Bd = smem + 5120 + r8*40 + c8;
#pragma unroll
        for (int u=0;u<4;u++){
            Ad[u*32*40+0]=f2tf(pa[u].x); Ad[u*32*40+1]=f2tf(pa[u].y);
            Ad[u*32*40+2]=f2tf(pa[u].z); Ad[u*32*40+3]=f2tf(pa[u].w);
            Bd[u*32*40+0]=f2tf(pb[u].x); Bd[u*32*40+1]=f2tf(pb[u].y);
            Bd[u*32*40+2]=f2tf(pb[u].z); Bd[u*32*40+3]=f2tf(pb[u].w);
        }
    }

    for (int kb8=0; kb8<8; kb8++){
        __syncthreads();
        if (kb8 < 7){
            int off = (kb8+1)*32;
#pragma unroll
            for (int u=0;u<4;u++){
                pa[u] = *(const float4*)(Ag + (long)(u*32)*256 + off);
                pb[u] = *(const float4*)(Bg + (long)(u*32)*ldb + off);
            }
        }
        const float* Asb = smem + (kb8&1)*10240;
        const float* Bsb = smem + 5120 + (kb8&1)*10240;
#pragma unroll
        for (int k8=0;k8<4;k8++){
            wmma::fragment<wmma::matrix_a,16,16,8,wmma::precision::tf32,wmma::row_major> af[4];
            wmma::fragment<wmma::matrix_b,16,16,8,wmma::precision::tf32,wmma::col_major> bf[2];
#pragma unroll
            for (int mi=0;mi<4;mi++)
                wmma::load_matrix_sync(af[mi], Asb + (wm*64 + mi*16)*40 + k8*8, 40);
#pragma unroll
            for (int ni=0;ni<2;ni++)
                wmma::load_matrix_sync(bf[ni], Bsb + (wn*32 + ni*16)*40 + k8*8, 40);
#pragma unroll
            for (int mi=0;mi<4;mi++)
#pragma unroll
                for (int ni=0;ni<2;ni++)
                    wmma::mma_sync(acc[mi][ni], af[mi], bf[ni], acc[mi][ni]);
        }
        if (kb8 < 7){
            float* Ad = smem + ((kb8+1)&1)*10240 + r8*40 + c8;
            float* Bd = smem + 5120 + ((kb8+1)&1)*10240 + r8*40 + c8;
#pragma unroll
            for (int u=0;u<4;u++){
                Ad[u*32*40+0]=f2tf(pa[u].x); Ad[u*32*40+1]=f2tf(pa[u].y);
                Ad[u*32*40+2]=f2tf(pa[u].z); Ad[u*32*40+3]=f2tf(pa[u].w);
                Bd[u*32*40+0]=f2tf(pb[u].x); Bd[u*32*40+1]=f2tf(pb[u].y);
                Bd[u*32*40+2]=f2tf(pb[u].z); Bd[u*32*40+3]=f2tf(pb[u].w);
            }
        }
    }
    if (mode != 3){
#pragma unroll
        for (int mi=0;mi<4;mi++)
#pragma unroll
            for (int ni=0;ni<2;ni++)
                wmma::store_matrix_sync(&Cp[(long)(row0+wm*64+mi*16)*ldc + col0 + wn*32 + ni*16],
                                        acc[mi][ni], ldc, wmma::mem_row_major);
    } else {
        __syncthreads();
        float* stage = smem + wid*(16*18);
#pragma unroll
        for (int mi=0;mi<4;mi++)
#pragma unroll
            for (int ni=0;ni<2;ni++){
                wmma::store_matrix_sync(stage, acc[mi][ni], 18, wmma::mem_row_major);
                __syncwarp();
                for (int e=lane; e<256; e+=32){
                    int r = e>>4, c = e&15;
                    int col = col0 + wn*32 + ni*16 + c;
                    Cp[(long)(row0+wm*64+mi*16+r)*ldc + col] = stage[r*18+c] + bias[col];
                }
                __syncwarp();
            }
    }
}

// ---------------- LN (+bias) in place on g_K / g_Vm -------------------------
__global__ void k_ln(const float* __restrict__ kb, const float* __restrict__ vb,
                     const float* __restrict__ gamma, const float* __restrict__ beta){
    int z = blockIdx.y;
    float* X = z ? &g_Vm[0] : &g_K[0];
    const float* bias = z ? vb : kb;
    int wid = threadIdx.x>>5, lane = threadIdx.x&31;
    long row = (long)blockIdx.x*8 + wid;
    float4* R = (float4*)(X + row*256);
    const float4* B4 = (const float4*)bias;
    const float4* G4 = (const float4*)gamma;
    const float4* T4 = (const float4*)beta;
    float4 x0 = R[lane], x1 = R[lane+32];
    float4 b0 = B4[lane], b1 = B4[lane+32];
    x0.x+=b0.x; x0.y+=b0.y; x0.z+=b0.z; x0.w+=b0.w;
    x1.x+=b1.x; x1.y+=b1.y; x1.z+=b1.z; x1.w+=b1.w;
    float s  = x0.x+x0.y+x0.z+x0.w + x1.x+x1.y+x1.z+x1.w;
    float s2 = x0.x*x0.x+x0.y*x0.y+x0.z*x0.z+x0.w*x0.w
             + x1.x*x1.x+x1.y*x1.y+x1.z*x1.z+x1.w*x1.w;
    s = warpSum(s); s2 = warpSum(s2);
    float m = s*(1.f/256.f);
    float r = rsqrtf(s2*(1.f/256.f) - m*m + 1e-5f);
    float4 g0 = G4[lane], g1 = G4[lane+32];
    float4 t0 = T4[lane], t1 = T4[lane+32];
    float4 o0, o1;
    o0.x=(x0.x-m)*r*g0.x+t0.x; o0.y=(x0.y-m)*r*g0.y+t0.y;
    o0.z=(x0.z-m)*r*g0.z+t0.z; o0.w=(x0.w-m)*r*g0.w+t0.w;
    o1.x=(x1.x-m)*r*g1.x+t1.x; o1.y=(x1.y-m)*r*g1.y+t1.y;
    o1.z=(x1.z-m)*r*g1.z+t1.z; o1.w=(x1.w-m)*r*g1.w+t1.w;
    R[lane] = o0; R[lane+32] = o1;
}

// ---------------- Q = LN(sum_s Gp[s,id_s] + dir'): warp per row -------------
__global__ void k_q(const int* __restrict__ idl, const int* __restrict__ idr,
                    const float* __restrict__ gamma, const float* __restrict__ beta){
    int gw = blockIdx.x*8 + (threadIdx.x>>5);   // 0..16383
    int dir = gw >> 13;
    int bl  = gw & 8191;
    int lane = threadIdx.x & 31;
    const int* ids = (dir ? idr : idl) + bl*Sc;
    int i0=ids[0], i1=ids[1], i2=ids[2], i3=ids[3], i4=ids[4];
    const float* Gp = dir ? &g_Gp[1][0] : &g_Gp[0][0];
    int d0 = lane*8;
    float4 a0, a1;
    {
        const float4* r0 = (const float4*)&Gp[(0*Vc+i0)*Dc + d0];
        const float4* r1 = (const float4*)&Gp[(1*Vc+i1)*Dc + d0];
        const float4* r2 = (const float4*)&Gp[(2*Vc+i2)*Dc + d0];
        const float4* r3 = (const float4*)&Gp[(3*Vc+i3)*Dc + d0];
        const float4* r4 = (const float4*)&Gp[(4*Vc+i4)*Dc + d0];
        const float4* db = (const float4*)&g_dirb[dir][d0];
        float4 v0 = db[0], v1 = db[1];
        float4 t;
        t=r0[0]; v0.x+=t.x; v0.y+=t.y; v0.z+=t.z; v0.w+=t.w;
        t=r0[1]; v1.x+=t.x; v1.y+=t.y; v1.z+=t.z; v1.w+=t.w;
        t=r1[0]; v0.x+=t.x; v0.y+=t.y; v0.z+=t.z; v0.w+=t.w;
        t=r1[1]; v1.x+=t.x; v1.y+=t.y; v1.z+=t.z; v1.w+=t.w;
        t=r2[0]; v0.x+=t.x; v0.y+=t.y; v0.z+=t.z; v0.w+=t.w;
        t=r2[1]; v1.x+=t.x; v1.y+=t.y; v1.z+=t.z; v1.w+=t.w;
        t=r3[0]; v0.x+=t.x; v0.y+=t.y; v0.z+=t.z; v0.w+=t.w;
        t=r3[1]; v1.x+=t.x; v1.y+=t.y; v1.z+=t.z; v1.w+=t.w;
        t=r4[0]; v0.x+=t.x; v0.y+=t.y; v0.z+=t.z; v0.w+=t.w;
        t=r4[1]; v1.x+=t.x; v1.y+=t.y; v1.z+=t.z; v1.w+=t.w;
        a0 = v0; a1 = v1;
    }
    float s  = a0.x+a0.y+a0.z+a0.w + a1.x+a1.y+a1.z+a1.w;
    float s2 = a0.x*a0.x+a0.y*a0.y+a0.z*a0.z+a0.w*a0.w
             + a1.x*a1.x+a1.y*a1.y+a1.z*a1.z+a1.w*a1.w;
    s = warpSum(s); s2 = warpSum(s2);
    float m = s*(1.f/256.f);
    float r = rsqrtf(s2*(1.f/256.f) - m*m + 1e-5f);
    const float4* G4 = (const float4*)&gamma[d0];
    const float4* T4 = (const float4*)&beta[d0];
    float4 g0=G4[0], g1=G4[1], t0=T4[0], t1=T4[1];
    float4 o0, o1;
    o0.x=(a0.x-m)*r*g0.x+t0.x; o0.y=(a0.y-m)*r*g0.y+t0.y;
    o0.z=(a0.z-m)*r*g0.z+t0.z; o0.w=(a0.w-m)*r*g0.w+t0.w;
    o1.x=(a1.x-m)*r*g1.x+t1.x; o1.y=(a1.y-m)*r*g1.y+t1.y;
    o1.z=(a1.z-m)*r*g1.z+t1.z; o1.w=(a1.w-m)*r*g1.w+t1.w;
    float4* Q4 = (float4*)&g_Q[dir][bl*Dc + d0];
    Q4[0] = o0; Q4[1] = o1;
}

// ---------------- flash attention: both dirs in one 512-thread CTA ----------
// K/V/M staged ONCE per (b,lt,hp); warp = (dir, head, quarter).
// Pads: K/P = 36 (conflict-free fragment LDS), V/M = 40.
#define LDK 36
#define LDV 40
#define LDM 40
#define LDP 36
__global__ void __launch_bounds__(512,1) k_attn(const float* __restrict__ mask,
                                                const float* __restrict__ tau_p){
    extern __shared__ float sm[];
    float* Ksm = sm;                         // [2][32][36]
    float* Vsm = Ksm + 2*32*LDK;             // [2][32][40]
    float* Msm = Vsm + 2*32*LDV;             // [128][40]
    float* Psm = Msm + 128*LDM;              // [4][128][36]  (dir*2+head)
    int lt = blockIdx.x >> 2, hp = blockIdx.x & 3;
    int b = blockIdx.y;
    int l0 = lt*128;
    int t = threadIdx.x, wid = t>>5, lane = t&31;
    int dir = wid>>3, hh = (wid>>2)&1, wr = wid&3;
    int lq = lane>>2, lr = lane&3;
    float tau = fminf(fmaxf(tau_p[0],0.25f),4.f);
    float kscale = 1.44269504f/(5.656854249f*tau);

    // stage Q for all 4 (dir,head) slots into Psm
    for (int i=t; i<4096; i+=512){
        int slot = i>>10, row = (i>>3)&127, c4 = i&7;
        int qd = slot>>1, qh = slot&1;
        const float* Qb = (qd ? g_Q[1] : g_Q[0]) + (long)(b*Lc + l0 + row)*Dc + (hp*2+qh)*32;
        *(float4*)&Psm[(slot*128 + row)*LDP + c4*4] = *(const float4*)&Qb[c4*4];
    }
    __syncthreads();
    uint32_t qa[2][4][4];
    {
        const float* Qh = Psm + (dir*2+hh)*128*LDP;
#pragma unroll
        for (int mi=0;mi<2;mi++)
#pragma unroll
        for (int k8=0;k8<4;k8++){
            int r = wr*32 + mi*16 + lq, c = k8*8 + lr;
            qa[mi][k8][0] = f2tf_u(Qh[r*LDP + c]);
            qa[mi][k8][1] = f2tf_u(Qh[(r+8)*LDP + c]);
            qa[mi][k8][2] = f2tf_u(Qh[r*LDP + c+4]);
            qa[mi][k8][3] = f2tf_u(Qh[(r+8)*LDP + c+4]);
        }
    }
    float o[2][4][4];
#pragma unroll
    for (int mi=0;mi<2;mi++)
#pragma unroll
        for (int ni=0;ni<4;ni++)
#pragma unroll
            for (int e=0;e<4;e++) o[mi][ni][e]=0.f;
    float lsum[4] = {0.f,0.f,0.f,0.f};

    const float* Kg = g_K  + (long)(b*Nc)*Dc + hp*64;
    const float* Vg = g_Vm + (long)(b*Nc)*Dc + hp*64;
    const float* Mg = mask + (long)(b*Lc + l0)*Nc;
    float* Ph = Psm + (dir*2+hh)*128*LDP;

    // staging decomposition: 512 threads, 1 K/V float4 item + 2 M items each
    int s_hh = t>>8, s_n = (t>>3)&31, s_c4 = t&7;
    float4 pk, pv, pm[2];
    pk = *(const float4*)&Kg[(long)s_n*Dc + s_hh*32 + s_c4*4];
    pv = *(const float4*)&Vg[(long)s_n*Dc + s_hh*32 + s_c4*4];
#pragma unroll
    for (int u=0;u<2;u++){
        int i = t + u*512, row = i>>3, c4 = i&7;
        pm[u] = *(const float4*)&Mg[(long)row*Nc + c4*4];
    }

    for (int n0=0; n0<Nc; n0+=32){
        __syncthreads();
        {
            float* d = &Ksm[(s_hh*32+s_n)*LDK + s_c4*4];
            float4 kk;
            kk.x=f2tf(pk.x*kscale); kk.y=f2tf(pk.y*kscale);
            kk.z=f2tf(pk.z*kscale); kk.w=f2tf(pk.w*kscale);
            *(float4*)d = kk;
            float* dv = &Vsm[(s_hh*32+s_n)*LDV + s_c4*4];
            float4 vv;
            vv.x=f2tf(pv.x); vv.y=f2tf(pv.y); vv.z=f2tf(pv.z); vv.w=f2tf(pv.w);
            *(float4*)dv = vv;
        }
#pragma unroll
        for (int u=0;u<2;u++){
            int i = t + u*512, row = i>>3, c4 = i&7;
            *(float4*)&Msm[row*LDM + c4*4] = pm[u];
        }
        if (n0 + 32 < Nc){
            pk = *(const float4*)&Kg[(long)(n0+32+s_n)*Dc + s_hh*32 + s_c4*4];
            pv = *(const float4*)&Vg[(long)(n0+32+s_n)*Dc + s_hh*32 + s_c4*4];
#pragma unroll
            for (int u=0;u<2;u++){
                int i = t + u*512, row = i>>3, c4 = i&7;
                pm[u] = *(const float4*)&Mg[(long)row*Nc + n0+32 + c4*4];
            }
        }
        __syncthreads();

        float sc[2][4][4];
#pragma unroll
        for (int mi=0;mi<2;mi++)
#pragma unroll
            for (int ni=0;ni<4;ni++)
#pragma unroll
                for (int e=0;e<4;e++) sc[mi][ni][e]=0.f;
        const float* Kh = Ksm + hh*32*LDK;
#pragma unroll
        for (int k8=0;k8<4;k8++){
            uint32_t bf[4][2];
#pragma unroll
            for (int ni=0;ni<4;ni++){
                bf[ni][0] = __float_as_uint(Kh[(ni*8+lq)*LDK + k8*8 + lr]);
                bf[ni][1] = __float_as_uint(Kh[(ni*8+lq)*LDK + k8*8 + lr + 4]);
            }
#pragma unroll
            for (int mi=0;mi<2;mi++)
#pragma unroll
                for (int ni=0;ni<4;ni++)
                    mma_tf32(sc[mi][ni], qa[mi][k8], bf[ni]);
        }
#pragma unroll
        for (int mi=0;mi<2;mi++)
#pragma unroll
        for (int half=0;half<2;half++){
            int q = mi*2+half;
            int row = wr*32 + mi*16 + half*8 + lq;
            float ls = 0.f;
#pragma unroll
            for (int ni=0;ni<4;ni++){
                float2 mm = *(const float2*)&Msm[row*LDM + ni*8 + 2*lr];
                float p0 = f2tf(exp2f(sc[mi][ni][half*2]   * mm.x));
                float p1 = f2tf(exp2f(sc[mi][ni][half*2+1] * mm.y));
                ls += p0 + p1;
                float2 pp; pp.x = p0; pp.y = p1;
                *(float2*)&Ph[row*LDP + ni*8 + 2*lr] = pp;
            }
            ls += __shfl_xor_sync(0xffffffffu, ls, 1);
            ls += __shfl_xor_sync(0xffffffffu, ls, 2);
            lsum[q] += ls;
        }
        __syncwarp();
        const float* Vh = Vsm + hh*32*LDV;
#pragma unroll
        for (int k8=0;k8<4;k8++){
            uint32_t pafr[2][4];
#pragma unroll
            for (int mi=0;mi<2;mi++){
                int r = wr*32 + mi*16 + lq, c = k8*8+lr;
                pafr[mi][0] = __float_as_uint(Ph[r*LDP + c]);
                pafr[mi][1] = __float_as_uint(Ph[(r+8)*LDP + c]);
                pafr[mi][2] = __float_as_uint(Ph[r*LDP + c+4]);
                pafr[mi][3] = __float_as_uint(Ph[(r+8)*LDP + c+4]);
            }
            uint32_t vbf[4][2];
#pragma unroll
            for (int ni=0;ni<4;ni++){
                vbf[ni][0] = __float_as_uint(Vh[(k8*8+lr)*LDV + ni*8 + lq]);
                vbf[ni][1] = __float_as_uint(Vh[(k8*8+lr+4)*LDV + ni*8 + lq]);
            }
#pragma unroll
            for (int mi=0;mi<2;mi++)
#pragma unroll
                for (int ni=0;ni<4;ni++)
                    mma_tf32(o[mi][ni], pafr[mi], vbf[ni]);
        }
    }
    float* Fg = (dir ? g_F[1] : g_F[0]) + (long)(b*Lc + l0)*Dc + (hp*2+hh)*32;
#pragma unroll
    for (int mi=0;mi<2;mi++)
#pragma unroll
    for (int half=0;half<2;half++){
        int q = mi*2+half;
        int row = wr*32 + mi*16 + half*8 + lq;
        float inv = 1.f/lsum[q];
#pragma unroll
        for (int ni=0;ni<4;ni++){
            float2 oo;
            oo.x = o[mi][ni][half*2]*inv;
            oo.y = o[mi][ni][half*2+1]*inv;
            *(float2*)&Fg[(long)row*Dc + ni*8 + 2*lr] = oo;
        }
    }
}

// ---------------- agreement loss: warp per (b,l) ----------------------------
__global__ void k_loss(const float* __restrict__ out, const float* __restrict__ tmask){
    int gw = blockIdx.x*8 + (threadIdx.x>>5);
    if (gw >= (Lc-1)*Bc) return;
    int l = gw % (Lc-1), b = gw / (Lc-1);
    int lane = threadIdx.x & 31;
    const float* rl = out + 1 + (long)(b*Lc + l)*Vc;
    const float* rr = out + 1 + (long)Bc*Lc*Vc + (long)(b*Lc + l + 1)*Vc;
    float xl[16], xr[16];
    float ml = -1e30f, mr = -1e30f;
#pragma unroll
    for (int u=0;u<16;u++){
        xl[u] = rl[lane + u*32]*0.5f;
        xr[u] = rr[lane + u*32]*0.5f;
        ml = fmaxf(ml, xl[u]); mr = fmaxf(mr, xr[u]);
    }
    ml = warpMax(ml); mr = warpMax(mr);
    float el[16], er[16], sl = 0.f, sr = 0.f;
#pragma unroll
    for (int u=0;u<16;u++){
        el[u] = __expf(xl[u]-ml); sl += el[u];
        er[u] = __expf(xr[u]-mr); sr += er[u];
    }
    sl = warpSum(sl); sr = warpSum(sr);
    float isl = 1.f/sl, isr = 1.f/sr;
    float agree = 0.f;
#pragma unroll
    for (int u=0;u<16;u++){
        float d = el[u]*isl - er[u]*isr;
        agree += d*d;
    }
    agree = warpSum(agree);
    if (lane == 0) atomicAdd(&g_num, agree * tmask[b*Lc + l]);
}

__global__ void k_final(const float* __restrict__ tmask, float* __restrict__ out){
    __shared__ float red[32];
    float s = 0.f;
    for (int e=threadIdx.x; e<Bc*Lc; e+=256){
        int l = e % Lc;
        if (l < Lc-1) s += tmask[e];
    }
    s = blockSum(s, red);
    if (threadIdx.x == 0){
        float den = fmaxf(s, 1.0f);
        out[0] = 0.1f * g_num / den;
    }
}

// ---------------- launch ----------------------------------------------------
extern "C" void kernel_launch(void* const* d_in, const int* in_sizes, int n_in,
                              void* d_out, int out_size){
    const float* vis   = (const float*)d_in[0];
    const int*   idl   = (const int*)  d_in[1];
    const int*   idr   = (const int*)  d_in[2];
    const float* tmask = (const float*)d_in[4];
    const float* vmask = (const float*)d_in[5];
    const float* emb   = (const float*)d_in[6];
    const float* dl    = (const float*)d_in[7];
    const float* dr    = (const float*)d_in[8];
    const float* pw    = (const float*)d_in[9];
    const float* pb    = (const float*)d_in[10];
    const float* qg    = (const float*)d_in[11];
    const float* qb    = (const float*)d_in[12];
    const float* kw    = (const float*)d_in[13];
    const float* kb    = (const float*)d_in[14];
    const float* vw    = (const float*)d_in[15];
    const float* vb    = (const float*)d_in[16];
    const float* kvg   = (const float*)d_in[17];
    const float* kvb   = (const float*)d_in[18];
    const float* tau   = (const float*)d_in[19];
    const float* clsb  = (const float*)d_in[20];
    const float* cwl   = (const float*)d_in[21];
    const float* cwr   = (const float*)d_in[22];
    float* out = (float*)d_out;

    const int SM_GEMM = GSM_FLOATS*4;
    const int SM_ATTN = (2*32*LDK + 2*32*LDV + 128*LDM + 4*128*LDP)*4;  // 113664
    static bool init_done = false;
    static cudaStream_t s1;
    static cudaEvent_t e0, e1;
    if (!init_done){
        cudaFuncSetAttribute(k_gemm, cudaFuncAttributeMaxDynamicSharedMemorySize, SM_GEMM);
        cudaFuncSetAttribute(k_attn, cudaFuncAttributeMaxDynamicSharedMemorySize, SM_ATTN);
        cudaStreamCreateWithFlags(&s1, cudaStreamNonBlocking);
        cudaEventCreateWithFlags(&e0, cudaEventDisableTiming);
        cudaEventCreateWithFlags(&e1, cudaEventDisableTiming);
        init_done = true;
    }

    cudaEventRecord(e0, 0);
    cudaStreamWaitEvent(s1, e0, 0);
    k_gemm<<<dim3(256,2,2), 256, SM_GEMM, s1>>>(0, vis, kw, vw, nullptr, nullptr);
    k_ln<<<dim3(4096,2), 256, 0, s1>>>(kb, vb, kvg, kvb);
    cudaEventRecord(e1, s1);

    k_w3dirb<<<dim3(2624,2), 256>>>(cwl, cwr, dl, dr, pw, pb);
    k_gemm<<<dim3(2,2,10), 256, SM_GEMM>>>(1, pw, nullptr, nullptr, nullptr, nullptr);
    k_gemm<<<dim3(4,2,10), 256, SM_GEMM>>>(2, emb, nullptr, nullptr, nullptr, nullptr);
    k_q<<<2048, 256>>>(idl, idr, qg, qb);

    cudaStreamWaitEvent(0, e1, 0);
    k_attn<<<dim3(8,32), 512, SM_ATTN>>>(vmask, tau);
    k_gemm<<<dim3(64,4,2), 256, SM_GEMM>>>(3, nullptr, emb, nullptr, clsb, out);
    k_loss<<<1020, 256>>>(out, tmask);
    k_final<<<1, 256>>>(tmask, out);
}

// round 14
// speedup vs baseline: 4.3557x; 1.2299x over previous
#include <cuda_runtime.h>
#include <cuda_fp16.h>
#include <cstdint>
#include <math.h>
#include <mma.h>
using namespace nvcuda;

#define Bc  32
#define Lc  256
#define Sc  5
#define Nc  1024
#define Dc  256
#define Vc  512
#define Hc  8
#define DHc 32

// ---------------- scratch ----------------
__device__ float g_W3T[2][Sc*Dc*Dc];
__device__ float g_M[10*Dc*Dc];
__device__ float g_Gp[2][Sc*Vc*Dc];
__device__ float g_dirb[2][Dc];
__device__ float g_Q[2][Bc*Lc*Dc];
__device__ float g_K[Bc*Nc*Dc];
__device__ float g_Vm[Bc*Nc*Dc];
__device__ float g_F[2][Bc*Lc*Dc];
__device__ float g_num;

// ---------------- helpers ----------------
__device__ __forceinline__ float warpSum(float v){
#pragma unroll
    for (int o=16;o>0;o>>=1) v += __shfl_xor_sync(0xffffffffu, v, o);
    return v;
}
__device__ __forceinline__ float warpMax(float v){
#pragma unroll
    for (int o=16;o>0;o>>=1) v = fmaxf(v, __shfl_xor_sync(0xffffffffu, v, o));
    return v;
}
__device__ __forceinline__ float blockSum(float v, float* red){
    v = warpSum(v);
    int w = threadIdx.x >> 5;
    __syncthreads();
    if ((threadIdx.x & 31) == 0) red[w] = v;
    __syncthreads();
    if (w == 0){
        float r = (threadIdx.x < 8) ? red[threadIdx.x] : 0.f;
        r = warpSum(r);
        if (threadIdx.x == 0) red[0] = r;
    }
    __syncthreads();
    return red[0];
}
__device__ __forceinline__ float f2tf(float x){
    uint32_t u; asm("cvt.rna.tf32.f32 %0, %1;" : "=r"(u) : "f"(x));
    return __uint_as_float(u);
}
__device__ __forceinline__ uint32_t h2pack(float lo, float hi){
    __half2 h = __floats2half2_rn(lo, hi);
    uint32_t u; memcpy(&u, &h, 4);
    return u;
}
__device__ __forceinline__ void mma_tf32(float* c, const uint32_t* a, const uint32_t* b){
    asm volatile("mma.sync.aligned.m16n8k8.row.col.f32.tf32.tf32.f32 "
        "{%0,%1,%2,%3}, {%4,%5,%6,%7}, {%8,%9}, {%0,%1,%2,%3};"
        : "+f"(c[0]),"+f"(c[1]),"+f"(c[2]),"+f"(c[3])
        : "r"(a[0]),"r"(a[1]),"r"(a[2]),"r"(a[3]), "r"(b[0]),"r"(b[1]));
}
__device__ __forceinline__ void mma_f16(float* c, const uint32_t* a, const uint32_t* b){
    asm volatile("mma.sync.aligned.m16n8k16.row.col.f32.f16.f16.f32 "
        "{%0,%1,%2,%3}, {%4,%5,%6,%7}, {%8,%9}, {%0,%1,%2,%3};"
        : "+f"(c[0]),"+f"(c[1]),"+f"(c[2]),"+f"(c[3])
        : "r"(a[0]),"r"(a[1]),"r"(a[2]),"r"(a[3]), "r"(b[0]),"r"(b[1]));
}

// ---------------- k1: W3^T fold + dirb + zero, merged -----------------------
__global__ void k_w3dirb(const float* __restrict__ wl, const float* __restrict__ wr,
                         const float* __restrict__ dl, const float* __restrict__ dr,
                         const float* __restrict__ P, const float* __restrict__ pb){
    if (blockIdx.x == 0 && blockIdx.y == 0 && threadIdx.x == 0) g_num = 0.f;
    if (blockIdx.x < 2560){
        int dir = blockIdx.y;
        const float* w = dir ? wr : wl;
        int idx = blockIdx.x*256 + threadIdx.x;
        int dt = idx & 255;
        int sj = idx >> 8;
        int s = sj / 256, j = sj % 256;
        float v = 0.f;
#pragma unroll
        for (int k=0;k<5;k++){
            int f = dt + 256*k;
            int o = f/5, sk = f%5;
            int tp = s - sk + 1;
            if (tp >= 0 && tp < 3) v += w[(o*Dc + j)*3 + tp];
        }
        g_W3T[dir][(s*Dc + j)*Dc + dt] = 0.2f*v;
    } else if (blockIdx.y == 0){
        int gw = (blockIdx.x-2560)*8 + (threadIdx.x>>5);
        int dir = gw >> 8, d = gw & 255;
        int lane = threadIdx.x & 31;
        const float* dv = dir ? dr : dl;
        const float4* P4 = (const float4*)(P + d*Dc);
        const float4* D4 = (const float4*)dv;
        float4 p0 = P4[lane], q0 = D4[lane];
        float4 p1 = P4[lane+32], q1 = D4[lane+32];
        float s = p0.x*q0.x + p0.y*q0.y + p0.z*q0.z + p0.w*q0.w
                + p1.x*q1.x + p1.y*q1.y + p1.z*q1.z + p1.w*q1.w;
        s = warpSum(s);
        if (lane == 0) g_dirb[dir][d] = s + pb[d];
    }
}

// ---------------- generic tf32 GEMM, double-buffered smem -------------------
#define GSM_FLOATS (4*5120)
__global__ void __launch_bounds__(256,2) k_gemm(int mode,
        const float* __restrict__ A, const float* __restrict__ B0,
        const float* __restrict__ B1, const float* __restrict__ bias,
        float* __restrict__ Cext){
    extern __shared__ float smem[];
    int z = blockIdx.z;
    const float* Ap; const float* Bp; float* Cp;
    int ldb, ldc;
    if (mode==0){
        Ap = A; Bp = z ? B1 : B0; ldb = 256;
        Cp = z ? &g_Vm[0] : &g_K[0]; ldc = 256;
    } else if (mode==1){
        Ap = A;
        Bp = &g_W3T[0][0] + (long)z*65536; ldb = 256;
        Cp = &g_M[0] + (long)z*65536; ldc = 256;
    } else if (mode==2){
        Ap = A;
        Bp = &g_M[0] + (long)z*65536; ldb = 256;
        Cp = &g_Gp[0][0] + (long)(z/5)*655360 + (long)(z%5)*131072; ldc = 256;
    } else {
        Ap = &g_F[0][0] + (long)z*8192*256;
        Bp = B0; ldb = 256;
        Cp = Cext + 1 + (long)z*8192*512; ldc = 512;
    }
    int row0 = blockIdx.x*128, col0 = blockIdx.y*128;
    int t = threadIdx.x, wid = t>>5, lane = t&31;
    int wm = wid>>2, wn = wid&3;

    wmma::fragment<wmma::accumulator,16,16,8,float> acc[4][2];
#pragma unroll
    for (int mi=0;mi<4;mi++)
#pragma unroll
        for (int ni=0;ni<2;ni++) wmma::fill_fragment(acc[mi][ni], 0.f);

    int r8 = t>>3, c8 = (t&7)*4;
    const float* Ag = &Ap[(long)(row0+r8)*256 + c8];
    const float* Bg = &Bp[(long)(col0+r8)*ldb + c8];

    float4 pa[4], pb[4];
#pragma unroll
    for (int u=0;u<4;u++){
        pa[u] = *(const float4*)(Ag + (long)(u*32)*256);
        pb[u] = *(const float4*)(Bg + (long)(u*32)*ldb);
    }
    {
        float* Ad = smem + r8*40 + c8;
        float* Bd = smem + 5120 + r8*40 + c8;
#pragma unroll
        for (int u=0;u<4;u++){
            Ad[u*32*40+0]=f2tf(pa[u].x); Ad[u*32*40+1]=f2tf(pa[u].y);
            Ad[u*32*40+2]=f2tf(pa[u].z); Ad[u*32*40+3]=f2tf(pa[u].w);
            Bd[u*32*40+0]=f2tf(pb[u].x); Bd[u*32*40+1]=f2tf(pb[u].y);
            Bd[u*32*40+2]=f2tf(pb[u].z); Bd[u*32*40+3]=f2tf(pb[u].w);
        }
    }

    for (int kb8=0; kb8<8; kb8++){
        __syncthreads();
        if (kb8 < 7){
            int off = (kb8+1)*32;
#pragma unroll
            for (int u=0;u<4;u++){
                pa[u] = *(const float4*)(Ag + (long)(u*32)*256 + off);
                pb[u] = *(const float4*)(Bg + (long)(u*32)*ldb + off);
            }
        }
        const float* Asb = smem + (kb8&1)*10240;
        const float* Bsb = smem + 5120 + (kb8&1)*10240;
#pragma unroll
        for (int k8=0;k8<4;k8++){
            wmma::fragment<wmma::matrix_a,16,16,8,wmma::precision::tf32,wmma::row_major> af[4];
            wmma::fragment<wmma::matrix_b,16,16,8,wmma::precision::tf32,wmma::col_major> bf[2];
#pragma unroll
            for (int mi=0;mi<4;mi++)
                wmma::load_matrix_sync(af[mi], Asb + (wm*64 + mi*16)*40 + k8*8, 40);
#pragma unroll
            for (int ni=0;ni<2;ni++)
                wmma::load_matrix_sync(bf[ni], Bsb + (wn*32 + ni*16)*40 + k8*8, 40);
#pragma unroll
            for (int mi=0;mi<4;mi++)
#pragma unroll
                for (int ni=0;ni<2;ni++)
                    wmma::mma_sync(acc[mi][ni], af[mi], bf[ni], acc[mi][ni]);
        }
        if (kb8 < 7){
            float* Ad = smem + ((kb8+1)&1)*10240 + r8*40 + c8;
            float* Bd = smem + 5120 + ((kb8+1)&1)*10240 + r8*40 + c8;
#pragma unroll
            for (int u=0;u<4;u++){
                Ad[u*32*40+0]=f2tf(pa[u].x); Ad[u*32*40+1]=f2tf(pa[u].y);
                Ad[u*32*40+2]=f2tf(pa[u].z); Ad[u*32*40+3]=f2tf(pa[u].w);
                Bd[u*32*40+0]=f2tf(pb[u].x); Bd[u*32*40+1]=f2tf(pb[u].y);
                Bd[u*32*40+2]=f2tf(pb[u].z); Bd[u*32*40+3]=f2tf(pb[u].w);
            }
        }
    }
    if (mode != 3){
#pragma unroll
        for (int mi=0;mi<4;mi++)
#pragma unroll
            for (int ni=0;ni<2;ni++)
                wmma::store_matrix_sync(&Cp[(long)(row0+wm*64+mi*16)*ldc + col0 + wn*32 + ni*16],
                                        acc[mi][ni], ldc, wmma::mem_row_major);
    } else {
        __syncthreads();
        float* stage = smem + wid*(16*18);
#pragma unroll
        for (int mi=0;mi<4;mi++)
#pragma unroll
            for (int ni=0;ni<2;ni++){
                wmma::store_matrix_sync(stage, acc[mi][ni], 18, wmma::mem_row_major);
                __syncwarp();
                for (int e=lane; e<256; e+=32){
                    int r = e>>4, c = e&15;
                    int col = col0 + wn*32 + ni*16 + c;
                    Cp[(long)(row0+wm*64+mi*16+r)*ldc + col] = stage[r*18+c] + bias[col];
                }
                __syncwarp();
            }
    }
}

// ---------------- LN (+bias) in place on g_K / g_Vm -------------------------
__global__ void k_ln(const float* __restrict__ kb, const float* __restrict__ vb,
                     const float* __restrict__ gamma, const float* __restrict__ beta){
    int z = blockIdx.y;
    float* X = z ? &g_Vm[0] : &g_K[0];
    const float* bias = z ? vb : kb;
    int wid = threadIdx.x>>5, lane = threadIdx.x&31;
    long row = (long)blockIdx.x*8 + wid;
    float4* R = (float4*)(X + row*256);
    const float4* B4 = (const float4*)bias;
    const float4* G4 = (const float4*)gamma;
    const float4* T4 = (const float4*)beta;
    float4 x0 = R[lane], x1 = R[lane+32];
    float4 b0 = B4[lane], b1 = B4[lane+32];
    x0.x+=b0.x; x0.y+=b0.y; x0.z+=b0.z; x0.w+=b0.w;
    x1.x+=b1.x; x1.y+=b1.y; x1.z+=b1.z; x1.w+=b1.w;
    float s  = x0.x+x0.y+x0.z+x0.w + x1.x+x1.y+x1.z+x1.w;
    float s2 = x0.x*x0.x+x0.y*x0.y+x0.z*x0.z+x0.w*x0.w
             + x1.x*x1.x+x1.y*x1.y+x1.z*x1.z+x1.w*x1.w;
    s = warpSum(s); s2 = warpSum(s2);
    float m = s*(1.f/256.f);
    float r = rsqrtf(s2*(1.f/256.f) - m*m + 1e-5f);
    float4 g0 = G4[lane], g1 = G4[lane+32];
    float4 t0 = T4[lane], t1 = T4[lane+32];
    float4 o0, o1;
    o0.x=(x0.x-m)*r*g0.x+t0.x; o0.y=(x0.y-m)*r*g0.y+t0.y;
    o0.z=(x0.z-m)*r*g0.z+t0.z; o0.w=(x0.w-m)*r*g0.w+t0.w;
    o1.x=(x1.x-m)*r*g1.x+t1.x; o1.y=(x1.y-m)*r*g1.y+t1.y;
    o1.z=(x1.z-m)*r*g1.z+t1.z; o1.w=(x1.w-m)*r*g1.w+t1.w;
    R[lane] = o0; R[lane+32] = o1;
}

// ---------------- Q = LN(sum_s Gp[s,id_s] + dir'): warp per row -------------
__global__ void k_q(const int* __restrict__ idl, const int* __restrict__ idr,
                    const float* __restrict__ gamma, const float* __restrict__ beta){
    int gw = blockIdx.x*8 + (threadIdx.x>>5);
    int dir = gw >> 13;
    int bl  = gw & 8191;
    int lane = threadIdx.x & 31;
    const int* ids = (dir ? idr : idl) + bl*Sc;
    int i0=ids[0], i1=ids[1], i2=ids[2], i3=ids[3], i4=ids[4];
    const float* Gp = dir ? &g_Gp[1][0] : &g_Gp[0][0];
    int d0 = lane*8;
    float4 a0, a1;
    {
        const float4* r0 = (const float4*)&Gp[(0*Vc+i0)*Dc + d0];
        const float4* r1 = (const float4*)&Gp[(1*Vc+i1)*Dc + d0];
        const float4* r2 = (const float4*)&Gp[(2*Vc+i2)*Dc + d0];
        const float4* r3 = (const float4*)&Gp[(3*Vc+i3)*Dc + d0];
        const float4* r4 = (const float4*)&Gp[(4*Vc+i4)*Dc + d0];
        const float4* db = (const float4*)&g_dirb[dir][d0];
        float4 v0 = db[0], v1 = db[1];
        float4 t;
        t=r0[0]; v0.x+=t.x; v0.y+=t.y; v0.z+=t.z; v0.w+=t.w;
        t=r0[1]; v1.x+=t.x; v1.y+=t.y; v1.z+=t.z; v1.w+=t.w;
        t=r1[0]; v0.x+=t.x; v0.y+=t.y; v0.z+=t.z; v0.w+=t.w;
        t=r1[1]; v1.x+=t.x; v1.y+=t.y; v1.z+=t.z; v1.w+=t.w;
        t=r2[0]; v0.x+=t.x; v0.y+=t.y; v0.z+=t.z; v0.w+=t.w;
        t=r2[1]; v1.x+=t.x; v1.y+=t.y; v1.z+=t.z; v1.w+=t.w;
        t=r3[0]; v0.x+=t.x; v0.y+=t.y; v0.z+=t.z; v0.w+=t.w;
        t=r3[1]; v1.x+=t.x; v1.y+=t.y; v1.z+=t.z; v1.w+=t.w;
        t=r4[0]; v0.x+=t.x; v0.y+=t.y; v0.z+=t.z; v0.w+=t.w;
        t=r4[1]; v1.x+=t.x; v1.y+=t.y; v1.z+=t.z; v1.w+=t.w;
        a0 = v0; a1 = v1;
    }
    float s  = a0.x+a0.y+a0.z+a0.w + a1.x+a1.y+a1.z+a1.w;
    float s2 = a0.x*a0.x+a0.y*a0.y+a0.z*a0.z+a0.w*a0.w
             + a1.x*a1.x+a1.y*a1.y+a1.z*a1.z+a1.w*a1.w;
    s = warpSum(s); s2 = warpSum(s2);
    float m = s*(1.f/256.f);
    float r = rsqrtf(s2*(1.f/256.f) - m*m + 1e-5f);
    const float4* G4 = (const float4*)&gamma[d0];
    const float4* T4 = (const float4*)&beta[d0];
    float4 g0=G4[0], g1=G4[1], t0=T4[0], t1=T4[1];
    float4 o0, o1;
    o0.x=(a0.x-m)*r*g0.x+t0.x; o0.y=(a0.y-m)*r*g0.y+t0.y;
    o0.z=(a0.z-m)*r*g0.z+t0.z; o0.w=(a0.w-m)*r*g0.w+t0.w;
    o1.x=(a1.x-m)*r*g1.x+t1.x; o1.y=(a1.y-m)*r*g1.y+t1.y;
    o1.z=(a1.z-m)*r*g1.z+t1.z; o1.w=(a1.w-m)*r*g1.w+t1.w;
    float4* Q4 = (float4*)&g_Q[dir][bl*Dc + d0];
    Q4[0] = o0; Q4[1] = o1;
}

// ---------------- flash attention: fp16 mma m16n8k16, dual-dir CTA ----------
// smem (after 128x40 f32 mask):
//   Ksm32 [hh][n 32][dhp 16] stride 20 (half2 of dh pair)
//   Vp32  [hh][dh 32][np 16] stride 20 (half2 of n pair)
//   Psm32 [slot 4][row 128][16] stride 20 (Q then P, half2)
#define LDM 40
#define LDH 20
__global__ void __launch_bounds__(512,1) k_attn(const float* __restrict__ mask,
                                                const float* __restrict__ tau_p){
    extern __shared__ float sm[];
    float*    Msm   = sm;                       // 128*40 floats
    uint32_t* Ksm32 = (uint32_t*)(sm + 128*LDM);
    uint32_t* Vp32  = Ksm32 + 2*32*LDH;
    uint32_t* Psm32 = Vp32  + 2*32*LDH;
    int lt = blockIdx.x >> 2, hp = blockIdx.x & 3;
    int b = blockIdx.y;
    int l0 = lt*128;
    int t = threadIdx.x, wid = t>>5, lane = t&31;
    int dir = wid>>3, hh = (wid>>2)&1, wr = wid&3;
    int lq = lane>>2, lr = lane&3;
    float tau = fminf(fmaxf(tau_p[0],0.25f),4.f);
    float kscale = 1.44269504f/(5.656854249f*tau);

    // stage Q (fp16 pairs) for all 4 (dir,head) slots
    for (int u=0;u<8;u++){
        int i = t + u*512;                       // < 4096
        int slot = i>>10, row = (i>>3)&127, c4 = i&7;
        int qd = slot>>1, qh = slot&1;
        const float* Qb = (qd ? g_Q[1] : g_Q[0]) + (long)(b*Lc + l0 + row)*Dc + (hp*2+qh)*32;
        float4 q = *(const float4*)&Qb[c4*4];
        uint32_t* d = &Psm32[(slot*128 + row)*LDH + c4*2];
        d[0] = h2pack(q.x, q.y);
        d[1] = h2pack(q.z, q.w);
    }
    __syncthreads();
    uint32_t qa[2][2][4];                        // [mi][kstep]
    {
        const uint32_t* Qh = Psm32 + (dir*2+hh)*128*LDH;
#pragma unroll
        for (int mi=0;mi<2;mi++)
#pragma unroll
        for (int ks=0;ks<2;ks++){
            int r = wr*32 + mi*16 + lq;
            qa[mi][ks][0] = Qh[r*LDH + ks*8 + lr];
            qa[mi][ks][1] = Qh[(r+8)*LDH + ks*8 + lr];
            qa[mi][ks][2] = Qh[r*LDH + ks*8 + lr + 4];
            qa[mi][ks][3] = Qh[(r+8)*LDH + ks*8 + lr + 4];
        }
    }
    float o[2][4][4];
#pragma unroll
    for (int mi=0;mi<2;mi++)
#pragma unroll
        for (int ni=0;ni<4;ni++)
#pragma unroll
            for (int e=0;e<4;e++) o[mi][ni][e]=0.f;
    float lsum[4] = {0.f,0.f,0.f,0.f};

    const float* Kg = g_K  + (long)(b*Nc)*Dc + hp*64;
    const float* Vg = g_Vm + (long)(b*Nc)*Dc + hp*64;
    const float* Mg = mask + (long)(b*Lc + l0)*Nc;
    uint32_t* Ph = Psm32 + (dir*2+hh)*128*LDH;

    // staging decomposition
    int k_hh = t>>8, k_n = (t>>3)&31, k_c4 = t&7;          // K: all 512 threads
    int v_hh = 0, v_dq = 0, v_j = 0;                       // V: threads < 256
    if (t < 256){ v_hh = t>>7; v_dq = (t>>4)&7; v_j = t&15; }
    float4 pk, pv0, pv1, pm[2];
    pk = *(const float4*)&Kg[(long)k_n*Dc + k_hh*32 + k_c4*4];
    if (t < 256){
        pv0 = *(const float4*)&Vg[(long)(2*v_j  )*Dc + v_hh*32 + v_dq*4];
        pv1 = *(const float4*)&Vg[(long)(2*v_j+1)*Dc + v_hh*32 + v_dq*4];
    }
#pragma unroll
    for (int u=0;u<2;u++){
        int i = t + u*512, row = i>>3, c4 = i&7;
        pm[u] = *(const float4*)&Mg[(long)row*Nc + c4*4];
    }

    for (int n0=0; n0<Nc; n0+=32){
        __syncthreads();
        {   // K store: fp16 pairs, pre-scaled
            uint32_t* d = &Ksm32[(k_hh*32+k_n)*LDH + k_c4*2];
            d[0] = h2pack(pk.x*kscale, pk.y*kscale);
            d[1] = h2pack(pk.z*kscale, pk.w*kscale);
        }
        if (t < 256){   // V store: pairs across n at fixed dh
            uint32_t* base = &Vp32[(v_hh*32 + v_dq*4)*LDH + v_j];
            base[0*LDH] = h2pack(pv0.x, pv1.x);
            base[1*LDH] = h2pack(pv0.y, pv1.y);
            base[2*LDH] = h2pack(pv0.z, pv1.z);
            base[3*LDH] = h2pack(pv0.w, pv1.w);
        }
#pragma unroll
        for (int u=0;u<2;u++){
            int i = t + u*512, row = i>>3, c4 = i&7;
            *(float4*)&Msm[row*LDM + c4*4] = pm[u];
        }
        if (n0 + 32 < Nc){
            pk = *(const float4*)&Kg[(long)(n0+32+k_n)*Dc + k_hh*32 + k_c4*4];
            if (t < 256){
                pv0 = *(const float4*)&Vg[(long)(n0+32+2*v_j  )*Dc + v_hh*32 + v_dq*4];
                pv1 = *(const float4*)&Vg[(long)(n0+32+2*v_j+1)*Dc + v_hh*32 + v_dq*4];
            }
#pragma unroll
            for (int u=0;u<2;u++){
                int i = t + u*512, row = i>>3, c4 = i&7;
                pm[u] = *(const float4*)&Mg[(long)row*Nc + n0+32 + c4*4];
            }
        }
        __syncthreads();

        // S = Q K^T  (fp16 k16 × 2 ksteps over dh=32)
        float sc[2][4][4];
#pragma unroll
        for (int mi=0;mi<2;mi++)
#pragma unroll
            for (int ni=0;ni<4;ni++)
#pragma unroll
                for (int e=0;e<4;e++) sc[mi][ni][e]=0.f;
        const uint32_t* Kh = Ksm32 + hh*32*LDH;
#pragma unroll
        for (int ks=0;ks<2;ks++){
            uint32_t bf[4][2];
#pragma unroll
            for (int ni=0;ni<4;ni++){
                bf[ni][0] = Kh[(ni*8+lq)*LDH + ks*8 + lr];
                bf[ni][1] = Kh[(ni*8+lq)*LDH + ks*8 + lr + 4];
            }
#pragma unroll
            for (int mi=0;mi<2;mi++)
#pragma unroll
                for (int ni=0;ni<4;ni++)
                    mma_f16(sc[mi][ni], qa[mi][ks], bf[ni]);
        }
        // softmax (no max), P packed as half2 of adjacent n
#pragma unroll
        for (int mi=0;mi<2;mi++)
#pragma unroll
        for (int half=0;half<2;half++){
            int q = mi*2+half;
            int row = wr*32 + mi*16 + half*8 + lq;
            float ls = 0.f;
#pragma unroll
            for (int ni=0;ni<4;ni++){
                float2 mm = *(const float2*)&Msm[row*LDM + ni*8 + 2*lr];
                float p0 = exp2f(sc[mi][ni][half*2]   * mm.x);
                float p1 = exp2f(sc[mi][ni][half*2+1] * mm.y);
                __half2 hp2 = __floats2half2_rn(p0, p1);
                float2 pr = __half22float2(hp2);          // rounded values for lsum
                ls += pr.x + pr.y;
                uint32_t u; memcpy(&u, &hp2, 4);
                Ph[row*LDH + ni*4 + lr] = u;
            }
            ls += __shfl_xor_sync(0xffffffffu, ls, 1);
            ls += __shfl_xor_sync(0xffffffffu, ls, 2);
            lsum[q] += ls;
        }
        __syncwarp();
        // O += P V  (fp16 k16 × 2 ksteps over npos=32)
        const uint32_t* Vh = Vp32 + hh*32*LDH;
#pragma unroll
        for (int ks=0;ks<2;ks++){
            uint32_t pafr[2][4];
#pragma unroll
            for (int mi=0;mi<2;mi++){
                int r = wr*32 + mi*16 + lq;
                pafr[mi][0] = Ph[r*LDH + ks*8 + lr];
                pafr[mi][1] = Ph[(r+8)*LDH + ks*8 + lr];
                pafr[mi][2] = Ph[r*LDH + ks*8 + lr + 4];
                pafr[mi][3] = Ph[(r+8)*LDH + ks*8 + lr + 4];
            }
            uint32_t vbf[4][2];
#pragma unroll
            for (int ni=0;ni<4;ni++){
                vbf[ni][0] = Vh[(ni*8+lq)*LDH + ks*8 + lr];
                vbf[ni][1] = Vh[(ni*8+lq)*LDH + ks*8 + lr + 4];
            }
#pragma unroll
            for (int mi=0;mi<2;mi++)
#pragma unroll
                for (int ni=0;ni<4;ni++)
                    mma_f16(o[mi][ni], pafr[mi], vbf[ni]);
        }
    }
    float* Fg = (dir ? g_F[1] : g_F[0]) + (long)(b*Lc + l0)*Dc + (hp*2+hh)*32;
#pragma unroll
    for (int mi=0;mi<2;mi++)
#pragma unroll
    for (int half=0;half<2;half++){
        int q = mi*2+half;
        int row = wr*32 + mi*16 + half*8 + lq;
        float inv = 1.f/lsum[q];
#pragma unroll
        for (int ni=0;ni<4;ni++){
            float2 oo;
            oo.x = o[mi][ni][half*2]*inv;
            oo.y = o[mi][ni][half*2+1]*inv;
            *(float2*)&Fg[(long)row*Dc + ni*8 + 2*lr] = oo;
        }
    }
}

// ---------------- agreement loss: warp per (b,l) ----------------------------
__global__ void k_loss(const float* __restrict__ out, const float* __restrict__ tmask){
    int gw = blockIdx.x*8 + (threadIdx.x>>5);
    if (gw >= (Lc-1)*Bc) return;
    int l = gw % (Lc-1), b = gw / (Lc-1);
    int lane = threadIdx.x & 31;
    const float* rl = out + 1 + (long)(b*Lc + l)*Vc;
    const float* rr = out + 1 + (long)Bc*Lc*Vc + (long)(b*Lc + l + 1)*Vc;
    float xl[16], xr[16];
    float ml = -1e30f, mr = -1e30f;
#pragma unroll
    for (int u=0;u<16;u++){
        xl[u] = rl[lane + u*32]*0.5f;
        xr[u] = rr[lane + u*32]*0.5f;
        ml = fmaxf(ml, xl[u]); mr = fmaxf(mr, xr[u]);
    }
    ml = warpMax(ml); mr = warpMax(mr);
    float el[16], er[16], sl = 0.f, sr = 0.f;
#pragma unroll
    for (int u=0;u<16;u++){
        el[u] = __expf(xl[u]-ml); sl += el[u];
        er[u] = __expf(xr[u]-mr); sr += er[u];
    }
    sl = warpSum(sl); sr = warpSum(sr);
    float isl = 1.f/sl, isr = 1.f/sr;
    float agree = 0.f;
#pragma unroll
    for (int u=0;u<16;u++){
        float d = el[u]*isl - er[u]*isr;
        agree += d*d;
    }
    agree = warpSum(agree);
    if (lane == 0) atomicAdd(&g_num, agree * tmask[b*Lc + l]);
}

__global__ void k_final(const float* __restrict__ tmask, float* __restrict__ out){
    __shared__ float red[32];
    float s = 0.f;
    for (int e=threadIdx.x; e<Bc*Lc; e+=256){
        int l = e % Lc;
        if (l < Lc-1) s += tmask[e];
    }
    s = blockSum(s, red);
    if (threadIdx.x == 0){
        float den = fmaxf(s, 1.0f);
        out[0] = 0.1f * g_num / den;
    }
}

// ---------------- launch ----------------------------------------------------
extern "C" void kernel_launch(void* const* d_in, const int* in_sizes, int n_in,
                              void* d_out, int out_size){
    const float* vis   = (const float*)d_in[0];
    const int*   idl   = (const int*)  d_in[1];
    const int*   idr   = (const int*)  d_in[2];
    const float* tmask = (const float*)d_in[4];
    const float* vmask = (const float*)d_in[5];
    const float* emb   = (const float*)d_in[6];
    const float* dl    = (const float*)d_in[7];
    const float* dr    = (const float*)d_in[8];
    const float* pw    = (const float*)d_in[9];
    const float* pb    = (const float*)d_in[10];
    const float* qg    = (const float*)d_in[11];
    const float* qb    = (const float*)d_in[12];
    const float* kw    = (const float*)d_in[13];
    const float* kb    = (const float*)d_in[14];
    const float* vw    = (const float*)d_in[15];
    const float* vb    = (const float*)d_in[16];
    const float* kvg   = (const float*)d_in[17];
    const float* kvb   = (const float*)d_in[18];
    const float* tau   = (const float*)d_in[19];
    const float* clsb  = (const float*)d_in[20];
    const float* cwl   = (const float*)d_in[21];
    const float* cwr   = (const float*)d_in[22];
    float* out = (float*)d_out;

    const int SM_GEMM = GSM_FLOATS*4;
    const int SM_ATTN = 128*LDM*4 + (2*32*LDH + 2*32*LDH + 4*128*LDH)*4;  // 71680
    static bool init_done = false;
    static cudaStream_t s1;
    static cudaEvent_t e0, e1;
    if (!init_done){
        cudaFuncSetAttribute(k_gemm, cudaFuncAttributeMaxDynamicSharedMemorySize, SM_GEMM);
        cudaFuncSetAttribute(k_attn, cudaFuncAttributeMaxDynamicSharedMemorySize, SM_ATTN);
        cudaStreamCreateWithFlags(&s1, cudaStreamNonBlocking);
        cudaEventCreateWithFlags(&e0, cudaEventDisableTiming);
        cudaEventCreateWithFlags(&e1, cudaEventDisableTiming);
        init_done = true;
    }

    cudaEventRecord(e0, 0);
    cudaStreamWaitEvent(s1, e0, 0);
    k_gemm<<<dim3(256,2,2), 256, SM_GEMM, s1>>>(0, vis, kw, vw, nullptr, nullptr);
    k_ln<<<dim3(4096,2), 256, 0, s1>>>(kb, vb, kvg, kvb);
    cudaEventRecord(e1, s1);

    k_w3dirb<<<dim3(2624,2), 256>>>(cwl, cwr, dl, dr, pw, pb);
    k_gemm<<<dim3(2,2,10), 256, SM_GEMM>>>(1, pw, nullptr, nullptr, nullptr, nullptr);
    k_gemm<<<dim3(4,2,10), 256, SM_GEMM>>>(2, emb, nullptr, nullptr, nullptr, nullptr);
    k_q<<<2048, 256>>>(idl, idr, qg, qb);

    cudaStreamWaitEvent(0, e1, 0);
    k_attn<<<dim3(8,32), 512, SM_ATTN>>>(vmask, tau);
    k_gemm<<<dim3(64,4,2), 256, SM_GEMM>>>(3, nullptr, emb, nullptr, clsb, out);
    k_loss<<<1020, 256>>>(out, tmask);
    k_final<<<1, 256>>>(tmask, out);
}

// round 15
// speedup vs baseline: 6.4086x; 1.4713x over previous
#include <cuda_runtime.h>
#include <cuda_fp16.h>
#include <cstdint>
#include <math.h>

#define Bc  32
#define Lc  256
#define Sc  5
#define Nc  1024
#define Dc  256
#define Vc  512
#define Hc  8
#define DHc 32

// ---------------- scratch ----------------
__device__ float g_W3T[2][Sc*Dc*Dc];
__device__ float g_M[10*Dc*Dc];
__device__ float g_Gp[2][Sc*Vc*Dc];
__device__ float g_dirb[2][Dc];
__device__ float g_Q[2][Bc*Lc*Dc];
__device__ float g_K[Bc*Nc*Dc];
__device__ float g_Vm[Bc*Nc*Dc];
__device__ float g_F[2][Bc*Lc*Dc];
__device__ float g_num;

// ---------------- helpers ----------------
__device__ __forceinline__ float warpSum(float v){
#pragma unroll
    for (int o=16;o>0;o>>=1) v += __shfl_xor_sync(0xffffffffu, v, o);
    return v;
}
__device__ __forceinline__ float warpMax(float v){
#pragma unroll
    for (int o=16;o>0;o>>=1) v = fmaxf(v, __shfl_xor_sync(0xffffffffu, v, o));
    return v;
}
__device__ __forceinline__ float blockSum(float v, float* red){
    v = warpSum(v);
    int w = threadIdx.x >> 5;
    __syncthreads();
    if ((threadIdx.x & 31) == 0) red[w] = v;
    __syncthreads();
    if (w == 0){
        float r = (threadIdx.x < 8) ? red[threadIdx.x] : 0.f;
        r = warpSum(r);
        if (threadIdx.x == 0) red[0] = r;
    }
    __syncthreads();
    return red[0];
}
__device__ __forceinline__ uint32_t h2pack(float lo, float hi){
    __half2 h = __floats2half2_rn(lo, hi);
    uint32_t u; memcpy(&u, &h, 4);
    return u;
}
__device__ __forceinline__ void mma_f16(float* c, const uint32_t* a, const uint32_t* b){
    asm volatile("mma.sync.aligned.m16n8k16.row.col.f32.f16.f16.f32 "
        "{%0,%1,%2,%3}, {%4,%5,%6,%7}, {%8,%9}, {%0,%1,%2,%3};"
        : "+f"(c[0]),"+f"(c[1]),"+f"(c[2]),"+f"(c[3])
        : "r"(a[0]),"r"(a[1]),"r"(a[2]),"r"(a[3]), "r"(b[0]),"r"(b[1]));
}

// ---------------- k1: W3^T fold + dirb + zero, merged -----------------------
__global__ void k_w3dirb(const float* __restrict__ wl, const float* __restrict__ wr,
                         const float* __restrict__ dl, const float* __restrict__ dr,
                         const float* __restrict__ P, const float* __restrict__ pb){
    if (blockIdx.x == 0 && blockIdx.y == 0 && threadIdx.x == 0) g_num = 0.f;
    if (blockIdx.x < 2560){
        int dir = blockIdx.y;
        const float* w = dir ? wr : wl;
        int idx = blockIdx.x*256 + threadIdx.x;
        int dt = idx & 255;
        int sj = idx >> 8;
        int s = sj / 256, j = sj % 256;
        float v = 0.f;
#pragma unroll
        for (int k=0;k<5;k++){
            int f = dt + 256*k;
            int o = f/5, sk = f%5;
            int tp = s - sk + 1;
            if (tp >= 0 && tp < 3) v += w[(o*Dc + j)*3 + tp];
        }
        g_W3T[dir][(s*Dc + j)*Dc + dt] = 0.2f*v;
    } else if (blockIdx.y == 0){
        int gw = (blockIdx.x-2560)*8 + (threadIdx.x>>5);
        int dir = gw >> 8, d = gw & 255;
        int lane = threadIdx.x & 31;
        const float* dv = dir ? dr : dl;
        const float4* P4 = (const float4*)(P + d*Dc);
        const float4* D4 = (const float4*)dv;
        float4 p0 = P4[lane], q0 = D4[lane];
        float4 p1 = P4[lane+32], q1 = D4[lane+32];
        float s = p0.x*q0.x + p0.y*q0.y + p0.z*q0.z + p0.w*q0.w
                + p1.x*q1.x + p1.y*q1.y + p1.z*q1.z + p1.w*q1.w;
        s = warpSum(s);
        if (lane == 0) g_dirb[dir][d] = s + pb[d];
    }
}

// ---------------- generic fp16 GEMM, double-buffered smem -------------------
// C = A @ B^T (+bias on mode 3), K=256, tile 128x128, 8 warps (wm2 x wn4)
// smem (uint32/half2): A[2][128*20]  B[2][128*20]   (LDG=20, conflict-free)
#define LDG16 20
#define GSM_BYTES (4*128*LDG16*4)     // 40960
__global__ void __launch_bounds__(256,2) k_gemm(int mode,
        const float* __restrict__ A, const float* __restrict__ B0,
        const float* __restrict__ B1, const float* __restrict__ bias,
        float* __restrict__ Cext){
    extern __shared__ uint32_t sm16[];
    int z = blockIdx.z;
    const float* Ap; const float* Bp; float* Cp;
    int ldb, ldc;
    if (mode==0){
        Ap = A; Bp = z ? B1 : B0; ldb = 256;
        Cp = z ? &g_Vm[0] : &g_K[0]; ldc = 256;
    } else if (mode==1){
        Ap = A;
        Bp = &g_W3T[0][0] + (long)z*65536; ldb = 256;
        Cp = &g_M[0] + (long)z*65536; ldc = 256;
    } else if (mode==2){
        Ap = A;
        Bp = &g_M[0] + (long)z*65536; ldb = 256;
        Cp = &g_Gp[0][0] + (long)(z/5)*655360 + (long)(z%5)*131072; ldc = 256;
    } else {
        Ap = &g_F[0][0] + (long)z*8192*256;
        Bp = B0; ldb = 256;
        Cp = Cext + 1 + (long)z*8192*512; ldc = 512;
    }
    int row0 = blockIdx.x*128, col0 = blockIdx.y*128;
    int t = threadIdx.x, wid = t>>5, lane = t&31;
    int wm = wid>>2, wn = wid&3;
    int lq = lane>>2, lr = lane&3;

    float acc[4][4][4];
#pragma unroll
    for (int mi=0;mi<4;mi++)
#pragma unroll
        for (int ni=0;ni<4;ni++)
#pragma unroll
            for (int e=0;e<4;e++) acc[mi][ni][e]=0.f;

    int r8 = t>>3, cp2 = (t&7)*2;                 // pair index 0..14 step 2
    const float* Ag = &Ap[(long)(row0+r8)*256 + (t&7)*4];
    const float* Bg = &Bp[(long)(col0+r8)*ldb + (t&7)*4];
    uint32_t* Ab = sm16;
    uint32_t* Bb = sm16 + 2*128*LDG16;

    float4 pa[4], pb[4];
#pragma unroll
    for (int u=0;u<4;u++){
        pa[u] = *(const float4*)(Ag + (long)(u*32)*256);
        pb[u] = *(const float4*)(Bg + (long)(u*32)*ldb);
    }
    {
        uint32_t* Ad = Ab + r8*LDG16 + cp2;
        uint32_t* Bd = Bb + r8*LDG16 + cp2;
#pragma unroll
        for (int u=0;u<4;u++){
            Ad[u*32*LDG16+0]=h2pack(pa[u].x,pa[u].y); Ad[u*32*LDG16+1]=h2pack(pa[u].z,pa[u].w);
            Bd[u*32*LDG16+0]=h2pack(pb[u].x,pb[u].y); Bd[u*32*LDG16+1]=h2pack(pb[u].z,pb[u].w);
        }
    }

    for (int kb8=0; kb8<8; kb8++){
        __syncthreads();
        if (kb8 < 7){
            int off = (kb8+1)*32;
#pragma unroll
            for (int u=0;u<4;u++){
                pa[u] = *(const float4*)(Ag + (long)(u*32)*256 + off);
                pb[u] = *(const float4*)(Bg + (long)(u*32)*ldb + off);
            }
        }
        const uint32_t* Asb = Ab + (kb8&1)*128*LDG16;
        const uint32_t* Bsb = Bb + (kb8&1)*128*LDG16;
#pragma unroll
        for (int ks=0;ks<2;ks++){
            uint32_t af[4][4];
#pragma unroll
            for (int mi=0;mi<4;mi++){
                int r = wm*64 + mi*16 + lq;
                af[mi][0] = Asb[r*LDG16 + ks*8 + lr];
                af[mi][1] = Asb[(r+8)*LDG16 + ks*8 + lr];
                af[mi][2] = Asb[r*LDG16 + ks*8 + lr + 4];
                af[mi][3] = Asb[(r+8)*LDG16 + ks*8 + lr + 4];
            }
            uint32_t bf[4][2];
#pragma unroll
            for (int ni=0;ni<4;ni++){
                int c = wn*32 + ni*8 + lq;
                bf[ni][0] = Bsb[c*LDG16 + ks*8 + lr];
                bf[ni][1] = Bsb[c*LDG16 + ks*8 + lr + 4];
            }
#pragma unroll
            for (int mi=0;mi<4;mi++)
#pragma unroll
                for (int ni=0;ni<4;ni++)
                    mma_f16(acc[mi][ni], af[mi], bf[ni]);
        }
        if (kb8 < 7){
            uint32_t* Ad = Ab + ((kb8+1)&1)*128*LDG16 + r8*LDG16 + cp2;
            uint32_t* Bd = Bb + ((kb8+1)&1)*128*LDG16 + r8*LDG16 + cp2;
#pragma unroll
            for (int u=0;u<4;u++){
                Ad[u*32*LDG16+0]=h2pack(pa[u].x,pa[u].y); Ad[u*32*LDG16+1]=h2pack(pa[u].z,pa[u].w);
                Bd[u*32*LDG16+0]=h2pack(pb[u].x,pb[u].y); Bd[u*32*LDG16+1]=h2pack(pb[u].z,pb[u].w);
            }
        }
    }
    if (mode != 3){
        // aligned float2 stores: cols 2*lr,2*lr+1
#pragma unroll
        for (int mi=0;mi<4;mi++)
#pragma unroll
        for (int ni=0;ni<4;ni++){
            long r = row0 + wm*64 + mi*16 + lq;
            int  c = col0 + wn*32 + ni*8 + 2*lr;
            *(float2*)&Cp[r*ldc + c]     = make_float2(acc[mi][ni][0], acc[mi][ni][1]);
            *(float2*)&Cp[(r+8)*ldc + c] = make_float2(acc[mi][ni][2], acc[mi][ni][3]);
        }
    } else {
        // stage per warp (16x9), scalar stores + bias (out+1 misaligned)
        __syncthreads();
        float* stage = (float*)sm16 + wid*(16*9);
#pragma unroll
        for (int mi=0;mi<4;mi++)
#pragma unroll
        for (int ni=0;ni<4;ni++){
            stage[lq*9 + 2*lr]       = acc[mi][ni][0];
            stage[lq*9 + 2*lr+1]     = acc[mi][ni][1];
            stage[(lq+8)*9 + 2*lr]   = acc[mi][ni][2];
            stage[(lq+8)*9 + 2*lr+1] = acc[mi][ni][3];
            __syncwarp();
#pragma unroll
            for (int u=0;u<4;u++){
                int e = lane + u*32;            // 0..127
                int r = e>>3, c = e&7;
                int col = col0 + wn*32 + ni*8 + c;
                Cp[(long)(row0+wm*64+mi*16+r)*ldc + col] = stage[r*9+c] + bias[col];
            }
            __syncwarp();
        }
    }
}

// ---------------- LN (+bias) in place on g_K / g_Vm -------------------------
__global__ void k_ln(const float* __restrict__ kb, const float* __restrict__ vb,
                     const float* __restrict__ gamma, const float* __restrict__ beta){
    int z = blockIdx.y;
    float* X = z ? &g_Vm[0] : &g_K[0];
    const float* bias = z ? vb : kb;
    int wid = threadIdx.x>>5, lane = threadIdx.x&31;
    long row = (long)blockIdx.x*8 + wid;
    float4* R = (float4*)(X + row*256);
    const float4* B4 = (const float4*)bias;
    const float4* G4 = (const float4*)gamma;
    const float4* T4 = (const float4*)beta;
    float4 x0 = R[lane], x1 = R[lane+32];
    float4 b0 = B4[lane], b1 = B4[lane+32];
    x0.x+=b0.x; x0.y+=b0.y; x0.z+=b0.z; x0.w+=b0.w;
    x1.x+=b1.x; x1.y+=b1.y; x1.z+=b1.z; x1.w+=b1.w;
    float s  = x0.x+x0.y+x0.z+x0.w + x1.x+x1.y+x1.z+x1.w;
    float s2 = x0.x*x0.x+x0.y*x0.y+x0.z*x0.z+x0.w*x0.w
             + x1.x*x1.x+x1.y*x1.y+x1.z*x1.z+x1.w*x1.w;
    s = warpSum(s); s2 = warpSum(s2);
    float m = s*(1.f/256.f);
    float r = rsqrtf(s2*(1.f/256.f) - m*m + 1e-5f);
    float4 g0 = G4[lane], g1 = G4[lane+32];
    float4 t0 = T4[lane], t1 = T4[lane+32];
    float4 o0, o1;
    o0.x=(x0.x-m)*r*g0.x+t0.x; o0.y=(x0.y-m)*r*g0.y+t0.y;
    o0.z=(x0.z-m)*r*g0.z+t0.z; o0.w=(x0.w-m)*r*g0.w+t0.w;
    o1.x=(x1.x-m)*r*g1.x+t1.x; o1.y=(x1.y-m)*r*g1.y+t1.y;
    o1.z=(x1.z-m)*r*g1.z+t1.z; o1.w=(x1.w-m)*r*g1.w+t1.w;
    R[lane] = o0; R[lane+32] = o1;
}

// ---------------- Q = LN(sum_s Gp[s,id_s] + dir'): warp per row -------------
__global__ void k_q(const int* __restrict__ idl, const int* __restrict__ idr,
                    const float* __restrict__ gamma, const float* __restrict__ beta){
    int gw = blockIdx.x*8 + (threadIdx.x>>5);
    int dir = gw >> 13;
    int bl  = gw & 8191;
    int lane = threadIdx.x & 31;
    const int* ids = (dir ? idr : idl) + bl*Sc;
    int i0=ids[0], i1=ids[1], i2=ids[2], i3=ids[3], i4=ids[4];
    const float* Gp = dir ? &g_Gp[1][0] : &g_Gp[0][0];
    int d0 = lane*8;
    float4 a0, a1;
    {
        const float4* r0 = (const float4*)&Gp[(0*Vc+i0)*Dc + d0];
        const float4* r1 = (const float4*)&Gp[(1*Vc+i1)*Dc + d0];
        const float4* r2 = (const float4*)&Gp[(2*Vc+i2)*Dc + d0];
        const float4* r3 = (const float4*)&Gp[(3*Vc+i3)*Dc + d0];
        const float4* r4 = (const float4*)&Gp[(4*Vc+i4)*Dc + d0];
        const float4* db = (const float4*)&g_dirb[dir][d0];
        float4 v0 = db[0], v1 = db[1];
        float4 t;
        t=r0[0]; v0.x+=t.x; v0.y+=t.y; v0.z+=t.z; v0.w+=t.w;
        t=r0[1]; v1.x+=t.x; v1.y+=t.y; v1.z+=t.z; v1.w+=t.w;
        t=r1[0]; v0.x+=t.x; v0.y+=t.y; v0.z+=t.z; v0.w+=t.w;
        t=r1[1]; v1.x+=t.x; v1.y+=t.y; v1.z+=t.z; v1.w+=t.w;
        t=r2[0]; v0.x+=t.x; v0.y+=t.y; v0.z+=t.z; v0.w+=t.w;
        t=r2[1]; v1.x+=t.x; v1.y+=t.y; v1.z+=t.z; v1.w+=t.w;
        t=r3[0]; v0.x+=t.x; v0.y+=t.y; v0.z+=t.z; v0.w+=t.w;
        t=r3[1]; v1.x+=t.x; v1.y+=t.y; v1.z+=t.z; v1.w+=t.w;
        t=r4[0]; v0.x+=t.x; v0.y+=t.y; v0.z+=t.z; v0.w+=t.w;
        t=r4[1]; v1.x+=t.x; v1.y+=t.y; v1.z+=t.z; v1.w+=t.w;
        a0 = v0; a1 = v1;
    }
    float s  = a0.x+a0.y+a0.z+a0.w + a1.x+a1.y+a1.z+a1.w;
    float s2 = a0.x*a0.x+a0.y*a0.y+a0.z*a0.z+a0.w*a0.w
             + a1.x*a1.x+a1.y*a1.y+a1.z*a1.z+a1.w*a1.w;
    s = warpSum(s); s2 = warpSum(s2);
    float m = s*(1.f/256.f);
    float r = rsqrtf(s2*(1.f/256.f) - m*m + 1e-5f);
    const float4* G4 = (const float4*)&gamma[d0];
    const float4* T4 = (const float4*)&beta[d0];
    float4 g0=G4[0], g1=G4[1], t0=T4[0], t1=T4[1];
    float4 o0, o1;
    o0.x=(a0.x-m)*r*g0.x+t0.x; o0.y=(a0.y-m)*r*g0.y+t0.y;
    o0.z=(a0.z-m)*r*g0.z+t0.z; o0.w=(a0.w-m)*r*g0.w+t0.w;
    o1.x=(a1.x-m)*r*g1.x+t1.x; o1.y=(a1.y-m)*r*g1.y+t1.y;
    o1.z=(a1.z-m)*r*g1.z+t1.z; o1.w=(a1.w-m)*r*g1.w+t1.w;
    float4* Q4 = (float4*)&g_Q[dir][bl*Dc + d0];
    Q4[0] = o0; Q4[1] = o1;
}

// ---------------- flash attention: fp16 mma m16n8k16, dual-dir CTA ----------
#define LDM 40
#define LDH 20
__global__ void __launch_bounds__(512,1) k_attn(const float* __restrict__ mask,
                                                const float* __restrict__ tau_p){
    extern __shared__ float sm[];
    float*    Msm   = sm;
    uint32_t* Ksm32 = (uint32_t*)(sm + 128*LDM);
    uint32_t* Vp32  = Ksm32 + 2*32*LDH;
    uint32_t* Psm32 = Vp32  + 2*32*LDH;
    int lt = blockIdx.x >> 2, hp = blockIdx.x & 3;
    int b = blockIdx.y;
    int l0 = lt*128;
    int t = threadIdx.x, wid = t>>5, lane = t&31;
    int dir = wid>>3, hh = (wid>>2)&1, wr = wid&3;
    int lq = lane>>2, lr = lane&3;
    float tau = fminf(fmaxf(tau_p[0],0.25f),4.f);
    float kscale = 1.44269504f/(5.656854249f*tau);

    for (int u=0;u<8;u++){
        int i = t + u*512;
        int slot = i>>10, row = (i>>3)&127, c4 = i&7;
        int qd = slot>>1, qh = slot&1;
        const float* Qb = (qd ? g_Q[1] : g_Q[0]) + (long)(b*Lc + l0 + row)*Dc + (hp*2+qh)*32;
        float4 q = *(const float4*)&Qb[c4*4];
        uint32_t* d = &Psm32[(slot*128 + row)*LDH + c4*2];
        d[0] = h2pack(q.x, q.y);
        d[1] = h2pack(q.z, q.w);
    }
    __syncthreads();
    uint32_t qa[2][2][4];
    {
        const uint32_t* Qh = Psm32 + (dir*2+hh)*128*LDH;
#pragma unroll
        for (int mi=0;mi<2;mi++)
#pragma unroll
        for (int ks=0;ks<2;ks++){
            int r = wr*32 + mi*16 + lq;
            qa[mi][ks][0] = Qh[r*LDH + ks*8 + lr];
            qa[mi][ks][1] = Qh[(r+8)*LDH + ks*8 + lr];
            qa[mi][ks][2] = Qh[r*LDH + ks*8 + lr + 4];
            qa[mi][ks][3] = Qh[(r+8)*LDH + ks*8 + lr + 4];
        }
    }
    float o[2][4][4];
#pragma unroll
    for (int mi=0;mi<2;mi++)
#pragma unroll
        for (int ni=0;ni<4;ni++)
#pragma unroll
            for (int e=0;e<4;e++) o[mi][ni][e]=0.f;
    float lsum[4] = {0.f,0.f,0.f,0.f};

    const float* Kg = g_K  + (long)(b*Nc)*Dc + hp*64;
    const float* Vg = g_Vm + (long)(b*Nc)*Dc + hp*64;
    const float* Mg = mask + (long)(b*Lc + l0)*Nc;
    uint32_t* Ph = Psm32 + (dir*2+hh)*128*LDH;

    int k_hh = t>>8, k_n = (t>>3)&31, k_c4 = t&7;
    int v_hh = 0, v_dq = 0, v_j = 0;
    if (t < 256){ v_hh = t>>7; v_dq = (t>>4)&7; v_j = t&15; }
    float4 pk, pv0, pv1, pm[2];
    pk = *(const float4*)&Kg[(long)k_n*Dc + k_hh*32 + k_c4*4];
    if (t < 256){
        pv0 = *(const float4*)&Vg[(long)(2*v_j  )*Dc + v_hh*32 + v_dq*4];
        pv1 = *(const float4*)&Vg[(long)(2*v_j+1)*Dc + v_hh*32 + v_dq*4];
    }
#pragma unroll
    for (int u=0;u<2;u++){
        int i = t + u*512, row = i>>3, c4 = i&7;
        pm[u] = *(const float4*)&Mg[(long)row*Nc + c4*4];
    }

    for (int n0=0; n0<Nc; n0+=32){
        __syncthreads();
        {
            uint32_t* d = &Ksm32[(k_hh*32+k_n)*LDH + k_c4*2];
            d[0] = h2pack(pk.x*kscale, pk.y*kscale);
            d[1] = h2pack(pk.z*kscale, pk.w*kscale);
        }
        if (t < 256){
            uint32_t* base = &Vp32[(v_hh*32 + v_dq*4)*LDH + v_j];
            base[0*LDH] = h2pack(pv0.x, pv1.x);
            base[1*LDH] = h2pack(pv0.y, pv1.y);
            base[2*LDH] = h2pack(pv0.z, pv1.z);
            base[3*LDH] = h2pack(pv0.w, pv1.w);
        }
#pragma unroll
        for (int u=0;u<2;u++){
            int i = t + u*512, row = i>>3, c4 = i&7;
            *(float4*)&Msm[row*LDM + c4*4] = pm[u];
        }
        if (n0 + 32 < Nc){
            pk = *(const float4*)&Kg[(long)(n0+32+k_n)*Dc + k_hh*32 + k_c4*4];
            if (t < 256){
                pv0 = *(const float4*)&Vg[(long)(n0+32+2*v_j  )*Dc + v_hh*32 + v_dq*4];
                pv1 = *(const float4*)&Vg[(long)(n0+32+2*v_j+1)*Dc + v_hh*32 + v_dq*4];
            }
#pragma unroll
            for (int u=0;u<2;u++){
                int i = t + u*512, row = i>>3, c4 = i&7;
                pm[u] = *(const float4*)&Mg[(long)row*Nc + n0+32 + c4*4];
            }
        }
        __syncthreads();

        float sc[2][4][4];
#pragma unroll
        for (int mi=0;mi<2;mi++)
#pragma unroll
            for (int ni=0;ni<4;ni++)
#pragma unroll
                for (int e=0;e<4;e++) sc[mi][ni][e]=0.f;
        const uint32_t* Kh = Ksm32 + hh*32*LDH;
#pragma unroll
        for (int ks=0;ks<2;ks++){
            uint32_t bf[4][2];
#pragma unroll
            for (int ni=0;ni<4;ni++){
                bf[ni][0] = Kh[(ni*8+lq)*LDH + ks*8 + lr];
                bf[ni][1] = Kh[(ni*8+lq)*LDH + ks*8 + lr + 4];
            }
#pragma unroll
            for (int mi=0;mi<2;mi++)
#pragma unroll
                for (int ni=0;ni<4;ni++)
                    mma_f16(sc[mi][ni], qa[mi][ks], bf[ni]);
        }
#pragma unroll
        for (int mi=0;mi<2;mi++)
#pragma unroll
        for (int half=0;half<2;half++){
            int q = mi*2+half;
            int row = wr*32 + mi*16 + half*8 + lq;
            float ls = 0.f;
#pragma unroll
            for (int ni=0;ni<4;ni++){
                float2 mm = *(const float2*)&Msm[row*LDM + ni*8 + 2*lr];
                float p0 = exp2f(sc[mi][ni][half*2]   * mm.x);
                float p1 = exp2f(sc[mi][ni][half*2+1] * mm.y);
                __half2 hp2 = __floats2half2_rn(p0, p1);
                float2 pr = __half22float2(hp2);
                ls += pr.x + pr.y;
                uint32_t u; memcpy(&u, &hp2, 4);
                Ph[row*LDH + ni*4 + lr] = u;
            }
            ls += __shfl_xor_sync(0xffffffffu, ls, 1);
            ls += __shfl_xor_sync(0xffffffffu, ls, 2);
            lsum[q] += ls;
        }
        __syncwarp();
        const uint32_t* Vh = Vp32 + hh*32*LDH;
#pragma unroll
        for (int ks=0;ks<2;ks++){
            uint32_t pafr[2][4];
#pragma unroll
            for (int mi=0;mi<2;mi++){
                int r = wr*32 + mi*16 + lq;
                pafr[mi][0] = Ph[r*LDH + ks*8 + lr];
                pafr[mi][1] = Ph[(r+8)*LDH + ks*8 + lr];
                pafr[mi][2] = Ph[r*LDH + ks*8 + lr + 4];
                pafr[mi][3] = Ph[(r+8)*LDH + ks*8 + lr + 4];
            }
            uint32_t vbf[4][2];
#pragma unroll
            for (int ni=0;ni<4;ni++){
                vbf[ni][0] = Vh[(ni*8+lq)*LDH + ks*8 + lr];
                vbf[ni][1] = Vh[(ni*8+lq)*LDH + ks*8 + lr + 4];
            }
#pragma unroll
            for (int mi=0;mi<2;mi++)
#pragma unroll
                for (int ni=0;ni<4;ni++)
                    mma_f16(o[mi][ni], pafr[mi], vbf[ni]);
        }
    }
    float* Fg = (dir ? g_F[1] : g_F[0]) + (long)(b*Lc + l0)*Dc + (hp*2+hh)*32;
#pragma unroll
    for (int mi=0;mi<2;mi++)
#pragma unroll
    for (int half=0;half<2;half++){
        int q = mi*2+half;
        int row = wr*32 + mi*16 + half*8 + lq;
        float inv = 1.f/lsum[q];
#pragma unroll
        for (int ni=0;ni<4;ni++){
            float2 oo;
            oo.x = o[mi][ni][half*2]*inv;
            oo.y = o[mi][ni][half*2+1]*inv;
            *(float2*)&Fg[(long)row*Dc + ni*8 + 2*lr] = oo;
        }
    }
}

// ---------------- agreement loss: warp per (b,l) ----------------------------
__global__ void k_loss(const float* __restrict__ out, const float* __restrict__ tmask){
    int gw = blockIdx.x*8 + (threadIdx.x>>5);
    if (gw >= (Lc-1)*Bc) return;
    int l = gw % (Lc-1), b = gw / (Lc-1);
    int lane = threadIdx.x & 31;
    const float* rl = out + 1 + (long)(b*Lc + l)*Vc;
    const float* rr = out + 1 + (long)Bc*Lc*Vc + (long)(b*Lc + l + 1)*Vc;
    float xl[16], xr[16];
    float ml = -1e30f, mr = -1e30f;
#pragma unroll
    for (int u=0;u<16;u++){
        xl[u] = rl[lane + u*32]*0.5f;
        xr[u] = rr[lane + u*32]*0.5f;
        ml = fmaxf(ml, xl[u]); mr = fmaxf(mr, xr[u]);
    }
    ml = warpMax(ml); mr = warpMax(mr);
    float el[16], er[16], sl = 0.f, sr = 0.f;
#pragma unroll
    for (int u=0;u<16;u++){
        el[u] = __expf(xl[u]-ml); sl += el[u];
        er[u] = __expf(xr[u]-mr); sr += er[u];
    }
    sl = warpSum(sl); sr = warpSum(sr);
    float isl = 1.f/sl, isr = 1.f/sr;
    float agree = 0.f;
#pragma unroll
    for (int u=0;u<16;u++){
        float d = el[u]*isl - er[u]*isr;
        agree += d*d;
    }
    agree = warpSum(agree);
    if (lane == 0) atomicAdd(&g_num, agree * tmask[b*Lc + l]);
}

__global__ void k_final(const float* __restrict__ tmask, float* __restrict__ out){
    __shared__ float red[32];
    float s = 0.f;
    for (int e=threadIdx.x; e<Bc*Lc; e+=256){
        int l = e % Lc;
        if (l < Lc-1) s += tmask[e];
    }
    s = blockSum(s, red);
    if (threadIdx.x == 0){
        float den = fmaxf(s, 1.0f);
        out[0] = 0.1f * g_num / den;
    }
}

// ---------------- launch ----------------------------------------------------
extern "C" void kernel_launch(void* const* d_in, const int* in_sizes, int n_in,
                              void* d_out, int out_size){
    const float* vis   = (const float*)d_in[0];
    const int*   idl   = (const int*)  d_in[1];
    const int*   idr   = (const int*)  d_in[2];
    const float* tmask = (const float*)d_in[4];
    const float* vmask = (const float*)d_in[5];
    const float* emb   = (const float*)d_in[6];
    const float* dl    = (const float*)d_in[7];
    const float* dr    = (const float*)d_in[8];
    const float* pw    = (const float*)d_in[9];
    const float* pb    = (const float*)d_in[10];
    const float* qg    = (const float*)d_in[11];
    const float* qb    = (const float*)d_in[12];
    const float* kw    = (const float*)d_in[13];
    const float* kb    = (const float*)d_in[14];
    const float* vw    = (const float*)d_in[15];
    const float* vb    = (const float*)d_in[16];
    const float* kvg   = (const float*)d_in[17];
    const float* kvb   = (const float*)d_in[18];
    const float* tau   = (const float*)d_in[19];
    const float* clsb  = (const float*)d_in[20];
    const float* cwl   = (const float*)d_in[21];
    const float* cwr   = (const float*)d_in[22];
    float* out = (float*)d_out;

    const int SM_GEMM = GSM_BYTES;                                       // 40960
    const int SM_ATTN = 128*LDM*4 + (2*32*LDH + 2*32*LDH + 4*128*LDH)*4; // 71680
    static bool init_done = false;
    static cudaStream_t s1;
    static cudaEvent_t e0, e1;
    if (!init_done){
        cudaFuncSetAttribute(k_gemm, cudaFuncAttributeMaxDynamicSharedMemorySize, SM_GEMM);
        cudaFuncSetAttribute(k_attn, cudaFuncAttributeMaxDynamicSharedMemorySize, SM_ATTN);
        cudaStreamCreateWithFlags(&s1, cudaStreamNonBlocking);
        cudaEventCreateWithFlags(&e0, cudaEventDisableTiming);
        cudaEventCreateWithFlags(&e1, cudaEventDisableTiming);
        init_done = true;
    }

    cudaEventRecord(e0, 0);
    cudaStreamWaitEvent(s1, e0, 0);
    k_gemm<<<dim3(256,2,2), 256, SM_GEMM, s1>>>(0, vis, kw, vw, nullptr, nullptr);
    k_ln<<<dim3(4096,2), 256, 0, s1>>>(kb, vb, kvg, kvb);
    cudaEventRecord(e1, s1);

    k_w3dirb<<<dim3(2624,2), 256>>>(cwl, cwr, dl, dr, pw, pb);
    k_gemm<<<dim3(2,2,10), 256, SM_GEMM>>>(1, pw, nullptr, nullptr, nullptr, nullptr);
    k_gemm<<<dim3(4,2,10), 256, SM_GEMM>>>(2, emb, nullptr, nullptr, nullptr, nullptr);
    k_q<<<2048, 256>>>(idl, idr, qg, qb);

    cudaStreamWaitEvent(0, e1, 0);
    k_attn<<<dim3(8,32), 512, SM_ATTN>>>(vmask, tau);
    k_gemm<<<dim3(64,4,2), 256, SM_GEMM>>>(3, nullptr, emb, nullptr, clsb, out);
    k_loss<<<1020, 256>>>(out, tmask);
    k_final<<<1, 256>>>(tmask, out);
}